// round 1
// baseline (speedup 1.0000x reference)
#include <cuda_runtime.h>
#include <math.h>

#define DV   32
#define HIDV 256
#define BV   32

// ---------------- weight scratch (accessed by symbol inside kernels) ----------------
__device__ float g_WqT[DV*DV];
__device__ float g_WkT[DV*DV];
__device__ float g_WvT[DV*DV];
__device__ float g_Wn1T[2*DV*HIDV];   // [i][j] i<64, j<256
__device__ float g_Wn2T[HIDV*DV];     // [j][d]
__device__ float g_CA[DV*HIDV];       // folded Wq -> We1[:, :32]
__device__ float g_CB[DV*HIDV];       // folded Wk -> We1[:, 32:64]
__device__ float g_cbA[HIDV];
__device__ float g_cbB[HIDV];         // includes be1
__device__ float g_w65[HIDV];         // We1[:,64]

// ---------------- activation scratch ----------------
__device__ float g_q [BV*128*DV];
__device__ float g_kT[BV*DV*128];     // [b][d][node]
__device__ float g_v [BV*128*DV];
__device__ float g_A [BV*128*HIDV];   // per-x-node edge term [b][node][j]
__device__ float g_Bt[BV*HIDV*128];   // per-y-node edge term transposed [b][j][node]
__device__ float g_yv[BV*128*DV];
// x-type buffers passed by pointer: R1 (32*32*32), R2 (same), NF (32*128*32)
__device__ float g_xbuf[32768 + 32768 + 131072];

// ============================================================================
// Weight prep: transposes + folding of Wq/Wk/bq/bk/be1 into the edge MLP
// ============================================================================
__global__ void prep_kernel(const float* __restrict__ Wq, const float* __restrict__ bq,
                            const float* __restrict__ Wk, const float* __restrict__ bk,
                            const float* __restrict__ Wv,
                            const float* __restrict__ Wn1, const float* __restrict__ Wn2,
                            const float* __restrict__ We1, const float* __restrict__ be1) {
    int t = threadIdx.x;
    for (int idx = t; idx < DV*DV; idx += 256) {
        int d = idx / DV, dd = idx % DV;
        g_WqT[dd*DV + d] = Wq[idx];
        g_WkT[dd*DV + d] = Wk[idx];
        g_WvT[dd*DV + d] = Wv[idx];
    }
    for (int idx = t; idx < 2*DV*HIDV; idx += 256) {
        int j = idx / (2*DV), i = idx % (2*DV);
        g_Wn1T[i*HIDV + j] = Wn1[idx];
    }
    for (int idx = t; idx < HIDV*DV; idx += 256) {
        int d = idx / HIDV, j = idx % HIDV;
        g_Wn2T[j*DV + d] = Wn2[idx];
    }
    int j = t;  // 0..255
    for (int d = 0; d < DV; d++) {
        float a = 0.f, b = 0.f;
        for (int i = 0; i < DV; i++) {
            a += Wq[i*DV + d] * We1[j*65 + i];
            b += Wk[i*DV + d] * We1[j*65 + 32 + i];
        }
        g_CA[d*HIDV + j] = a;
        g_CB[d*HIDV + j] = b;
    }
    float ca = 0.f, cb = 0.f;
    for (int i = 0; i < DV; i++) {
        ca += We1[j*65 + i]      * bq[i];
        cb += We1[j*65 + 32 + i] * bk[i];
    }
    g_cbA[j] = ca;
    g_cbB[j] = cb + be1[j];
    g_w65[j] = We1[j*65 + 64];
}

// ============================================================================
// QKV projection for intra attention. grid = B*n/8, block 256.
// ============================================================================
__global__ void qkv_kernel(const float* __restrict__ x, const float* __restrict__ bq,
                           const float* __restrict__ bk, const float* __restrict__ bv, int n) {
    int idx = blockIdx.x * blockDim.x + threadIdx.x;   // B*n*32 threads
    int d    = idx & 31;
    int node = (idx >> 5) % n;
    int b    = idx / (32*n);
    const float* xr = x + (b*n + node)*DV;
    float q = bq[d], k = bk[d], v = bv[d];
    #pragma unroll
    for (int dd = 0; dd < DV; dd++) {
        float xv = xr[dd];
        q = fmaf(xv, g_WqT[dd*DV + d], q);
        k = fmaf(xv, g_WkT[dd*DV + d], k);
        v = fmaf(xv, g_WvT[dd*DV + d], v);
    }
    g_q [(b*n + node)*DV + d] = q;
    g_kT[ b*DV*n + d*n + node] = k;
    g_v [(b*n + node)*DV + d] = v;
}

// ============================================================================
// Intra attention + node MLP. One warp per row. grid = B*(n/8), block 256.
// ============================================================================
__global__ void intra_attn_kernel(const float* __restrict__ x, const float* __restrict__ bn1,
                                  const float* __restrict__ bn2, float* __restrict__ out, int n) {
    __shared__ float es[8][128];
    __shared__ float cs[8][64];
    __shared__ float hs[8][256];
    int w = threadIdx.x >> 5, lane = threadIdx.x & 31;
    int chunks = n >> 3;
    int b = blockIdx.x / chunks;
    int row = (blockIdx.x % chunks)*8 + w;
    int nmi = n >> 5;

    const float* qr = g_q + (b*n + row)*DV;
    const float* kb = g_kT + b*DV*n;
    float s[4];
    #pragma unroll
    for (int mi = 0; mi < 4; mi++) s[mi] = 0.f;
    for (int d = 0; d < DV; d++) {
        float qd = qr[d];
        const float* kr = kb + d*n;
        for (int mi = 0; mi < nmi; mi++)
            s[mi] = fmaf(qd, kr[lane + (mi << 5)], s[mi]);
    }
    float mx = s[0];
    for (int mi = 1; mi < nmi; mi++) mx = fmaxf(mx, s[mi]);
    for (int o = 16; o; o >>= 1) mx = fmaxf(mx, __shfl_xor_sync(0xffffffffu, mx, o));
    float sum = 0.f;
    for (int mi = 0; mi < nmi; mi++) { s[mi] = __expf(s[mi] - mx); sum += s[mi]; }
    for (int o = 16; o; o >>= 1) sum += __shfl_xor_sync(0xffffffffu, sum, o);
    float inv = 1.f / sum;
    for (int mi = 0; mi < nmi; mi++) es[w][lane + (mi << 5)] = s[mi]*inv;
    __syncwarp();

    const float* vb = g_v + b*n*DV;
    float agg = 0.f;
    for (int m = 0; m < n; m++) agg = fmaf(es[w][m], vb[m*DV + lane], agg);

    float xv = x[(b*n + row)*DV + lane];
    cs[w][lane] = xv; cs[w][32 + lane] = agg;
    __syncwarp();
    #pragma unroll
    for (int tt = 0; tt < 8; tt++) {
        int j = lane + (tt << 5);
        float h = bn1[j];
        #pragma unroll 8
        for (int i = 0; i < 64; i++) h = fmaf(g_Wn1T[i*HIDV + j], cs[w][i], h);
        hs[w][j] = fmaxf(h, 0.f);
    }
    __syncwarp();
    float o = bn2[lane];
    #pragma unroll 8
    for (int j = 0; j < HIDV; j++) o = fmaf(g_Wn2T[j*DV + lane], hs[w][j], o);
    out[(b*n + row)*DV + lane] = xv + o;
}

// ============================================================================
// inter() per-node edge terms. block 256 = one (b, node).
// ============================================================================
__global__ void projA_kernel(const float* __restrict__ x, int Nx) {
    int j = threadIdx.x;
    int node = blockIdx.x % Nx, b = blockIdx.x / Nx;
    const float* xr = x + (b*Nx + node)*DV;
    float a = g_cbA[j];
    #pragma unroll
    for (int d = 0; d < DV; d++) a = fmaf(xr[d], g_CA[d*HIDV + j], a);
    g_A[(b*Nx + node)*HIDV + j] = a;
}

__global__ void projB_kernel(const float* __restrict__ y, int Ny) {
    int j = threadIdx.x;
    int node = blockIdx.x % Ny, b = blockIdx.x / Ny;
    const float* yr = y + (b*Ny + node)*DV;
    float a = g_cbB[j];
    #pragma unroll
    for (int d = 0; d < DV; d++) a = fmaf(yr[d], g_CB[d*HIDV + j], a);
    g_Bt[b*HIDV*Ny + j*Ny + node] = a;   // transposed store: coalesced reads later
}

__global__ void yv_kernel(const float* __restrict__ y, const float* __restrict__ bv, int Ny) {
    int idx = blockIdx.x * blockDim.x + threadIdx.x;
    int d    = idx & 31;
    int node = (idx >> 5) % Ny;
    int b    = idx / (32*Ny);
    const float* yr = y + (b*Ny + node)*DV;
    float v = bv[d];
    #pragma unroll
    for (int dd = 0; dd < DV; dd++) v = fmaf(yr[dd], g_WvT[dd*DV + d], v);
    g_yv[(b*Ny + node)*DV + d] = v;
}

// ============================================================================
// inter() edge scoring + softmax + aggregate + node MLP. Warp per x-row.
// grid = B*(Nx/8), block 256. lane owns Ny/32 edge columns.
// ============================================================================
__global__ void edge_kernel(const float* __restrict__ x, const float* __restrict__ dis,
                            const float* __restrict__ bn1, const float* __restrict__ bn2,
                            const float* __restrict__ We2,
                            float* __restrict__ xout, float* __restrict__ eout,
                            int Nx, int Ny) {
    __shared__ float es[8][128];
    __shared__ float cs[8][64];
    __shared__ float hs[8][256];
    int w = threadIdx.x >> 5, lane = threadIdx.x & 31;
    int chunks = Nx >> 3;
    int b = blockIdx.x / chunks;
    int i = (blockIdx.x % chunks)*8 + w;
    int njj = Ny >> 5;

    float disv[4], sc[4];
    const float* dr = dis + (b*Nx + i)*Ny;
    #pragma unroll
    for (int jj = 0; jj < 4; jj++) sc[jj] = 0.f;
    for (int jj = 0; jj < njj; jj++) disv[jj] = dr[lane + (jj << 5)];

    const float* Ar = g_A  + (b*Nx + i)*HIDV;
    const float* Bb = g_Bt + b*HIDV*Ny;
    #pragma unroll 4
    for (int t = 0; t < HIDV; t++) {
        float a  = Ar[t];
        float wt = g_w65[t];
        float w2 = We2[t];
        const float* Brow = Bb + t*Ny;
        for (int jj = 0; jj < njj; jj++) {
            float h = fmaf(wt, disv[jj], a + Brow[lane + (jj << 5)]);
            sc[jj] = fmaf(w2, fmaxf(h, 0.f), sc[jj]);
        }
    }
    // softmax over Ny (be2 is softmax-invariant: dropped)
    float mx = sc[0];
    for (int jj = 1; jj < njj; jj++) mx = fmaxf(mx, sc[jj]);
    for (int o = 16; o; o >>= 1) mx = fmaxf(mx, __shfl_xor_sync(0xffffffffu, mx, o));
    float sum = 0.f;
    for (int jj = 0; jj < njj; jj++) { sc[jj] = __expf(sc[jj] - mx); sum += sc[jj]; }
    for (int o = 16; o; o >>= 1) sum += __shfl_xor_sync(0xffffffffu, sum, o);
    float inv = 1.f / sum;
    for (int jj = 0; jj < njj; jj++) {
        float e = sc[jj]*inv;
        es[w][lane + (jj << 5)] = e;
        if (eout) eout[(b*Nx + i)*Ny + lane + (jj << 5)] = e;
    }
    __syncwarp();

    const float* yvb = g_yv + b*Ny*DV;
    float agg = 0.f;
    for (int jm = 0; jm < Ny; jm++) agg = fmaf(es[w][jm], yvb[jm*DV + lane], agg);

    float xv = x[(b*Nx + i)*DV + lane];
    cs[w][lane] = xv; cs[w][32 + lane] = agg;
    __syncwarp();
    #pragma unroll
    for (int tt = 0; tt < 8; tt++) {
        int j = lane + (tt << 5);
        float h = bn1[j];
        #pragma unroll 8
        for (int ii = 0; ii < 64; ii++) h = fmaf(g_Wn1T[ii*HIDV + j], cs[w][ii], h);
        hs[w][j] = fmaxf(h, 0.f);
    }
    __syncwarp();
    float o = bn2[lane];
    #pragma unroll 8
    for (int j = 0; j < HIDV; j++) o = fmaf(g_Wn2T[j*DV + lane], hs[w][j], o);
    xout[(b*Nx + i)*DV + lane] = xv + o;
}

// ============================================================================
extern "C" void kernel_launch(void* const* d_in, const int* in_sizes, int n_in,
                              void* d_out, int out_size) {
    const float* robot    = (const float*)d_in[0];
    const float* frontier = (const float*)d_in[1];
    const float* rh       = (const float*)d_in[2];
    const float* fh       = (const float*)d_in[3];
    const float* rf       = (const float*)d_in[4];   // robot_frontier [B,32,128]
    const float* rp       = (const float*)d_in[5];   // robot_past    [B,32,64]
    const float* fpd      = (const float*)d_in[6];   // frontier_past [B,128,64]
    const float* Wq  = (const float*)d_in[7];  const float* bq  = (const float*)d_in[8];
    const float* Wk  = (const float*)d_in[9];  const float* bk  = (const float*)d_in[10];
    const float* Wv  = (const float*)d_in[11]; const float* bv  = (const float*)d_in[12];
    const float* Wn1 = (const float*)d_in[13]; const float* bn1 = (const float*)d_in[14];
    const float* Wn2 = (const float*)d_in[15]; const float* bn2 = (const float*)d_in[16];
    const float* We1 = (const float*)d_in[17]; const float* be1 = (const float*)d_in[18];
    const float* We2 = (const float*)d_in[19];
    // d_in[20] = be2: softmax-invariant, unused.

    float* out    = (float*)d_out;
    float* r_out  = out;                       // [32,32,32]
    float* f_out  = r_out  + 32*32*32;         // [32,128,32]
    float* rh_out = f_out  + 32*128*32;        // [32,64,32]
    float* fh_out = rh_out + 32*64*32;         // [32,64,32]
    float* e_out  = fh_out + 32*64*32;         // [32,32,128]

    float* xb = nullptr;
    cudaGetSymbolAddress((void**)&xb, g_xbuf);
    float* R1  = xb;                 // intra(robot)
    float* R2  = xb + 32768;         // after inter1
    float* NFb = xb + 65536;         // new_frontier after inter2

    prep_kernel<<<1, 256>>>(Wq, bq, Wk, bk, Wv, Wn1, Wn2, We1, be1);

    // ---- intra blocks ----
    qkv_kernel<<<BV*32/8,  256>>>(robot, bq, bk, bv, 32);
    intra_attn_kernel<<<BV*(32/8),  256>>>(robot, bn1, bn2, R1, 32);

    qkv_kernel<<<BV*128/8, 256>>>(frontier, bq, bk, bv, 128);
    intra_attn_kernel<<<BV*(128/8), 256>>>(frontier, bn1, bn2, f_out, 128);

    qkv_kernel<<<BV*64/8,  256>>>(rh, bq, bk, bv, 64);
    intra_attn_kernel<<<BV*(64/8),  256>>>(rh, bn1, bn2, rh_out, 64);

    qkv_kernel<<<BV*64/8,  256>>>(fh, bq, bk, bv, 64);
    intra_attn_kernel<<<BV*(64/8),  256>>>(fh, bn1, bn2, fh_out, 64);

    // ---- inter 1: robot <- robot_history ----
    projA_kernel<<<BV*32,  256>>>(R1, 32);
    projB_kernel<<<BV*64,  256>>>(rh_out, 64);
    yv_kernel   <<<BV*64/8, 256>>>(rh_out, bv, 64);
    edge_kernel <<<BV*(32/8), 256>>>(R1, rp, bn1, bn2, We2, R2, nullptr, 32, 64);

    // ---- inter 2: frontier <- frontier_history ----
    projA_kernel<<<BV*128, 256>>>(f_out, 128);
    projB_kernel<<<BV*64,  256>>>(fh_out, 64);
    yv_kernel   <<<BV*64/8, 256>>>(fh_out, bv, 64);
    edge_kernel <<<BV*(128/8), 256>>>(f_out, fpd, bn1, bn2, We2, NFb, nullptr, 128, 64);

    // ---- inter 3: robot <- new_frontier (writes robot + edge outputs) ----
    projA_kernel<<<BV*32,  256>>>(R2, 32);
    projB_kernel<<<BV*128, 256>>>(NFb, 128);
    yv_kernel   <<<BV*128/8, 256>>>(NFb, bv, 128);
    edge_kernel <<<BV*(32/8), 256>>>(R2, rf, bn1, bn2, We2, r_out, e_out, 32, 128);
}

// round 3
// speedup vs baseline: 2.0979x; 2.0979x over previous
#include <cuda_runtime.h>
#include <math.h>

#define DV   32
#define HIDV 256
#define BV   32

// ---------------- weight scratch ----------------
__device__ float g_WqT[DV*DV];
__device__ float g_WkT[DV*DV];
__device__ float g_WvT[DV*DV];
__device__ float g_Wn1T[2*DV*HIDV];   // [i][j]
__device__ float g_Wn2T[HIDV*DV];     // [j][d]
__device__ float g_CA[DV*HIDV];       // folded Wq -> We1[:, :32]
__device__ float g_CB[DV*HIDV];       // folded Wk -> We1[:, 32:64]
__device__ float g_cbA[HIDV];
__device__ float g_cbB[HIDV];         // includes be1
__device__ float g_w65[HIDV];         // We1[:,64]

// ---------------- activation scratch ----------------
__device__ float g_R1[BV*32*DV];
__device__ float g_R2[BV*32*DV];
__device__ float g_A1[BV*32*HIDV];
__device__ float g_B1[BV*64*HIDV];    // [b][node][j]
__device__ float g_yv1[BV*64*DV];
__device__ float g_A2[BV*128*HIDV];
__device__ float g_B2[BV*64*HIDV];
__device__ float g_yv2[BV*64*DV];
__device__ float g_A3[BV*32*HIDV];
__device__ float g_B3[BV*128*HIDV];
__device__ float g_yv3[BV*128*DV];

// ============================================================================
// Weight prep: transposes + folding of Wq/Wk/bq/bk/be1 into the edge MLP
// ============================================================================
__global__ void prep_kernel(const float* __restrict__ Wq, const float* __restrict__ bq,
                            const float* __restrict__ Wk, const float* __restrict__ bk,
                            const float* __restrict__ Wv,
                            const float* __restrict__ Wn1, const float* __restrict__ Wn2,
                            const float* __restrict__ We1, const float* __restrict__ be1) {
    int t = threadIdx.x;
    for (int idx = t; idx < DV*DV; idx += 256) {
        int d = idx / DV, dd = idx % DV;
        g_WqT[dd*DV + d] = Wq[idx];
        g_WkT[dd*DV + d] = Wk[idx];
        g_WvT[dd*DV + d] = Wv[idx];
    }
    for (int idx = t; idx < 2*DV*HIDV; idx += 256) {
        int j = idx / (2*DV), i = idx % (2*DV);
        g_Wn1T[i*HIDV + j] = Wn1[idx];
    }
    for (int idx = t; idx < HIDV*DV; idx += 256) {
        int d = idx / HIDV, j = idx % HIDV;
        g_Wn2T[j*DV + d] = Wn2[idx];
    }
    int j = t;
    for (int d = 0; d < DV; d++) {
        float a = 0.f, b = 0.f;
        for (int i = 0; i < DV; i++) {
            a += Wq[i*DV + d] * We1[j*65 + i];
            b += Wk[i*DV + d] * We1[j*65 + 32 + i];
        }
        g_CA[d*HIDV + j] = a;
        g_CB[d*HIDV + j] = b;
    }
    float ca = 0.f, cb = 0.f;
    for (int i = 0; i < DV; i++) {
        ca += We1[j*65 + i]      * bq[i];
        cb += We1[j*65 + 32 + i] * bk[i];
    }
    g_cbA[j] = ca;
    g_cbB[j] = cb + be1[j];
    g_w65[j] = We1[j*65 + 64];
}

// ============================================================================
// Fused intra: qkv + attention + node MLP + inter-projection tails.
// grid = 32 b * 9 chunks, block 256. chunk covers 32 rows (warp -> 4 rows).
// ============================================================================
__global__ void __launch_bounds__(256) intra_fused(
        const float* __restrict__ robot, const float* __restrict__ frontier,
        const float* __restrict__ rh, const float* __restrict__ fh,
        const float* __restrict__ bq, const float* __restrict__ bk,
        const float* __restrict__ bv,
        const float* __restrict__ bn1, const float* __restrict__ bn2,
        float* __restrict__ f_out, float* __restrict__ rh_out, float* __restrict__ fh_out) {
    __shared__ float kTs[32][128];
    __shared__ float vs[128][32];
    __shared__ float es[8][128];
    __shared__ float qs[8][32];
    __shared__ float cs[8][64];
    __shared__ float hs[8][256];

    int b = blockIdx.x / 9;
    int c = blockIdx.x % 9;
    const float* x; float* out; int n, chunk, mode;
    if (c == 0)      { x = robot;    out = g_R1;   n = 32;  chunk = 0;   mode = 0; }
    else if (c < 5)  { x = frontier; out = f_out;  n = 128; chunk = c-1; mode = 1; }
    else if (c < 7)  { x = rh;       out = rh_out; n = 64;  chunk = c-5; mode = 2; }
    else             { x = fh;       out = fh_out; n = 64;  chunk = c-7; mode = 3; }

    int tid = threadIdx.x;
    // phase 1: k,v for the whole sequence
    for (int idx = tid; idx < n*32; idx += 256) {
        int m = idx >> 5, d = idx & 31;
        const float* xr = x + (b*n + m)*DV;
        float k = bk[d], v = bv[d];
        #pragma unroll
        for (int dd = 0; dd < DV; dd++) {
            float xv = xr[dd];
            k = fmaf(xv, g_WkT[dd*DV + d], k);
            v = fmaf(xv, g_WvT[dd*DV + d], v);
        }
        kTs[d][m] = k; vs[m][d] = v;
    }
    __syncthreads();

    int w = tid >> 5, lane = tid & 31;
    int nmi = n >> 5;
    for (int r = 0; r < 4; r++) {
        int row = chunk*32 + w*4 + r;
        const float* xr = x + (b*n + row)*DV;
        // q for this row
        float q = bq[lane];
        #pragma unroll
        for (int dd = 0; dd < DV; dd++) q = fmaf(xr[dd], g_WqT[dd*DV + lane], q);
        qs[w][lane] = q;
        __syncwarp();
        // scores
        float s[4];
        #pragma unroll
        for (int mi = 0; mi < 4; mi++) s[mi] = 0.f;
        #pragma unroll 8
        for (int d = 0; d < DV; d++) {
            float qd = qs[w][d];
            for (int mi = 0; mi < nmi; mi++)
                s[mi] = fmaf(qd, kTs[d][lane + (mi << 5)], s[mi]);
        }
        float mx = s[0];
        for (int mi = 1; mi < nmi; mi++) mx = fmaxf(mx, s[mi]);
        for (int o = 16; o; o >>= 1) mx = fmaxf(mx, __shfl_xor_sync(0xffffffffu, mx, o));
        float sum = 0.f;
        for (int mi = 0; mi < nmi; mi++) { s[mi] = __expf(s[mi] - mx); sum += s[mi]; }
        for (int o = 16; o; o >>= 1) sum += __shfl_xor_sync(0xffffffffu, sum, o);
        float inv = 1.f / sum;
        for (int mi = 0; mi < nmi; mi++) es[w][lane + (mi << 5)] = s[mi]*inv;
        __syncwarp();
        float agg = 0.f;
        for (int m = 0; m < n; m++) agg = fmaf(es[w][m], vs[m][lane], agg);
        // node MLP
        float xv = xr[lane];
        cs[w][lane] = xv; cs[w][32 + lane] = agg;
        __syncwarp();
        #pragma unroll
        for (int tt = 0; tt < 8; tt++) {
            int j = lane + (tt << 5);
            float h = bn1[j];
            #pragma unroll 8
            for (int i2 = 0; i2 < 64; i2++) h = fmaf(g_Wn1T[i2*HIDV + j], cs[w][i2], h);
            hs[w][j] = fmaxf(h, 0.f);
        }
        __syncwarp();
        float o = bn2[lane];
        #pragma unroll 8
        for (int j = 0; j < HIDV; j++) o = fmaf(g_Wn2T[j*DV + lane], hs[w][j], o);
        float res = xv + o;
        out[(b*n + row)*DV + lane] = res;

        // -------- projection tail (feeds the next inter stage) --------
        cs[w][lane] = res;
        __syncwarp();
        if (mode == 0 || mode == 1) {
            float* A = (mode == 0) ? g_A1 : g_A2;
            #pragma unroll
            for (int tt = 0; tt < 8; tt++) {
                int j = lane + (tt << 5);
                float a = g_cbA[j];
                #pragma unroll
                for (int d = 0; d < DV; d++) a = fmaf(cs[w][d], g_CA[d*HIDV + j], a);
                A[(b*n + row)*HIDV + j] = a;
            }
        } else {
            float* Bm = (mode == 2) ? g_B1 : g_B2;
            float* yv = (mode == 2) ? g_yv1 : g_yv2;
            #pragma unroll
            for (int tt = 0; tt < 8; tt++) {
                int j = lane + (tt << 5);
                float a = g_cbB[j];
                #pragma unroll
                for (int d = 0; d < DV; d++) a = fmaf(cs[w][d], g_CB[d*HIDV + j], a);
                Bm[(b*n + row)*HIDV + j] = a;
            }
            float v = bv[lane];
            #pragma unroll
            for (int d = 0; d < DV; d++) v = fmaf(cs[w][d], g_WvT[d*DV + lane], v);
            yv[(b*n + row)*DV + lane] = v;
        }
        __syncwarp();
    }
}

// ============================================================================
// Edge core: edge scores via factored MLP + softmax + aggregate + node MLP
// (+ optional projection tail for the next stage). Warp per x-row, 8 rows/block.
// B matrix tiled through smem with a padded transpose.
// ============================================================================
struct EdgeSmem {
    float es[8][128];
    float cs[8][64];
    float hs[8][256];
    float As[8][256];
    float Bts[32*129];
    float w65s[256];
    float we2s[256];
};

__device__ __forceinline__ void edge_core(
        EdgeSmem* sm,
        const float* __restrict__ x, const float* __restrict__ dis,
        const float* __restrict__ A, const float* __restrict__ Bmat,
        const float* __restrict__ yv,
        const float* __restrict__ bn1, const float* __restrict__ bn2,
        const float* __restrict__ We2, const float* __restrict__ bv,
        float* __restrict__ xout, float* __restrict__ eout,
        int Nx, int Ny, int blk, int tailmode,
        float* __restrict__ Atail, float* __restrict__ Btail, float* __restrict__ yvtail) {
    int tid = threadIdx.x;
    int w = tid >> 5, lane = tid & 31;
    int chunks = Nx >> 3;
    int b = blk / chunks;
    int i = (blk % chunks)*8 + w;
    int njj = Ny >> 5;

    if (tid < 256) { sm->w65s[tid] = g_w65[tid]; sm->we2s[tid] = We2[tid]; }
    const float* Ar = A + (b*Nx + i)*HIDV;
    for (int t = lane; t < 256; t += 32) sm->As[w][t] = Ar[t];

    float disv[4], sc[4];
    const float* dr = dis + (b*Nx + i)*Ny;
    #pragma unroll
    for (int jj = 0; jj < 4; jj++) sc[jj] = 0.f;
    for (int jj = 0; jj < njj; jj++) disv[jj] = dr[lane + (jj << 5)];

    const float* Bb = Bmat + b*Ny*HIDV;
    for (int tc = 0; tc < 256; tc += 32) {
        __syncthreads();
        for (int idx = tid; idx < (Ny << 5); idx += 256) {
            int node = idx >> 5, tt = idx & 31;
            sm->Bts[tt*129 + node] = Bb[node*HIDV + tc + tt];
        }
        __syncthreads();
        #pragma unroll 4
        for (int tt = 0; tt < 32; tt++) {
            int t = tc + tt;
            float a = sm->As[w][t], wt = sm->w65s[t], w2 = sm->we2s[t];
            const float* Brow = sm->Bts + tt*129;
            for (int jj = 0; jj < njj; jj++) {
                float h = fmaf(wt, disv[jj], a + Brow[lane + (jj << 5)]);
                sc[jj] = fmaf(w2, fmaxf(h, 0.f), sc[jj]);
            }
        }
    }
    // softmax (be2 is softmax-invariant: dropped)
    float mx = sc[0];
    for (int jj = 1; jj < njj; jj++) mx = fmaxf(mx, sc[jj]);
    for (int o = 16; o; o >>= 1) mx = fmaxf(mx, __shfl_xor_sync(0xffffffffu, mx, o));
    float sum = 0.f;
    for (int jj = 0; jj < njj; jj++) { sc[jj] = __expf(sc[jj] - mx); sum += sc[jj]; }
    for (int o = 16; o; o >>= 1) sum += __shfl_xor_sync(0xffffffffu, sum, o);
    float inv = 1.f / sum;
    for (int jj = 0; jj < njj; jj++) {
        float e = sc[jj]*inv;
        sm->es[w][lane + (jj << 5)] = e;
        if (eout) eout[(b*Nx + i)*Ny + lane + (jj << 5)] = e;
    }
    __syncwarp();
    const float* yvb = yv + b*Ny*DV;
    float agg = 0.f;
    for (int jm = 0; jm < Ny; jm++) agg = fmaf(sm->es[w][jm], yvb[jm*DV + lane], agg);
    float xv = x[(b*Nx + i)*DV + lane];
    sm->cs[w][lane] = xv; sm->cs[w][32 + lane] = agg;
    __syncwarp();
    #pragma unroll
    for (int tt = 0; tt < 8; tt++) {
        int j = lane + (tt << 5);
        float h = bn1[j];
        #pragma unroll 8
        for (int ii = 0; ii < 64; ii++) h = fmaf(g_Wn1T[ii*HIDV + j], sm->cs[w][ii], h);
        sm->hs[w][j] = fmaxf(h, 0.f);
    }
    __syncwarp();
    float o = bn2[lane];
    #pragma unroll 8
    for (int j = 0; j < HIDV; j++) o = fmaf(g_Wn2T[j*DV + lane], sm->hs[w][j], o);
    float res = xv + o;
    if (xout) xout[(b*Nx + i)*DV + lane] = res;

    // -------- projection tail --------
    if (tailmode <= 1) {
        sm->cs[w][lane] = res;
        __syncwarp();
        if (tailmode == 0) {
            #pragma unroll
            for (int tt = 0; tt < 8; tt++) {
                int j = lane + (tt << 5);
                float a = g_cbA[j];
                #pragma unroll
                for (int d = 0; d < DV; d++) a = fmaf(sm->cs[w][d], g_CA[d*HIDV + j], a);
                Atail[(b*Nx + i)*HIDV + j] = a;
            }
        } else {
            #pragma unroll
            for (int tt = 0; tt < 8; tt++) {
                int j = lane + (tt << 5);
                float a = g_cbB[j];
                #pragma unroll
                for (int d = 0; d < DV; d++) a = fmaf(sm->cs[w][d], g_CB[d*HIDV + j], a);
                Btail[(b*Nx + i)*HIDV + j] = a;
            }
            float v = bv[lane];
            #pragma unroll
            for (int d = 0; d < DV; d++) v = fmaf(sm->cs[w][d], g_WvT[d*DV + lane], v);
            yvtail[(b*Nx + i)*DV + lane] = v;
        }
    }
}

// inter1 (robot<-rh) and inter2 (frontier<-fh) batched; tails emit stage-3 operands.
__global__ void __launch_bounds__(256) edge12_kernel(
        const float* __restrict__ f_out, const float* __restrict__ rp,
        const float* __restrict__ fpd,
        const float* __restrict__ bn1, const float* __restrict__ bn2,
        const float* __restrict__ We2, const float* __restrict__ bv) {
    __shared__ EdgeSmem sm;
    int blk = blockIdx.x;
    if (blk < BV*4) {
        edge_core(&sm, g_R1, rp, g_A1, g_B1, g_yv1, bn1, bn2, We2, bv,
                  g_R2, nullptr, 32, 64, blk, 0, g_A3, nullptr, nullptr);
    } else {
        // new_frontier never materialized: only its B/yv projections are needed.
        edge_core(&sm, f_out, fpd, g_A2, g_B2, g_yv2, bn1, bn2, We2, bv,
                  nullptr, nullptr, 128, 64, blk - BV*4, 1, nullptr, g_B3, g_yv3);
    }
}

// inter3: robot <- new_frontier. Writes robot + edge outputs.
__global__ void __launch_bounds__(256) edge3_kernel(
        const float* __restrict__ rf,
        const float* __restrict__ bn1, const float* __restrict__ bn2,
        const float* __restrict__ We2, const float* __restrict__ bv,
        float* __restrict__ r_out, float* __restrict__ e_out) {
    __shared__ EdgeSmem sm;
    edge_core(&sm, g_R2, rf, g_A3, g_B3, g_yv3, bn1, bn2, We2, bv,
              r_out, e_out, 32, 128, blockIdx.x, 2, nullptr, nullptr, nullptr);
}

// ============================================================================
extern "C" void kernel_launch(void* const* d_in, const int* in_sizes, int n_in,
                              void* d_out, int out_size) {
    const float* robot    = (const float*)d_in[0];
    const float* frontier = (const float*)d_in[1];
    const float* rh       = (const float*)d_in[2];
    const float* fh       = (const float*)d_in[3];
    const float* rf       = (const float*)d_in[4];   // robot_frontier [B,32,128]
    const float* rp       = (const float*)d_in[5];   // robot_past    [B,32,64]
    const float* fpd      = (const float*)d_in[6];   // frontier_past [B,128,64]
    const float* Wq  = (const float*)d_in[7];  const float* bq  = (const float*)d_in[8];
    const float* Wk  = (const float*)d_in[9];  const float* bk  = (const float*)d_in[10];
    const float* Wv  = (const float*)d_in[11]; const float* bv  = (const float*)d_in[12];
    const float* Wn1 = (const float*)d_in[13]; const float* bn1 = (const float*)d_in[14];
    const float* Wn2 = (const float*)d_in[15]; const float* bn2 = (const float*)d_in[16];
    const float* We1 = (const float*)d_in[17]; const float* be1 = (const float*)d_in[18];
    const float* We2 = (const float*)d_in[19];
    // d_in[20] = be2: softmax-invariant, unused.

    float* out    = (float*)d_out;
    float* r_out  = out;                       // [32,32,32]
    float* f_out  = r_out  + 32*32*32;         // [32,128,32]
    float* rh_out = f_out  + 32*128*32;        // [32,64,32]
    float* fh_out = rh_out + 32*64*32;         // [32,64,32]
    float* e_out  = fh_out + 32*64*32;         // [32,32,128]

    prep_kernel<<<1, 256>>>(Wq, bq, Wk, bk, Wv, Wn1, Wn2, We1, be1);
    intra_fused<<<BV*9, 256>>>(robot, frontier, rh, fh, bq, bk, bv, bn1, bn2,
                               f_out, rh_out, fh_out);
    edge12_kernel<<<BV*4 + BV*16, 256>>>(f_out, rp, fpd, bn1, bn2, We2, bv);
    edge3_kernel<<<BV*4, 256>>>(rf, bn1, bn2, We2, bv, r_out, e_out);
}

// round 5
// speedup vs baseline: 2.1485x; 1.0241x over previous
#include <cuda_runtime.h>
#include <math.h>

#define BV 32

// ---------------- weight scratch ----------------
__device__ __align__(16) float g_WqT[1024];
__device__ __align__(16) float g_WkT[1024];
__device__ __align__(16) float g_WvT[1024];
__device__ __align__(16) float g_Wn1T[64*256];    // [i][j]
__device__ __align__(16) float g_CA[32*256];      // [d][j]
__device__ __align__(16) float g_CB[32*256];
__device__ __align__(16) float g_cbA[256];
__device__ __align__(16) float g_cbB[256];        // includes be1
__device__ __align__(16) float g_w65[256];

// ---------------- activation scratch ----------------
// rows: robot 1024, frontier 4096, rh 2048, fh 2048 -> 9216 total
__device__ __align__(16) float g_q [9216*32];
__device__ __align__(16) float g_v [9216*32];
__device__ __align__(16) float g_kT[9216*32];     // per seg: [b][d][node]

__device__ __align__(16) float g_R1 [BV*32*32];
__device__ __align__(16) float g_R2 [BV*32*32];
__device__ __align__(16) float g_A1 [BV*32*256];
__device__ __align__(16) float g_A2 [BV*128*256];
__device__ __align__(16) float g_A3 [BV*32*256];
__device__ __align__(16) float g_B1t[BV*256*64];  // [b][t][node]
__device__ __align__(16) float g_B2t[BV*256*64];
__device__ __align__(16) float g_B3t[BV*256*128];
__device__ __align__(16) float g_yv1[BV*64*32];
__device__ __align__(16) float g_yv2[BV*64*32];
__device__ __align__(16) float g_yv3[BV*128*32];

// ============================================================================
// prep: weight transposes + edge-MLP folding. grid 49, block 256.
// ============================================================================
__global__ void prep_kernel(const float* __restrict__ Wq, const float* __restrict__ bq,
                            const float* __restrict__ Wk, const float* __restrict__ bk,
                            const float* __restrict__ Wv, const float* __restrict__ Wn1,
                            const float* __restrict__ We1, const float* __restrict__ be1) {
    int blk = blockIdx.x, t = threadIdx.x;
    if (blk < 32) {                       // CA/CB for d = blk
        int d = blk, j = t;
        float a = 0.f, b2 = 0.f;
        #pragma unroll 8
        for (int i = 0; i < 32; i++) {
            a  += Wq[i*32 + d] * We1[j*65 + i];
            b2 += Wk[i*32 + d] * We1[j*65 + 32 + i];
        }
        g_CA[d*256 + j] = a;
        g_CB[d*256 + j] = b2;
    } else if (blk == 32) {               // small transposes + folded biases
        for (int idx = t; idx < 1024; idx += 256) {
            int d = idx >> 5, dd = idx & 31;
            g_WqT[dd*32 + d] = Wq[idx];
            g_WkT[dd*32 + d] = Wk[idx];
            g_WvT[dd*32 + d] = Wv[idx];
        }
        float ca = 0.f, cb2 = 0.f;
        #pragma unroll 8
        for (int i = 0; i < 32; i++) {
            ca  += We1[t*65 + i]      * bq[i];
            cb2 += We1[t*65 + 32 + i] * bk[i];
        }
        g_cbA[t] = ca;
        g_cbB[t] = cb2 + be1[t];
        g_w65[t] = We1[t*65 + 64];
    } else {                              // Wn1T: 16 blocks x 1024
        int base = (blk - 33) * 1024;
        for (int k = t; k < 1024; k += 256) {
            int idx = base + k;
            int j = idx >> 6, i = idx & 63;
            g_Wn1T[i*256 + j] = Wn1[idx];
        }
    }
}

// ============================================================================
// qkv: warp per node, lane = d. grid 32*36, block 256 (8 nodes).
// ============================================================================
__global__ void __launch_bounds__(256) qkv_kernel(
        const float* __restrict__ robot, const float* __restrict__ frontier,
        const float* __restrict__ rh, const float* __restrict__ fh,
        const float* __restrict__ bq, const float* __restrict__ bk,
        const float* __restrict__ bv) {
    __shared__ float ks[32][9];
    int tid = threadIdx.x, w = tid >> 5, lane = tid & 31;
    int b = blockIdx.x / 36, c = blockIdx.x % 36;
    const float* x; int n, chunk, rowbase;
    if (c < 4)       { x = robot;    n = 32;  chunk = c;      rowbase = 0; }
    else if (c < 20) { x = frontier; n = 128; chunk = c - 4;  rowbase = 1024; }
    else if (c < 28) { x = rh;       n = 64;  chunk = c - 20; rowbase = 5120; }
    else             { x = fh;       n = 64;  chunk = c - 28; rowbase = 7168; }
    int node = chunk*8 + w;
    float xval = x[(b*n + node)*32 + lane];
    float q = bq[lane], k = bk[lane], v = bv[lane];
    #pragma unroll 8
    for (int dd = 0; dd < 32; dd++) {
        float xv = __shfl_sync(0xffffffffu, xval, dd);
        q = fmaf(xv, g_WqT[dd*32 + lane], q);
        k = fmaf(xv, g_WkT[dd*32 + lane], k);
        v = fmaf(xv, g_WvT[dd*32 + lane], v);
    }
    int grow = rowbase + b*n + node;
    g_q[grow*32 + lane] = q;
    g_v[grow*32 + lane] = v;
    ks[lane][w] = k;
    __syncthreads();
    int d = tid >> 3, nd = tid & 7;
    g_kT[rowbase*32 + b*32*n + d*n + chunk*8 + nd] = ks[d][nd];
}

// ============================================================================
// node MLP helper (warp-level). cs: 64 inputs in smem, hs: 256 scratch.
// ============================================================================
__device__ __forceinline__ float mlp_node(const float* __restrict__ csw,
        float* __restrict__ hsw, int lane,
        const float* __restrict__ bn1, const float* __restrict__ bn2,
        const float* __restrict__ Wn2) {
    int j0 = lane*8;
    float4 h0 = *(const float4*)&bn1[j0];
    float4 h1 = *(const float4*)&bn1[j0 + 4];
    #pragma unroll 4
    for (int i = 0; i < 64; i++) {
        float c = csw[i];
        float4 w0 = *(const float4*)&g_Wn1T[i*256 + j0];
        float4 w1 = *(const float4*)&g_Wn1T[i*256 + j0 + 4];
        h0.x = fmaf(c, w0.x, h0.x); h0.y = fmaf(c, w0.y, h0.y);
        h0.z = fmaf(c, w0.z, h0.z); h0.w = fmaf(c, w0.w, h0.w);
        h1.x = fmaf(c, w1.x, h1.x); h1.y = fmaf(c, w1.y, h1.y);
        h1.z = fmaf(c, w1.z, h1.z); h1.w = fmaf(c, w1.w, h1.w);
    }
    h0.x = fmaxf(h0.x, 0.f); h0.y = fmaxf(h0.y, 0.f);
    h0.z = fmaxf(h0.z, 0.f); h0.w = fmaxf(h0.w, 0.f);
    h1.x = fmaxf(h1.x, 0.f); h1.y = fmaxf(h1.y, 0.f);
    h1.z = fmaxf(h1.z, 0.f); h1.w = fmaxf(h1.w, 0.f);
    *(float4*)&hsw[j0]     = h0;
    *(float4*)&hsw[j0 + 4] = h1;
    __syncwarp();
    float o0 = bn2[lane], o1 = 0.f, o2 = 0.f, o3 = 0.f;
    const float* wrow = Wn2 + lane*256;
    #pragma unroll 4
    for (int j = 0; j < 256; j += 4) {
        float4 hv = *(const float4*)&hsw[j];
        float4 wv = *(const float4*)&wrow[j];
        o0 = fmaf(hv.x, wv.x, o0); o1 = fmaf(hv.y, wv.y, o1);
        o2 = fmaf(hv.z, wv.z, o2); o3 = fmaf(hv.w, wv.w, o3);
    }
    return (o0 + o1) + (o2 + o3);
}

// projection of a 32-vector through folded 32x256 matrix; lane owns j=lane*8..+7
__device__ __forceinline__ void proj8(const float* __restrict__ csw, int lane,
        const float* __restrict__ C, const float* __restrict__ cb, float* r) {
    int j0 = lane*8;
    float4 a0 = *(const float4*)&cb[j0];
    float4 a1 = *(const float4*)&cb[j0 + 4];
    #pragma unroll 4
    for (int d = 0; d < 32; d++) {
        float c = csw[d];
        float4 w0 = *(const float4*)&C[d*256 + j0];
        float4 w1 = *(const float4*)&C[d*256 + j0 + 4];
        a0.x = fmaf(c, w0.x, a0.x); a0.y = fmaf(c, w0.y, a0.y);
        a0.z = fmaf(c, w0.z, a0.z); a0.w = fmaf(c, w0.w, a0.w);
        a1.x = fmaf(c, w1.x, a1.x); a1.y = fmaf(c, w1.y, a1.y);
        a1.z = fmaf(c, w1.z, a1.z); a1.w = fmaf(c, w1.w, a1.w);
    }
    r[0]=a0.x; r[1]=a0.y; r[2]=a0.z; r[3]=a0.w;
    r[4]=a1.x; r[5]=a1.y; r[6]=a1.z; r[7]=a1.w;
}

// ============================================================================
// Intra body: attention + MLP + projection tail. Warp per row.
// MODE: 0=robot(A1) 1=frontier(A2) 2=rh(B1t,yv1) 3=fh(B2t,yv2)
// ============================================================================
template<int NMI, int MODE>
__device__ __forceinline__ void intra_body(
        const float* __restrict__ x, float* __restrict__ out,
        const float* __restrict__ bn1, const float* __restrict__ bn2,
        const float* __restrict__ Wn2, const float* __restrict__ bv,
        int b, int chunk, int rowbase,
        float (*kTs)[128], float (*vs)[32], float (*qs)[32],
        float (*es)[128], float (*cs)[64], float (*hs)[256],
        float* __restrict__ Aout, float* __restrict__ Bout, float* __restrict__ yvout) {
    constexpr int n = NMI*32;
    constexpr int NF4 = n*8;
    constexpr int RQ = n/4;
    int tid = threadIdx.x, w = tid >> 5, lane = tid & 31;

    const float* kTg = g_kT + rowbase*32 + b*32*n;
    const float* vg  = g_v  + (rowbase + b*n)*32;
    for (int i4 = tid; i4 < NF4; i4 += 256) {
        int d = i4 / RQ, r4 = i4 % RQ;
        ((float4*)kTs[d])[r4] = ((const float4*)kTg)[i4];
    }
    for (int i4 = tid; i4 < NF4; i4 += 256)
        ((float4*)vs)[i4] = ((const float4*)vg)[i4];
    int row = chunk*8 + w;
    int grow = rowbase + b*n + row;
    qs[w][lane] = g_q[grow*32 + lane];
    __syncthreads();

    // scores
    float s[NMI];
    #pragma unroll
    for (int k = 0; k < NMI; k++) s[k] = 0.f;
    #pragma unroll 8
    for (int d = 0; d < 32; d++) {
        float qd = qs[w][d];
        if constexpr (NMI == 4) {
            float4 kv = *(const float4*)&kTs[d][lane*4];
            s[0] = fmaf(qd, kv.x, s[0]); s[1] = fmaf(qd, kv.y, s[1]);
            s[2] = fmaf(qd, kv.z, s[2]); s[3] = fmaf(qd, kv.w, s[3]);
        } else if constexpr (NMI == 2) {
            float2 kv = *(const float2*)&kTs[d][lane*2];
            s[0] = fmaf(qd, kv.x, s[0]); s[1] = fmaf(qd, kv.y, s[1]);
        } else {
            s[0] = fmaf(qd, kTs[d][lane], s[0]);
        }
    }
    // softmax
    float mx = s[0];
    #pragma unroll
    for (int k = 1; k < NMI; k++) mx = fmaxf(mx, s[k]);
    #pragma unroll
    for (int o = 16; o; o >>= 1) mx = fmaxf(mx, __shfl_xor_sync(0xffffffffu, mx, o));
    float sum = 0.f;
    #pragma unroll
    for (int k = 0; k < NMI; k++) { s[k] = __expf(s[k] - mx); sum += s[k]; }
    #pragma unroll
    for (int o = 16; o; o >>= 1) sum += __shfl_xor_sync(0xffffffffu, sum, o);
    float inv = 1.f / sum;
    if constexpr (NMI == 4) {
        float4 p = make_float4(s[0]*inv, s[1]*inv, s[2]*inv, s[3]*inv);
        *(float4*)&es[w][lane*4] = p;
    } else if constexpr (NMI == 2) {
        float2 p = make_float2(s[0]*inv, s[1]*inv);
        *(float2*)&es[w][lane*2] = p;
    } else {
        es[w][lane] = s[0]*inv;
    }
    __syncwarp();
    // aggregate
    float a0 = 0.f, a1 = 0.f, a2 = 0.f, a3 = 0.f;
    #pragma unroll 4
    for (int m = 0; m < n; m += 4) {
        a0 = fmaf(es[w][m],   vs[m][lane],   a0);
        a1 = fmaf(es[w][m+1], vs[m+1][lane], a1);
        a2 = fmaf(es[w][m+2], vs[m+2][lane], a2);
        a3 = fmaf(es[w][m+3], vs[m+3][lane], a3);
    }
    float agg = (a0 + a1) + (a2 + a3);
    float xv = x[(b*n + row)*32 + lane];
    cs[w][lane] = xv; cs[w][32 + lane] = agg;
    __syncwarp();
    float o = mlp_node(cs[w], hs[w], lane, bn1, bn2, Wn2);
    float res = xv + o;
    out[(b*n + row)*32 + lane] = res;
    cs[w][lane] = res;
    __syncwarp();

    float r8[8];
    if constexpr (MODE <= 1) {
        proj8(cs[w], lane, g_CA, g_cbA, r8);
        float* dst = Aout + (b*n + row)*256 + lane*8;
        *(float4*)dst       = make_float4(r8[0], r8[1], r8[2], r8[3]);
        *(float4*)(dst + 4) = make_float4(r8[4], r8[5], r8[6], r8[7]);
    } else {
        proj8(cs[w], lane, g_CB, g_cbB, r8);
        *(float4*)&hs[w][lane*8]     = make_float4(r8[0], r8[1], r8[2], r8[3]);
        *(float4*)&hs[w][lane*8 + 4] = make_float4(r8[4], r8[5], r8[6], r8[7]);
        float v0 = bv[lane], v1 = 0.f;
        #pragma unroll 8
        for (int d = 0; d < 32; d += 2) {
            v0 = fmaf(cs[w][d],   g_WvT[d*32 + lane],     v0);
            v1 = fmaf(cs[w][d+1], g_WvT[(d+1)*32 + lane], v1);
        }
        yvout[(b*n + row)*32 + lane] = v0 + v1;
        __syncthreads();
        int t = tid;
        float* dst = Bout + b*256*n + t*n + chunk*8;
        *(float4*)dst       = make_float4(hs[0][t], hs[1][t], hs[2][t], hs[3][t]);
        *(float4*)(dst + 4) = make_float4(hs[4][t], hs[5][t], hs[6][t], hs[7][t]);
    }
}

__global__ void __launch_bounds__(256) intra_kernel(
        const float* __restrict__ robot, const float* __restrict__ frontier,
        const float* __restrict__ rh, const float* __restrict__ fh,
        const float* __restrict__ bn1, const float* __restrict__ bn2,
        const float* __restrict__ Wn2, const float* __restrict__ bv,
        float* __restrict__ f_out, float* __restrict__ rh_out, float* __restrict__ fh_out) {
    __shared__ float kTs[32][128];
    __shared__ float vs[128][32];
    __shared__ float qs[8][32];
    __shared__ float es[8][128];
    __shared__ float cs[8][64];
    __shared__ float hs[8][256];
    int b = blockIdx.x / 36, c = blockIdx.x % 36;
    if (c < 4)
        intra_body<1,0>(robot, g_R1, bn1, bn2, Wn2, bv, b, c, 0,
                        kTs, vs, qs, es, cs, hs, g_A1, nullptr, nullptr);
    else if (c < 20)
        intra_body<4,1>(frontier, f_out, bn1, bn2, Wn2, bv, b, c-4, 1024,
                        kTs, vs, qs, es, cs, hs, g_A2, nullptr, nullptr);
    else if (c < 28)
        intra_body<2,2>(rh, rh_out, bn1, bn2, Wn2, bv, b, c-20, 5120,
                        kTs, vs, qs, es, cs, hs, nullptr, g_B1t, g_yv1);
    else
        intra_body<2,3>(fh, fh_out, bn1, bn2, Wn2, bv, b, c-28, 7168,
                        kTs, vs, qs, es, cs, hs, nullptr, g_B2t, g_yv2);
}

// ============================================================================
// Edge core: factored edge-MLP scores + softmax + aggregate + node MLP.
// Warp per x-row. B read pre-transposed [b][t][node] with float4.
// ============================================================================
template<int R>
__device__ __forceinline__ float edge_core(
        const float* __restrict__ x, const float* __restrict__ dis,
        const float* __restrict__ A, const float* __restrict__ Bt,
        const float* __restrict__ yv,
        const float* __restrict__ bn1, const float* __restrict__ bn2,
        const float* __restrict__ Wn2,
        int Nx, int b, int i, int lane,
        float* __restrict__ Asw, float* __restrict__ esw,
        float* __restrict__ csw, float* __restrict__ hsw,
        const float* __restrict__ w65s, const float* __restrict__ we2s,
        float* __restrict__ eout) {
    constexpr int Ny = 32*R;
    const float4* Ar = (const float4*)(A + (b*Nx + i)*256);
    ((float4*)Asw)[lane]      = Ar[lane];
    ((float4*)Asw)[32 + lane] = Ar[32 + lane];
    __syncwarp();

    const float* dr = dis + (b*Nx + i)*Ny;
    float dv[R];
    if constexpr (R == 4) {
        float4 t4 = *(const float4*)&dr[lane*4];
        dv[0]=t4.x; dv[1]=t4.y; dv[2]=t4.z; dv[3]=t4.w;
    } else {
        float2 t2 = *(const float2*)&dr[lane*2];
        dv[0]=t2.x; dv[1]=t2.y;
    }
    float sc[2][R];
    #pragma unroll
    for (int u = 0; u < 2; u++)
        #pragma unroll
        for (int k = 0; k < R; k++) sc[u][k] = 0.f;

    const float* Bb = Bt + b*256*Ny;
    #pragma unroll 2
    for (int t = 0; t < 256; t += 4) {
        float4 a4 = *(const float4*)&Asw[t];
        float4 w6 = *(const float4*)&w65s[t];
        float4 w2 = *(const float4*)&we2s[t];
        float av[4]  = {a4.x, a4.y, a4.z, a4.w};
        float w6v[4] = {w6.x, w6.y, w6.z, w6.w};
        float w2v[4] = {w2.x, w2.y, w2.z, w2.w};
        #pragma unroll
        for (int u = 0; u < 4; u++) {
            float* scp = sc[u & 1];
            if constexpr (R == 4) {
                float4 Bv = *(const float4*)&Bb[(t+u)*Ny + lane*4];
                float h;
                h = fmaf(w6v[u], dv[0], av[u] + Bv.x); scp[0] = fmaf(w2v[u], fmaxf(h, 0.f), scp[0]);
                h = fmaf(w6v[u], dv[1], av[u] + Bv.y); scp[1] = fmaf(w2v[u], fmaxf(h, 0.f), scp[1]);
                h = fmaf(w6v[u], dv[2], av[u] + Bv.z); scp[2] = fmaf(w2v[u], fmaxf(h, 0.f), scp[2]);
                h = fmaf(w6v[u], dv[3], av[u] + Bv.w); scp[3] = fmaf(w2v[u], fmaxf(h, 0.f), scp[3]);
            } else {
                float2 Bv = *(const float2*)&Bb[(t+u)*Ny + lane*2];
                float h;
                h = fmaf(w6v[u], dv[0], av[u] + Bv.x); scp[0] = fmaf(w2v[u], fmaxf(h, 0.f), scp[0]);
                h = fmaf(w6v[u], dv[1], av[u] + Bv.y); scp[1] = fmaf(w2v[u], fmaxf(h, 0.f), scp[1]);
            }
        }
    }
    float s[R];
    #pragma unroll
    for (int k = 0; k < R; k++) s[k] = sc[0][k] + sc[1][k];
    float mx = s[0];
    #pragma unroll
    for (int k = 1; k < R; k++) mx = fmaxf(mx, s[k]);
    #pragma unroll
    for (int o = 16; o; o >>= 1) mx = fmaxf(mx, __shfl_xor_sync(0xffffffffu, mx, o));
    float sum = 0.f;
    #pragma unroll
    for (int k = 0; k < R; k++) { s[k] = __expf(s[k] - mx); sum += s[k]; }
    #pragma unroll
    for (int o = 16; o; o >>= 1) sum += __shfl_xor_sync(0xffffffffu, sum, o);
    float inv = 1.f / sum;
    if constexpr (R == 4) {
        float4 p = make_float4(s[0]*inv, s[1]*inv, s[2]*inv, s[3]*inv);
        *(float4*)&esw[lane*4] = p;
        if (eout) *(float4*)&eout[(b*Nx + i)*Ny + lane*4] = p;
    } else {
        float2 p = make_float2(s[0]*inv, s[1]*inv);
        *(float2*)&esw[lane*2] = p;
        if (eout) *(float2*)&eout[(b*Nx + i)*Ny + lane*2] = p;
    }
    __syncwarp();
    const float* yvb = yv + b*Ny*32;
    float a0 = 0.f, a1 = 0.f, a2 = 0.f, a3 = 0.f;
    #pragma unroll 4
    for (int m = 0; m < Ny; m += 4) {
        a0 = fmaf(esw[m],   yvb[(m)*32 + lane],   a0);
        a1 = fmaf(esw[m+1], yvb[(m+1)*32 + lane], a1);
        a2 = fmaf(esw[m+2], yvb[(m+2)*32 + lane], a2);
        a3 = fmaf(esw[m+3], yvb[(m+3)*32 + lane], a3);
    }
    float agg = (a0 + a1) + (a2 + a3);
    float xv = x[(b*Nx + i)*32 + lane];
    csw[lane] = xv; csw[32 + lane] = agg;
    __syncwarp();
    float o = mlp_node(csw, hsw, lane, bn1, bn2, Wn2);
    return xv + o;
}

// inter1 (robot<-rh, tail A3) + inter2 (frontier<-fh, tail B3t/yv3). grid 640.
__global__ void __launch_bounds__(256) edge12_kernel(
        const float* __restrict__ f_in, const float* __restrict__ rp,
        const float* __restrict__ fpd,
        const float* __restrict__ bn1, const float* __restrict__ bn2,
        const float* __restrict__ Wn2, const float* __restrict__ We2,
        const float* __restrict__ bv) {
    __shared__ float As[8][256], es[8][128], cs[8][64], hs[8][256];
    __shared__ float w65s[256], we2s[256];
    int tid = threadIdx.x, w = tid >> 5, lane = tid & 31;
    w65s[tid] = g_w65[tid]; we2s[tid] = We2[tid];
    __syncthreads();
    int blk = blockIdx.x;
    if (blk < 128) {
        int b = blk >> 2, i = (blk & 3)*8 + w;
        float res = edge_core<2>(g_R1, rp, g_A1, g_B1t, g_yv1, bn1, bn2, Wn2,
                                 32, b, i, lane, As[w], es[w], cs[w], hs[w],
                                 w65s, we2s, nullptr);
        g_R2[(b*32 + i)*32 + lane] = res;
        cs[w][lane] = res;
        __syncwarp();
        float r8[8];
        proj8(cs[w], lane, g_CA, g_cbA, r8);
        float* dst = g_A3 + (b*32 + i)*256 + lane*8;
        *(float4*)dst       = make_float4(r8[0], r8[1], r8[2], r8[3]);
        *(float4*)(dst + 4) = make_float4(r8[4], r8[5], r8[6], r8[7]);
    } else {
        blk -= 128;
        int b = blk >> 4, chunk = blk & 15, i = chunk*8 + w;
        float res = edge_core<2>(f_in, fpd, g_A2, g_B2t, g_yv2, bn1, bn2, Wn2,
                                 128, b, i, lane, As[w], es[w], cs[w], hs[w],
                                 w65s, we2s, nullptr);
        // new_frontier never materialized: only its projections are needed.
        cs[w][lane] = res;
        __syncwarp();
        float r8[8];
        proj8(cs[w], lane, g_CB, g_cbB, r8);
        *(float4*)&hs[w][lane*8]     = make_float4(r8[0], r8[1], r8[2], r8[3]);
        *(float4*)&hs[w][lane*8 + 4] = make_float4(r8[4], r8[5], r8[6], r8[7]);
        float v0 = bv[lane], v1 = 0.f;
        #pragma unroll 8
        for (int d = 0; d < 32; d += 2) {
            v0 = fmaf(cs[w][d],   g_WvT[d*32 + lane],     v0);
            v1 = fmaf(cs[w][d+1], g_WvT[(d+1)*32 + lane], v1);
        }
        g_yv3[(b*128 + i)*32 + lane] = v0 + v1;
        __syncthreads();
        int t = tid;
        float* dst = g_B3t + b*256*128 + t*128 + chunk*8;
        *(float4*)dst       = make_float4(hs[0][t], hs[1][t], hs[2][t], hs[3][t]);
        *(float4*)(dst + 4) = make_float4(hs[4][t], hs[5][t], hs[6][t], hs[7][t]);
    }
}

// inter3: robot <- new_frontier. grid 512, block 64 (2 warps/block).
__global__ void __launch_bounds__(64) edge3_kernel(
        const float* __restrict__ rf,
        const float* __restrict__ bn1, const float* __restrict__ bn2,
        const float* __restrict__ Wn2, const float* __restrict__ We2,
        float* __restrict__ r_out, float* __restrict__ e_out) {
    __shared__ float As[2][256], es[2][128], cs[2][64], hs[2][256];
    __shared__ float w65s[256], we2s[256];
    int tid = threadIdx.x, w = tid >> 5, lane = tid & 31;
    for (int t = tid; t < 256; t += 64) { w65s[t] = g_w65[t]; we2s[t] = We2[t]; }
    __syncthreads();
    int b = blockIdx.x >> 4, i = (blockIdx.x & 15)*2 + w;
    float res = edge_core<4>(g_R2, rf, g_A3, g_B3t, g_yv3, bn1, bn2, Wn2,
                             32, b, i, lane, As[w], es[w], cs[w], hs[w],
                             w65s, we2s, e_out);
    r_out[(b*32 + i)*32 + lane] = res;
}

// ============================================================================
extern "C" void kernel_launch(void* const* d_in, const int* in_sizes, int n_in,
                              void* d_out, int out_size) {
    const float* robot    = (const float*)d_in[0];
    const float* frontier = (const float*)d_in[1];
    const float* rh       = (const float*)d_in[2];
    const float* fh       = (const float*)d_in[3];
    const float* rf       = (const float*)d_in[4];
    const float* rp       = (const float*)d_in[5];
    const float* fpd      = (const float*)d_in[6];
    const float* Wq  = (const float*)d_in[7];  const float* bq  = (const float*)d_in[8];
    const float* Wk  = (const float*)d_in[9];  const float* bk  = (const float*)d_in[10];
    const float* Wv  = (const float*)d_in[11]; const float* bv  = (const float*)d_in[12];
    const float* Wn1 = (const float*)d_in[13]; const float* bn1 = (const float*)d_in[14];
    const float* Wn2 = (const float*)d_in[15]; const float* bn2 = (const float*)d_in[16];
    const float* We1 = (const float*)d_in[17]; const float* be1 = (const float*)d_in[18];
    const float* We2 = (const float*)d_in[19];
    // d_in[20] = be2: softmax-invariant, unused.

    float* out    = (float*)d_out;
    float* r_out  = out;
    float* f_out  = r_out  + 32*32*32;
    float* rh_out = f_out  + 32*128*32;
    float* fh_out = rh_out + 32*64*32;
    float* e_out  = fh_out + 32*64*32;

    prep_kernel<<<49, 256>>>(Wq, bq, Wk, bk, Wv, Wn1, We1, be1);
    qkv_kernel<<<32*36, 256>>>(robot, frontier, rh, fh, bq, bk, bv);
    intra_kernel<<<32*36, 256>>>(robot, frontier, rh, fh, bn1, bn2, Wn2, bv,
                                 f_out, rh_out, fh_out);
    edge12_kernel<<<640, 256>>>(f_out, rp, fpd, bn1, bn2, Wn2, We2, bv);
    edge3_kernel<<<512, 64>>>(rf, bn1, bn2, Wn2, We2, r_out, e_out);
}

// round 6
// speedup vs baseline: 3.4331x; 1.5979x over previous
#include <cuda_runtime.h>
#include <math.h>

#define BV 32

// ---------------- weight scratch ----------------
__device__ __align__(16) float g_WqT[1024];
__device__ __align__(16) float g_WkT[1024];
__device__ __align__(16) float g_WvT[1024];
__device__ __align__(16) float g_Wn1T[64*256];    // [i][j]
__device__ __align__(16) float g_Wn2q[64*32*4];   // [jg][d][4] quad-packed Wn2
__device__ __align__(16) float g_CA[32*256];      // [d][j]
__device__ __align__(16) float g_CB[32*256];
__device__ __align__(16) float g_cbA[256];
__device__ __align__(16) float g_cbB[256];        // includes be1
__device__ __align__(16) float g_w65[256];

// ---------------- activation scratch ----------------
// rows: robot 1024, frontier 4096, rh 2048, fh 2048 -> 9216 total
__device__ __align__(16) float g_q [9216*32];
__device__ __align__(16) float g_v [9216*32];
__device__ __align__(16) float g_kT[9216*32];     // per seg: [b][d][node]

__device__ __align__(16) float g_R1 [BV*32*32];
__device__ __align__(16) float g_R2 [BV*32*32];
__device__ __align__(16) float g_A1 [BV*32*256];
__device__ __align__(16) float g_A2 [BV*128*256];
__device__ __align__(16) float g_A3 [BV*32*256];
__device__ __align__(16) float g_B1t[BV*256*64];  // [b][t][node]
__device__ __align__(16) float g_B2t[BV*256*64];
__device__ __align__(16) float g_B3t[BV*256*128];
__device__ __align__(16) float g_yv1[BV*64*32];
__device__ __align__(16) float g_yv2[BV*64*32];
__device__ __align__(16) float g_yv3[BV*128*32];

// ============================================================================
// prep: weight transposes + edge-MLP folding + Wn2 quad-pack. grid 57.
// ============================================================================
__global__ void prep_kernel(const float* __restrict__ Wq, const float* __restrict__ bq,
                            const float* __restrict__ Wk, const float* __restrict__ bk,
                            const float* __restrict__ Wv, const float* __restrict__ Wn1,
                            const float* __restrict__ Wn2,
                            const float* __restrict__ We1, const float* __restrict__ be1) {
    int blk = blockIdx.x, t = threadIdx.x;
    if (blk < 32) {                       // CA/CB for d = blk
        int d = blk, j = t;
        float a = 0.f, b2 = 0.f;
        #pragma unroll 8
        for (int i = 0; i < 32; i++) {
            a  += Wq[i*32 + d] * We1[j*65 + i];
            b2 += Wk[i*32 + d] * We1[j*65 + 32 + i];
        }
        g_CA[d*256 + j] = a;
        g_CB[d*256 + j] = b2;
    } else if (blk == 32) {               // small transposes + folded biases
        for (int idx = t; idx < 1024; idx += 256) {
            int d = idx >> 5, dd = idx & 31;
            g_WqT[dd*32 + d] = Wq[idx];
            g_WkT[dd*32 + d] = Wk[idx];
            g_WvT[dd*32 + d] = Wv[idx];
        }
        float ca = 0.f, cb2 = 0.f;
        #pragma unroll 8
        for (int i = 0; i < 32; i++) {
            ca  += We1[t*65 + i]      * bq[i];
            cb2 += We1[t*65 + 32 + i] * bk[i];
        }
        g_cbA[t] = ca;
        g_cbB[t] = cb2 + be1[t];
        g_w65[t] = We1[t*65 + 64];
    } else if (blk < 49) {                // Wn1T: 16 blocks x 1024
        int base = (blk - 33) * 1024;
        for (int k = t; k < 1024; k += 256) {
            int idx = base + k;
            int j = idx >> 6, i = idx & 63;
            g_Wn1T[i*256 + j] = Wn1[idx];
        }
    } else {                              // Wn2q: 8 blocks x 1024
        int base = (blk - 49) * 1024;
        for (int k = t; k < 1024; k += 256) {
            int f = base + k;
            int jg = f >> 7, rem = f & 127;
            int d = rem >> 2, u = rem & 3;
            g_Wn2q[f] = Wn2[d*256 + jg*4 + u];
        }
    }
}

// ============================================================================
// qkv: warp per node, lane = d. grid 32*36, block 256 (8 nodes).
// ============================================================================
__global__ void __launch_bounds__(256) qkv_kernel(
        const float* __restrict__ robot, const float* __restrict__ frontier,
        const float* __restrict__ rh, const float* __restrict__ fh,
        const float* __restrict__ bq, const float* __restrict__ bk,
        const float* __restrict__ bv) {
    __shared__ float ks[32][9];
    int tid = threadIdx.x, w = tid >> 5, lane = tid & 31;
    int b = blockIdx.x / 36, c = blockIdx.x % 36;
    const float* x; int n, chunk, rowbase;
    if (c < 4)       { x = robot;    n = 32;  chunk = c;      rowbase = 0; }
    else if (c < 20) { x = frontier; n = 128; chunk = c - 4;  rowbase = 1024; }
    else if (c < 28) { x = rh;       n = 64;  chunk = c - 20; rowbase = 5120; }
    else             { x = fh;       n = 64;  chunk = c - 28; rowbase = 7168; }
    int node = chunk*8 + w;
    float xval = x[(b*n + node)*32 + lane];
    float q = bq[lane], k = bk[lane], v = bv[lane];
    #pragma unroll 8
    for (int dd = 0; dd < 32; dd++) {
        float xv = __shfl_sync(0xffffffffu, xval, dd);
        q = fmaf(xv, g_WqT[dd*32 + lane], q);
        k = fmaf(xv, g_WkT[dd*32 + lane], k);
        v = fmaf(xv, g_WvT[dd*32 + lane], v);
    }
    int grow = rowbase + b*n + node;
    g_q[grow*32 + lane] = q;
    g_v[grow*32 + lane] = v;
    ks[lane][w] = k;
    __syncthreads();
    int d = tid >> 3, nd = tid & 7;
    g_kT[rowbase*32 + b*32*n + d*n + chunk*8 + nd] = ks[d][nd];
}

// ============================================================================
// Block-cooperative node MLP pieces
// ============================================================================
__device__ __forceinline__ void mlp8_hidden(const float (*csT)[8], float (*hs)[256],
        const float* __restrict__ bn1, int tid) {
    float h[8];
    float b = bn1[tid];
    #pragma unroll
    for (int r = 0; r < 8; r++) h[r] = b;
    #pragma unroll 8
    for (int i = 0; i < 64; i++) {
        float wv = g_Wn1T[i*256 + tid];
        float4 c0 = *(const float4*)&csT[i][0];
        float4 c1 = *(const float4*)&csT[i][4];
        h[0] = fmaf(wv, c0.x, h[0]); h[1] = fmaf(wv, c0.y, h[1]);
        h[2] = fmaf(wv, c0.z, h[2]); h[3] = fmaf(wv, c0.w, h[3]);
        h[4] = fmaf(wv, c1.x, h[4]); h[5] = fmaf(wv, c1.y, h[5]);
        h[6] = fmaf(wv, c1.z, h[6]); h[7] = fmaf(wv, c1.w, h[7]);
    }
    #pragma unroll
    for (int r = 0; r < 8; r++) hs[r][tid] = fmaxf(h[r], 0.f);
}

__device__ __forceinline__ void mlp4_hidden(const float (*csT)[4], float (*hs)[256],
        const float* __restrict__ bn1, int tid) {
    float h[4];
    float b = bn1[tid];
    #pragma unroll
    for (int r = 0; r < 4; r++) h[r] = b;
    #pragma unroll 8
    for (int i = 0; i < 64; i++) {
        float wv = g_Wn1T[i*256 + tid];
        float4 cv = *(const float4*)&csT[i][0];
        h[0] = fmaf(wv, cv.x, h[0]); h[1] = fmaf(wv, cv.y, h[1]);
        h[2] = fmaf(wv, cv.z, h[2]); h[3] = fmaf(wv, cv.w, h[3]);
    }
    #pragma unroll
    for (int r = 0; r < 4; r++) hs[r][tid] = fmaxf(h[r], 0.f);
}

__device__ __forceinline__ float mlp_out_row(const float* __restrict__ hsr, int lane,
        const float* __restrict__ bn2) {
    float o0 = bn2[lane], o1 = 0.f, o2 = 0.f, o3 = 0.f;
    #pragma unroll 4
    for (int jg = 0; jg < 64; jg++) {
        float4 hv = *(const float4*)&hsr[jg*4];
        float4 wv = *(const float4*)&g_Wn2q[(jg*32 + lane)*4];
        o0 = fmaf(hv.x, wv.x, o0); o1 = fmaf(hv.y, wv.y, o1);
        o2 = fmaf(hv.z, wv.z, o2); o3 = fmaf(hv.w, wv.w, o3);
    }
    return (o0 + o1) + (o2 + o3);
}

__device__ __forceinline__ void proj8(const float* __restrict__ csw, int lane,
        const float* __restrict__ C, const float* __restrict__ cb, float* r) {
    int j0 = lane*8;
    float4 a0 = *(const float4*)&cb[j0];
    float4 a1 = *(const float4*)&cb[j0 + 4];
    #pragma unroll 4
    for (int d = 0; d < 32; d++) {
        float c = csw[d];
        float4 w0 = *(const float4*)&C[d*256 + j0];
        float4 w1 = *(const float4*)&C[d*256 + j0 + 4];
        a0.x = fmaf(c, w0.x, a0.x); a0.y = fmaf(c, w0.y, a0.y);
        a0.z = fmaf(c, w0.z, a0.z); a0.w = fmaf(c, w0.w, a0.w);
        a1.x = fmaf(c, w1.x, a1.x); a1.y = fmaf(c, w1.y, a1.y);
        a1.z = fmaf(c, w1.z, a1.z); a1.w = fmaf(c, w1.w, a1.w);
    }
    r[0]=a0.x; r[1]=a0.y; r[2]=a0.z; r[3]=a0.w;
    r[4]=a1.x; r[5]=a1.y; r[6]=a1.z; r[7]=a1.w;
}

// ============================================================================
// Intra: attention (direct L1 reads of kT/v) + coop MLP + projection tail.
// Warp per row, 8 rows/block. MODE: 0=robot(A1) 1=frontier(A2) 2=rh(B1t,yv1) 3=fh(B2t,yv2)
// ============================================================================
template<int NMI, int MODE>
__device__ __forceinline__ void intra_body(
        const float* __restrict__ x, float* __restrict__ out,
        const float* __restrict__ bn1, const float* __restrict__ bn2,
        const float* __restrict__ bv,
        int b, int chunk, int rowbase,
        float (*qs)[32], float (*es)[128], float (*csT)[8], float (*hs)[256],
        float* __restrict__ Aout, float* __restrict__ Bout, float* __restrict__ yvout) {
    constexpr int n = NMI*32;
    int tid = threadIdx.x, w = tid >> 5, lane = tid & 31;
    int row = chunk*8 + w;
    int grow = rowbase + b*n + row;
    qs[w][lane] = g_q[grow*32 + lane];
    __syncwarp();

    const float* kTg = g_kT + rowbase*32 + b*32*n;
    float s[NMI];
    #pragma unroll
    for (int k = 0; k < NMI; k++) s[k] = 0.f;
    #pragma unroll 8
    for (int d = 0; d < 32; d++) {
        float qd = qs[w][d];
        if constexpr (NMI == 4) {
            float4 kv = *(const float4*)&kTg[d*n + lane*4];
            s[0] = fmaf(qd, kv.x, s[0]); s[1] = fmaf(qd, kv.y, s[1]);
            s[2] = fmaf(qd, kv.z, s[2]); s[3] = fmaf(qd, kv.w, s[3]);
        } else if constexpr (NMI == 2) {
            float2 kv = *(const float2*)&kTg[d*n + lane*2];
            s[0] = fmaf(qd, kv.x, s[0]); s[1] = fmaf(qd, kv.y, s[1]);
        } else {
            s[0] = fmaf(qd, kTg[d*n + lane], s[0]);
        }
    }
    float mx = s[0];
    #pragma unroll
    for (int k = 1; k < NMI; k++) mx = fmaxf(mx, s[k]);
    #pragma unroll
    for (int o = 16; o; o >>= 1) mx = fmaxf(mx, __shfl_xor_sync(0xffffffffu, mx, o));
    float sum = 0.f;
    #pragma unroll
    for (int k = 0; k < NMI; k++) { s[k] = __expf(s[k] - mx); sum += s[k]; }
    #pragma unroll
    for (int o = 16; o; o >>= 1) sum += __shfl_xor_sync(0xffffffffu, sum, o);
    float inv = 1.f / sum;
    if constexpr (NMI == 4) {
        *(float4*)&es[w][lane*4] = make_float4(s[0]*inv, s[1]*inv, s[2]*inv, s[3]*inv);
    } else if constexpr (NMI == 2) {
        *(float2*)&es[w][lane*2] = make_float2(s[0]*inv, s[1]*inv);
    } else {
        es[w][lane] = s[0]*inv;
    }
    __syncwarp();
    const float* vg = g_v + (rowbase + b*n)*32;
    float a0 = 0.f, a1 = 0.f, a2 = 0.f, a3 = 0.f;
    #pragma unroll 4
    for (int m = 0; m < n; m += 4) {
        a0 = fmaf(es[w][m],   vg[(m)*32 + lane],   a0);
        a1 = fmaf(es[w][m+1], vg[(m+1)*32 + lane], a1);
        a2 = fmaf(es[w][m+2], vg[(m+2)*32 + lane], a2);
        a3 = fmaf(es[w][m+3], vg[(m+3)*32 + lane], a3);
    }
    float agg = (a0 + a1) + (a2 + a3);
    float xv = x[(b*n + row)*32 + lane];
    csT[lane][w] = xv;
    csT[32 + lane][w] = agg;
    __syncthreads();
    mlp8_hidden(csT, hs, bn1, tid);
    __syncthreads();
    float res = csT[lane][w] + mlp_out_row(hs[w], lane, bn2);
    out[(b*n + row)*32 + lane] = res;
    es[w][lane] = res;
    __syncwarp();

    float r8[8];
    if constexpr (MODE <= 1) {
        proj8(es[w], lane, g_CA, g_cbA, r8);
        float* dst = Aout + (b*n + row)*256 + lane*8;
        *(float4*)dst       = make_float4(r8[0], r8[1], r8[2], r8[3]);
        *(float4*)(dst + 4) = make_float4(r8[4], r8[5], r8[6], r8[7]);
    } else {
        proj8(es[w], lane, g_CB, g_cbB, r8);
        float v0 = bv[lane], v1 = 0.f;
        #pragma unroll 8
        for (int d = 0; d < 32; d += 2) {
            v0 = fmaf(es[w][d],   g_WvT[d*32 + lane],     v0);
            v1 = fmaf(es[w][d+1], g_WvT[(d+1)*32 + lane], v1);
        }
        yvout[(b*n + row)*32 + lane] = v0 + v1;
        __syncthreads();
        *(float4*)&hs[w][lane*8]     = make_float4(r8[0], r8[1], r8[2], r8[3]);
        *(float4*)&hs[w][lane*8 + 4] = make_float4(r8[4], r8[5], r8[6], r8[7]);
        __syncthreads();
        int t = tid;
        float* dst = Bout + b*256*n + t*n + chunk*8;
        *(float4*)dst       = make_float4(hs[0][t], hs[1][t], hs[2][t], hs[3][t]);
        *(float4*)(dst + 4) = make_float4(hs[4][t], hs[5][t], hs[6][t], hs[7][t]);
    }
}

__global__ void __launch_bounds__(256) intra_kernel(
        const float* __restrict__ robot, const float* __restrict__ frontier,
        const float* __restrict__ rh, const float* __restrict__ fh,
        const float* __restrict__ bn1, const float* __restrict__ bn2,
        const float* __restrict__ bv,
        float* __restrict__ f_out, float* __restrict__ rh_out, float* __restrict__ fh_out) {
    __shared__ __align__(16) float qs[8][32];
    __shared__ __align__(16) float es[8][128];
    __shared__ __align__(16) float csT[64][8];
    __shared__ __align__(16) float hs[8][256];
    int b = blockIdx.x / 36, c = blockIdx.x % 36;
    if (c < 4)
        intra_body<1,0>(robot, g_R1, bn1, bn2, bv, b, c, 0,
                        qs, es, csT, hs, g_A1, nullptr, nullptr);
    else if (c < 20)
        intra_body<4,1>(frontier, f_out, bn1, bn2, bv, b, c-4, 1024,
                        qs, es, csT, hs, g_A2, nullptr, nullptr);
    else if (c < 28)
        intra_body<2,2>(rh, rh_out, bn1, bn2, bv, b, c-20, 5120,
                        qs, es, csT, hs, nullptr, g_B1t, g_yv1);
    else
        intra_body<2,3>(fh, fh_out, bn1, bn2, bv, b, c-28, 7168,
                        qs, es, csT, hs, nullptr, g_B2t, g_yv2);
}

// ============================================================================
// Edge t-split: 4 rows/block, warp = (row r, t-half h).
// MODE: 0=inter1(xout=R2, tail A3) 1=inter2(tails B3t/yv3) 2=inter3(r_out+e_out)
// ============================================================================
template<int R>
struct __align__(16) ESmem {
    float As[4][256];
    float scp[4][2][32*R];
    float es[4][32*R];
    float aggp[4][2][32];
    float csT[64][4];
    float hs[4][256];
    float rs[4][32];
    float w65s[256];
    float we2s[256];
};

template<int R, int MODE>
__device__ __forceinline__ void edge_ts_run(
        ESmem<R>* sm,
        const float* __restrict__ x, const float* __restrict__ dis,
        const float* __restrict__ A, const float* __restrict__ Bt,
        const float* __restrict__ yv,
        const float* __restrict__ bn1, const float* __restrict__ bn2,
        const float* __restrict__ bv, const float* __restrict__ We2,
        float* __restrict__ xout, float* __restrict__ eout,
        int Nx, int b, int i0,
        float* __restrict__ Atail, float* __restrict__ Btail,
        float* __restrict__ yvtail) {
    constexpr int Ny = 32*R;
    constexpr int NH = Ny/2;
    int tid = threadIdx.x, w = tid >> 5, lane = tid & 31;
    int r = w >> 1, h = w & 1;
    int i = i0 + r;

    sm->w65s[tid] = g_w65[tid];
    sm->we2s[tid] = We2[tid];
    {
        const float4* Ar = (const float4*)(A + (b*Nx + i)*256);
        ((float4*)(sm->As[r]))[h*32 + lane] = Ar[h*32 + lane];
    }
    __syncthreads();

    const float* dr = dis + (b*Nx + i)*Ny;
    float dv[R];
    if constexpr (R == 4) {
        float4 t4 = *(const float4*)&dr[lane*4];
        dv[0]=t4.x; dv[1]=t4.y; dv[2]=t4.z; dv[3]=t4.w;
    } else {
        float2 t2 = *(const float2*)&dr[lane*2];
        dv[0]=t2.x; dv[1]=t2.y;
    }
    float sc[2][R];
    #pragma unroll
    for (int u = 0; u < 2; u++)
        #pragma unroll
        for (int k = 0; k < R; k++) sc[u][k] = 0.f;
    const float* Bb = Bt + (b*256 + h*128)*Ny;
    const float* Ahs  = sm->As[r] + h*128;
    const float* w65h = sm->w65s + h*128;
    const float* we2h = sm->we2s + h*128;
    #pragma unroll 2
    for (int tt = 0; tt < 128; tt += 4) {
        float4 a4 = *(const float4*)&Ahs[tt];
        float4 w6 = *(const float4*)&w65h[tt];
        float4 w2 = *(const float4*)&we2h[tt];
        float av[4]  = {a4.x, a4.y, a4.z, a4.w};
        float w6v[4] = {w6.x, w6.y, w6.z, w6.w};
        float w2v[4] = {w2.x, w2.y, w2.z, w2.w};
        #pragma unroll
        for (int u = 0; u < 4; u++) {
            float* scp = sc[u & 1];
            if constexpr (R == 4) {
                float4 Bv = *(const float4*)&Bb[(tt+u)*Ny + lane*4];
                float hh;
                hh = fmaf(w6v[u], dv[0], av[u] + Bv.x); scp[0] = fmaf(w2v[u], fmaxf(hh, 0.f), scp[0]);
                hh = fmaf(w6v[u], dv[1], av[u] + Bv.y); scp[1] = fmaf(w2v[u], fmaxf(hh, 0.f), scp[1]);
                hh = fmaf(w6v[u], dv[2], av[u] + Bv.z); scp[2] = fmaf(w2v[u], fmaxf(hh, 0.f), scp[2]);
                hh = fmaf(w6v[u], dv[3], av[u] + Bv.w); scp[3] = fmaf(w2v[u], fmaxf(hh, 0.f), scp[3]);
            } else {
                float2 Bv = *(const float2*)&Bb[(tt+u)*Ny + lane*2];
                float hh;
                hh = fmaf(w6v[u], dv[0], av[u] + Bv.x); scp[0] = fmaf(w2v[u], fmaxf(hh, 0.f), scp[0]);
                hh = fmaf(w6v[u], dv[1], av[u] + Bv.y); scp[1] = fmaf(w2v[u], fmaxf(hh, 0.f), scp[1]);
            }
        }
    }
    if constexpr (R == 4) {
        *(float4*)&sm->scp[r][h][lane*4] = make_float4(sc[0][0]+sc[1][0], sc[0][1]+sc[1][1],
                                                       sc[0][2]+sc[1][2], sc[0][3]+sc[1][3]);
    } else {
        *(float2*)&sm->scp[r][h][lane*2] = make_float2(sc[0][0]+sc[1][0], sc[0][1]+sc[1][1]);
    }
    __syncthreads();

    if (h == 0) {
        float s[R];
        #pragma unroll
        for (int k = 0; k < R; k++)
            s[k] = sm->scp[r][0][lane*R + k] + sm->scp[r][1][lane*R + k];
        float mx = s[0];
        #pragma unroll
        for (int k = 1; k < R; k++) mx = fmaxf(mx, s[k]);
        #pragma unroll
        for (int o = 16; o; o >>= 1) mx = fmaxf(mx, __shfl_xor_sync(0xffffffffu, mx, o));
        float sum = 0.f;
        #pragma unroll
        for (int k = 0; k < R; k++) { s[k] = __expf(s[k] - mx); sum += s[k]; }
        #pragma unroll
        for (int o = 16; o; o >>= 1) sum += __shfl_xor_sync(0xffffffffu, sum, o);
        float inv = 1.f / sum;
        if constexpr (R == 4) {
            float4 p = make_float4(s[0]*inv, s[1]*inv, s[2]*inv, s[3]*inv);
            *(float4*)&sm->es[r][lane*4] = p;
            if (MODE == 2) *(float4*)&eout[(b*Nx + i)*Ny + lane*4] = p;
        } else {
            *(float2*)&sm->es[r][lane*2] = make_float2(s[0]*inv, s[1]*inv);
        }
    }
    __syncthreads();

    {
        const float* yvb = yv + (b*Ny + h*NH)*32;
        const float* esr = sm->es[r] + h*NH;
        float a0 = 0.f, a1 = 0.f, a2 = 0.f, a3 = 0.f;
        #pragma unroll 4
        for (int m = 0; m < NH; m += 4) {
            a0 = fmaf(esr[m],   yvb[(m)*32 + lane],   a0);
            a1 = fmaf(esr[m+1], yvb[(m+1)*32 + lane], a1);
            a2 = fmaf(esr[m+2], yvb[(m+2)*32 + lane], a2);
            a3 = fmaf(esr[m+3], yvb[(m+3)*32 + lane], a3);
        }
        sm->aggp[r][h][lane] = (a0 + a1) + (a2 + a3);
    }
    __syncthreads();
    if (h == 0) {
        float xv = x[(b*Nx + i)*32 + lane];
        sm->csT[lane][r] = xv;
        sm->csT[32 + lane][r] = sm->aggp[r][0][lane] + sm->aggp[r][1][lane];
    }
    __syncthreads();
    mlp4_hidden(sm->csT, sm->hs, bn1, tid);
    __syncthreads();

    if (w < 4) {
        int ii = i0 + w;
        float res = sm->csT[lane][w] + mlp_out_row(sm->hs[w], lane, bn2);
        if (MODE == 0 || MODE == 2) xout[(b*Nx + ii)*32 + lane] = res;
        sm->rs[w][lane] = res;
    }
    __syncwarp();
    if constexpr (MODE == 0) {
        if (w < 4) {
            int ii = i0 + w;
            float r8[8];
            proj8(sm->rs[w], lane, g_CA, g_cbA, r8);
            float* dst = Atail + (b*Nx + ii)*256 + lane*8;
            *(float4*)dst       = make_float4(r8[0], r8[1], r8[2], r8[3]);
            *(float4*)(dst + 4) = make_float4(r8[4], r8[5], r8[6], r8[7]);
        }
    } else if constexpr (MODE == 1) {
        if (w < 4) {
            int ii = i0 + w;
            float r8[8];
            proj8(sm->rs[w], lane, g_CB, g_cbB, r8);
            *(float4*)&sm->hs[w][lane*8]     = make_float4(r8[0], r8[1], r8[2], r8[3]);
            *(float4*)&sm->hs[w][lane*8 + 4] = make_float4(r8[4], r8[5], r8[6], r8[7]);
            float v0 = bv[lane], v1 = 0.f;
            #pragma unroll 8
            for (int d = 0; d < 32; d += 2) {
                v0 = fmaf(sm->rs[w][d],   g_WvT[d*32 + lane],     v0);
                v1 = fmaf(sm->rs[w][d+1], g_WvT[(d+1)*32 + lane], v1);
            }
            yvtail[(b*128 + ii)*32 + lane] = v0 + v1;
        }
        __syncthreads();
        int t = tid;
        float* dst = Btail + b*256*128 + t*128 + i0;
        *(float4*)dst = make_float4(sm->hs[0][t], sm->hs[1][t], sm->hs[2][t], sm->hs[3][t]);
    }
}

// inter1 (256 blocks) + inter2 (1024 blocks). grid 1280.
__global__ void __launch_bounds__(256) edge12_kernel(
        const float* __restrict__ f_in, const float* __restrict__ rp,
        const float* __restrict__ fpd,
        const float* __restrict__ bn1, const float* __restrict__ bn2,
        const float* __restrict__ We2, const float* __restrict__ bv) {
    __shared__ __align__(16) ESmem<2> sm;
    int blk = blockIdx.x;
    if (blk < 256) {
        int b = blk >> 3, i0 = (blk & 7)*4;
        edge_ts_run<2,0>(&sm, g_R1, rp, g_A1, g_B1t, g_yv1, bn1, bn2, bv, We2,
                         g_R2, nullptr, 32, b, i0, g_A3, nullptr, nullptr);
    } else {
        blk -= 256;
        int b = blk >> 5, i0 = (blk & 31)*4;
        edge_ts_run<2,1>(&sm, f_in, fpd, g_A2, g_B2t, g_yv2, bn1, bn2, bv, We2,
                         nullptr, nullptr, 128, b, i0, nullptr, g_B3t, g_yv3);
    }
}

// inter3: robot <- new_frontier. grid 256.
__global__ void __launch_bounds__(256) edge3_kernel(
        const float* __restrict__ rf,
        const float* __restrict__ bn1, const float* __restrict__ bn2,
        const float* __restrict__ We2, const float* __restrict__ bv,
        float* __restrict__ r_out, float* __restrict__ e_out) {
    __shared__ __align__(16) ESmem<4> sm;
    int b = blockIdx.x >> 3, i0 = (blockIdx.x & 7)*4;
    edge_ts_run<4,2>(&sm, g_R2, rf, g_A3, g_B3t, g_yv3, bn1, bn2, bv, We2,
                     r_out, e_out, 32, b, i0, nullptr, nullptr, nullptr);
}

// ============================================================================
extern "C" void kernel_launch(void* const* d_in, const int* in_sizes, int n_in,
                              void* d_out, int out_size) {
    const float* robot    = (const float*)d_in[0];
    const float* frontier = (const float*)d_in[1];
    const float* rh       = (const float*)d_in[2];
    const float* fh       = (const float*)d_in[3];
    const float* rf       = (const float*)d_in[4];
    const float* rp       = (const float*)d_in[5];
    const float* fpd      = (const float*)d_in[6];
    const float* Wq  = (const float*)d_in[7];  const float* bq  = (const float*)d_in[8];
    const float* Wk  = (const float*)d_in[9];  const float* bk  = (const float*)d_in[10];
    const float* Wv  = (const float*)d_in[11]; const float* bv  = (const float*)d_in[12];
    const float* Wn1 = (const float*)d_in[13]; const float* bn1 = (const float*)d_in[14];
    const float* Wn2 = (const float*)d_in[15]; const float* bn2 = (const float*)d_in[16];
    const float* We1 = (const float*)d_in[17]; const float* be1 = (const float*)d_in[18];
    const float* We2 = (const float*)d_in[19];
    // d_in[20] = be2: softmax-invariant, unused.

    float* out    = (float*)d_out;
    float* r_out  = out;
    float* f_out  = r_out  + 32*32*32;
    float* rh_out = f_out  + 32*128*32;
    float* fh_out = rh_out + 32*64*32;
    float* e_out  = fh_out + 32*64*32;

    prep_kernel<<<57, 256>>>(Wq, bq, Wk, bk, Wv, Wn1, Wn2, We1, be1);
    qkv_kernel<<<32*36, 256>>>(robot, frontier, rh, fh, bq, bk, bv);
    intra_kernel<<<32*36, 256>>>(robot, frontier, rh, fh, bn1, bn2, bv,
                                 f_out, rh_out, fh_out);
    edge12_kernel<<<1280, 256>>>(f_out, rp, fpd, bn1, bn2, We2, bv);
    edge3_kernel<<<256, 256>>>(rf, bn1, bn2, We2, bv, r_out, e_out);
}

// round 7
// speedup vs baseline: 3.9065x; 1.1379x over previous
#include <cuda_runtime.h>
#include <math.h>

#define BV 32

// ---------------- weight scratch ----------------
__device__ __align__(16) float g_WqT[1024];
__device__ __align__(16) float g_WkT[1024];
__device__ __align__(16) float g_WvT[1024];
__device__ __align__(16) float g_Wn1T[64*256];    // [i][j]
__device__ __align__(16) float g_Wn2q[64*32*4];   // [jg][d][4] quad-packed Wn2
__device__ __align__(16) float g_CA[32*256];      // [d][j]
__device__ __align__(16) float g_CB[32*256];
__device__ __align__(16) float g_cbA[256];
__device__ __align__(16) float g_cbB[256];        // includes be1
__device__ __align__(16) float g_w65[256];

// ---------------- activation scratch ----------------
// rows: robot 1024, frontier 4096, rh 2048, fh 2048 -> 9216 total
__device__ __align__(16) float g_q [9216*32];
__device__ __align__(16) float g_v [9216*32];
__device__ __align__(16) float g_kT[9216*32];     // per seg: [b][d][node]

__device__ __align__(16) float g_R1 [BV*32*32];
__device__ __align__(16) float g_R2 [BV*32*32];
__device__ __align__(16) float g_A1 [BV*32*256];
__device__ __align__(16) float g_A2 [BV*128*256];
__device__ __align__(16) float g_A3 [BV*32*256];
__device__ __align__(16) float g_B1t[BV*256*64];  // [b][t][node]
__device__ __align__(16) float g_B2t[BV*256*64];
__device__ __align__(16) float g_B3t[BV*256*128];
__device__ __align__(16) float g_yv1[BV*64*32];
__device__ __align__(16) float g_yv2[BV*64*32];
__device__ __align__(16) float g_yv3[BV*128*32];

// ============================================================================
// prep: weight transposes + edge-MLP folding + Wn2 quad-pack. grid 57.
// ============================================================================
__global__ void prep_kernel(const float* __restrict__ Wq, const float* __restrict__ bq,
                            const float* __restrict__ Wk, const float* __restrict__ bk,
                            const float* __restrict__ Wv, const float* __restrict__ Wn1,
                            const float* __restrict__ Wn2,
                            const float* __restrict__ We1, const float* __restrict__ be1) {
    int blk = blockIdx.x, t = threadIdx.x;
    if (blk < 32) {                       // CA/CB for d = blk
        int d = blk, j = t;
        float a = 0.f, b2 = 0.f;
        #pragma unroll 8
        for (int i = 0; i < 32; i++) {
            a  += Wq[i*32 + d] * We1[j*65 + i];
            b2 += Wk[i*32 + d] * We1[j*65 + 32 + i];
        }
        g_CA[d*256 + j] = a;
        g_CB[d*256 + j] = b2;
    } else if (blk == 32) {               // small transposes + folded biases
        for (int idx = t; idx < 1024; idx += 256) {
            int d = idx >> 5, dd = idx & 31;
            g_WqT[dd*32 + d] = Wq[idx];
            g_WkT[dd*32 + d] = Wk[idx];
            g_WvT[dd*32 + d] = Wv[idx];
        }
        float ca = 0.f, cb2 = 0.f;
        #pragma unroll 8
        for (int i = 0; i < 32; i++) {
            ca  += We1[t*65 + i]      * bq[i];
            cb2 += We1[t*65 + 32 + i] * bk[i];
        }
        g_cbA[t] = ca;
        g_cbB[t] = cb2 + be1[t];
        g_w65[t] = We1[t*65 + 64];
    } else if (blk < 49) {                // Wn1T: 16 blocks x 1024
        int base = (blk - 33) * 1024;
        for (int k = t; k < 1024; k += 256) {
            int idx = base + k;
            int j = idx >> 6, i = idx & 63;
            g_Wn1T[i*256 + j] = Wn1[idx];
        }
    } else {                              // Wn2q: 8 blocks x 1024
        int base = (blk - 49) * 1024;
        for (int k = t; k < 1024; k += 256) {
            int f = base + k;
            int jg = f >> 7, rem = f & 127;
            int d = rem >> 2, u = rem & 3;
            g_Wn2q[f] = Wn2[d*256 + jg*4 + u];
        }
    }
}

// ============================================================================
// qkv: warp per node, lane = d. grid 32*36, block 256 (8 nodes).
// ============================================================================
__global__ void __launch_bounds__(256) qkv_kernel(
        const float* __restrict__ robot, const float* __restrict__ frontier,
        const float* __restrict__ rh, const float* __restrict__ fh,
        const float* __restrict__ bq, const float* __restrict__ bk,
        const float* __restrict__ bv) {
    __shared__ float ks[32][9];
    int tid = threadIdx.x, w = tid >> 5, lane = tid & 31;
    int b = blockIdx.x / 36, c = blockIdx.x % 36;
    const float* x; int n, chunk, rowbase;
    if (c < 4)       { x = robot;    n = 32;  chunk = c;      rowbase = 0; }
    else if (c < 20) { x = frontier; n = 128; chunk = c - 4;  rowbase = 1024; }
    else if (c < 28) { x = rh;       n = 64;  chunk = c - 20; rowbase = 5120; }
    else             { x = fh;       n = 64;  chunk = c - 28; rowbase = 7168; }
    int node = chunk*8 + w;
    float xval = x[(b*n + node)*32 + lane];
    float q = bq[lane], k = bk[lane], v = bv[lane];
    #pragma unroll 8
    for (int dd = 0; dd < 32; dd++) {
        float xv = __shfl_sync(0xffffffffu, xval, dd);
        q = fmaf(xv, g_WqT[dd*32 + lane], q);
        k = fmaf(xv, g_WkT[dd*32 + lane], k);
        v = fmaf(xv, g_WvT[dd*32 + lane], v);
    }
    int grow = rowbase + b*n + node;
    g_q[grow*32 + lane] = q;
    g_v[grow*32 + lane] = v;
    ks[lane][w] = k;
    __syncthreads();
    int d = tid >> 3, nd = tid & 7;
    g_kT[rowbase*32 + b*32*n + d*n + chunk*8 + nd] = ks[d][nd];
}

// ============================================================================
// node MLP helpers
// ============================================================================
__device__ __forceinline__ void mlp8_hidden(const float (*csT)[8], float (*hs)[256],
        const float* __restrict__ bn1, int tid) {
    float h[8];
    float b = bn1[tid];
    #pragma unroll
    for (int r = 0; r < 8; r++) h[r] = b;
    #pragma unroll 8
    for (int i = 0; i < 64; i++) {
        float wv = g_Wn1T[i*256 + tid];
        float4 c0 = *(const float4*)&csT[i][0];
        float4 c1 = *(const float4*)&csT[i][4];
        h[0] = fmaf(wv, c0.x, h[0]); h[1] = fmaf(wv, c0.y, h[1]);
        h[2] = fmaf(wv, c0.z, h[2]); h[3] = fmaf(wv, c0.w, h[3]);
        h[4] = fmaf(wv, c1.x, h[4]); h[5] = fmaf(wv, c1.y, h[5]);
        h[6] = fmaf(wv, c1.z, h[6]); h[7] = fmaf(wv, c1.w, h[7]);
    }
    #pragma unroll
    for (int r = 0; r < 8; r++) hs[r][tid] = fmaxf(h[r], 0.f);
}

__device__ __forceinline__ float mlp_out_row(const float* __restrict__ hsr, int lane,
        const float* __restrict__ bn2) {
    float o0 = bn2[lane], o1 = 0.f, o2 = 0.f, o3 = 0.f;
    #pragma unroll 4
    for (int jg = 0; jg < 64; jg++) {
        float4 hv = *(const float4*)&hsr[jg*4];
        float4 wv = *(const float4*)&g_Wn2q[(jg*32 + lane)*4];
        o0 = fmaf(hv.x, wv.x, o0); o1 = fmaf(hv.y, wv.y, o1);
        o2 = fmaf(hv.z, wv.z, o2); o3 = fmaf(hv.w, wv.w, o3);
    }
    return (o0 + o1) + (o2 + o3);
}

__device__ __forceinline__ void proj8(const float* __restrict__ csw, int lane,
        const float* __restrict__ C, const float* __restrict__ cb, float* r) {
    int j0 = lane*8;
    float4 a0 = *(const float4*)&cb[j0];
    float4 a1 = *(const float4*)&cb[j0 + 4];
    #pragma unroll 4
    for (int d = 0; d < 32; d++) {
        float c = csw[d];
        float4 w0 = *(const float4*)&C[d*256 + j0];
        float4 w1 = *(const float4*)&C[d*256 + j0 + 4];
        a0.x = fmaf(c, w0.x, a0.x); a0.y = fmaf(c, w0.y, a0.y);
        a0.z = fmaf(c, w0.z, a0.z); a0.w = fmaf(c, w0.w, a0.w);
        a1.x = fmaf(c, w1.x, a1.x); a1.y = fmaf(c, w1.y, a1.y);
        a1.z = fmaf(c, w1.z, a1.z); a1.w = fmaf(c, w1.w, a1.w);
    }
    r[0]=a0.x; r[1]=a0.y; r[2]=a0.z; r[3]=a0.w;
    r[4]=a1.x; r[5]=a1.y; r[6]=a1.z; r[7]=a1.w;
}

// ============================================================================
// Intra: attention (direct L1 reads of kT/v) + coop MLP + projection tail.
// Warp per row, 8 rows/block. MODE: 0=robot(A1) 1=frontier(A2) 2=rh(B1t,yv1) 3=fh(B2t,yv2)
// ============================================================================
template<int NMI, int MODE>
__device__ __forceinline__ void intra_body(
        const float* __restrict__ x, float* __restrict__ out,
        const float* __restrict__ bn1, const float* __restrict__ bn2,
        const float* __restrict__ bv,
        int b, int chunk, int rowbase,
        float (*qs)[32], float (*es)[128], float (*csT)[8], float (*hs)[256],
        float* __restrict__ Aout, float* __restrict__ Bout, float* __restrict__ yvout) {
    constexpr int n = NMI*32;
    int tid = threadIdx.x, w = tid >> 5, lane = tid & 31;
    int row = chunk*8 + w;
    int grow = rowbase + b*n + row;
    qs[w][lane] = g_q[grow*32 + lane];
    __syncwarp();

    const float* kTg = g_kT + rowbase*32 + b*32*n;
    float s[NMI];
    #pragma unroll
    for (int k = 0; k < NMI; k++) s[k] = 0.f;
    #pragma unroll 8
    for (int d = 0; d < 32; d++) {
        float qd = qs[w][d];
        if constexpr (NMI == 4) {
            float4 kv = *(const float4*)&kTg[d*n + lane*4];
            s[0] = fmaf(qd, kv.x, s[0]); s[1] = fmaf(qd, kv.y, s[1]);
            s[2] = fmaf(qd, kv.z, s[2]); s[3] = fmaf(qd, kv.w, s[3]);
        } else if constexpr (NMI == 2) {
            float2 kv = *(const float2*)&kTg[d*n + lane*2];
            s[0] = fmaf(qd, kv.x, s[0]); s[1] = fmaf(qd, kv.y, s[1]);
        } else {
            s[0] = fmaf(qd, kTg[d*n + lane], s[0]);
        }
    }
    float mx = s[0];
    #pragma unroll
    for (int k = 1; k < NMI; k++) mx = fmaxf(mx, s[k]);
    #pragma unroll
    for (int o = 16; o; o >>= 1) mx = fmaxf(mx, __shfl_xor_sync(0xffffffffu, mx, o));
    float sum = 0.f;
    #pragma unroll
    for (int k = 0; k < NMI; k++) { s[k] = __expf(s[k] - mx); sum += s[k]; }
    #pragma unroll
    for (int o = 16; o; o >>= 1) sum += __shfl_xor_sync(0xffffffffu, sum, o);
    float inv = 1.f / sum;
    if constexpr (NMI == 4) {
        *(float4*)&es[w][lane*4] = make_float4(s[0]*inv, s[1]*inv, s[2]*inv, s[3]*inv);
    } else if constexpr (NMI == 2) {
        *(float2*)&es[w][lane*2] = make_float2(s[0]*inv, s[1]*inv);
    } else {
        es[w][lane] = s[0]*inv;
    }
    __syncwarp();
    const float* vg = g_v + (rowbase + b*n)*32;
    float a0 = 0.f, a1 = 0.f, a2 = 0.f, a3 = 0.f;
    #pragma unroll 4
    for (int m = 0; m < n; m += 4) {
        a0 = fmaf(es[w][m],   vg[(m)*32 + lane],   a0);
        a1 = fmaf(es[w][m+1], vg[(m+1)*32 + lane], a1);
        a2 = fmaf(es[w][m+2], vg[(m+2)*32 + lane], a2);
        a3 = fmaf(es[w][m+3], vg[(m+3)*32 + lane], a3);
    }
    float agg = (a0 + a1) + (a2 + a3);
    float xv = x[(b*n + row)*32 + lane];
    csT[lane][w] = xv;
    csT[32 + lane][w] = agg;
    __syncthreads();
    mlp8_hidden(csT, hs, bn1, tid);
    __syncthreads();
    float res = csT[lane][w] + mlp_out_row(hs[w], lane, bn2);
    out[(b*n + row)*32 + lane] = res;
    es[w][lane] = res;
    __syncwarp();

    float r8[8];
    if constexpr (MODE <= 1) {
        proj8(es[w], lane, g_CA, g_cbA, r8);
        float* dst = Aout + (b*n + row)*256 + lane*8;
        *(float4*)dst       = make_float4(r8[0], r8[1], r8[2], r8[3]);
        *(float4*)(dst + 4) = make_float4(r8[4], r8[5], r8[6], r8[7]);
    } else {
        proj8(es[w], lane, g_CB, g_cbB, r8);
        float v0 = bv[lane], v1 = 0.f;
        #pragma unroll 8
        for (int d = 0; d < 32; d += 2) {
            v0 = fmaf(es[w][d],   g_WvT[d*32 + lane],     v0);
            v1 = fmaf(es[w][d+1], g_WvT[(d+1)*32 + lane], v1);
        }
        yvout[(b*n + row)*32 + lane] = v0 + v1;
        __syncthreads();
        *(float4*)&hs[w][lane*8]     = make_float4(r8[0], r8[1], r8[2], r8[3]);
        *(float4*)&hs[w][lane*8 + 4] = make_float4(r8[4], r8[5], r8[6], r8[7]);
        __syncthreads();
        int t = tid;
        float* dst = Bout + b*256*n + t*n + chunk*8;
        *(float4*)dst       = make_float4(hs[0][t], hs[1][t], hs[2][t], hs[3][t]);
        *(float4*)(dst + 4) = make_float4(hs[4][t], hs[5][t], hs[6][t], hs[7][t]);
    }
}

__global__ void __launch_bounds__(256) intra_kernel(
        const float* __restrict__ robot, const float* __restrict__ frontier,
        const float* __restrict__ rh, const float* __restrict__ fh,
        const float* __restrict__ bn1, const float* __restrict__ bn2,
        const float* __restrict__ bv,
        float* __restrict__ f_out, float* __restrict__ rh_out, float* __restrict__ fh_out) {
    __shared__ __align__(16) float qs[8][32];
    __shared__ __align__(16) float es[8][128];
    __shared__ __align__(16) float csT[64][8];
    __shared__ __align__(16) float hs[8][256];
    int b = blockIdx.x / 36, c = blockIdx.x % 36;
    if (c < 4)
        intra_body<1,0>(robot, g_R1, bn1, bn2, bv, b, c, 0,
                        qs, es, csT, hs, g_A1, nullptr, nullptr);
    else if (c < 20)
        intra_body<4,1>(frontier, f_out, bn1, bn2, bv, b, c-4, 1024,
                        qs, es, csT, hs, g_A2, nullptr, nullptr);
    else if (c < 28)
        intra_body<2,2>(rh, rh_out, bn1, bn2, bv, b, c-20, 5120,
                        qs, es, csT, hs, nullptr, g_B1t, g_yv1);
    else
        intra_body<2,3>(fh, fh_out, bn1, bn2, bv, b, c-28, 7168,
                        qs, es, csT, hs, nullptr, g_B2t, g_yv2);
}

// ============================================================================
// Edge kernel, generic t-split: ROWS rows/block x SPLIT t-chunks, 32*ROWS*SPLIT thr.
// MODE: 0=inter1(xout, Atail) 1=inter2(Btail/yvtail) 2=inter3(xout + eout)
// ============================================================================
template<int R, int SPLIT, int ROWS>
struct __align__(16) ESmem {
    float As[ROWS][256];
    float scp[ROWS][SPLIT][32*R];
    float es[ROWS][32*R];
    float aggp[ROWS][SPLIT][32];
    float csT[64][ROWS];
    float hs[ROWS][256];
    float hp2[ROWS][256];
    float rs[ROWS][32];
    float w65s[256];
    float we2s[256];
};

template<int R, int SPLIT, int ROWS, int MODE>
__device__ __forceinline__ void edge_run(
        ESmem<R,SPLIT,ROWS>* sm,
        const float* __restrict__ x, const float* __restrict__ dis,
        const float* __restrict__ A, const float* __restrict__ Bt,
        const float* __restrict__ yv,
        const float* __restrict__ bn1, const float* __restrict__ bn2,
        const float* __restrict__ bv, const float* __restrict__ We2,
        float* __restrict__ xout, float* __restrict__ eout,
        int Nx, int b, int i0,
        float* __restrict__ Atail, float* __restrict__ Btail,
        float* __restrict__ yvtail) {
    constexpr int Ny  = 32*R;
    constexpr int TCH = 256/SPLIT;     // t per warp
    constexpr int SEG = Ny/SPLIT;      // aggregate span per warp
    int tid = threadIdx.x, w = tid >> 5, lane = tid & 31;
    int r = w / SPLIT, sp = w % SPLIT;
    int i = i0 + r;

    if (tid < 256) { sm->w65s[tid] = g_w65[tid]; sm->we2s[tid] = We2[tid]; }
    {
        constexpr int PER = 64/SPLIT;
        if (lane < PER) {
            const float4* Ar = (const float4*)(A + (b*Nx + i)*256);
            ((float4*)(sm->As[r]))[sp*PER + lane] = Ar[sp*PER + lane];
        }
    }
    __syncthreads();

    const float* dr = dis + (b*Nx + i)*Ny;
    float dv[R];
    if constexpr (R == 4) {
        float4 t4 = *(const float4*)&dr[lane*4];
        dv[0]=t4.x; dv[1]=t4.y; dv[2]=t4.z; dv[3]=t4.w;
    } else {
        float2 t2 = *(const float2*)&dr[lane*2];
        dv[0]=t2.x; dv[1]=t2.y;
    }
    float sc[2][R];
    #pragma unroll
    for (int u = 0; u < 2; u++)
        #pragma unroll
        for (int k = 0; k < R; k++) sc[u][k] = 0.f;
    const float* Bb   = Bt + (b*256 + sp*TCH)*Ny;
    const float* Ahs  = sm->As[r] + sp*TCH;
    const float* w65h = sm->w65s + sp*TCH;
    const float* we2h = sm->we2s + sp*TCH;
    #pragma unroll 2
    for (int tt = 0; tt < TCH; tt += 4) {
        float4 a4 = *(const float4*)&Ahs[tt];
        float4 w6 = *(const float4*)&w65h[tt];
        float4 w2 = *(const float4*)&we2h[tt];
        float av[4]  = {a4.x, a4.y, a4.z, a4.w};
        float w6v[4] = {w6.x, w6.y, w6.z, w6.w};
        float w2v[4] = {w2.x, w2.y, w2.z, w2.w};
        #pragma unroll
        for (int u = 0; u < 4; u++) {
            float* scp = sc[u & 1];
            if constexpr (R == 4) {
                float4 Bv = *(const float4*)&Bb[(tt+u)*Ny + lane*4];
                float hh;
                hh = fmaf(w6v[u], dv[0], av[u] + Bv.x); scp[0] = fmaf(w2v[u], fmaxf(hh, 0.f), scp[0]);
                hh = fmaf(w6v[u], dv[1], av[u] + Bv.y); scp[1] = fmaf(w2v[u], fmaxf(hh, 0.f), scp[1]);
                hh = fmaf(w6v[u], dv[2], av[u] + Bv.z); scp[2] = fmaf(w2v[u], fmaxf(hh, 0.f), scp[2]);
                hh = fmaf(w6v[u], dv[3], av[u] + Bv.w); scp[3] = fmaf(w2v[u], fmaxf(hh, 0.f), scp[3]);
            } else {
                float2 Bv = *(const float2*)&Bb[(tt+u)*Ny + lane*2];
                float hh;
                hh = fmaf(w6v[u], dv[0], av[u] + Bv.x); scp[0] = fmaf(w2v[u], fmaxf(hh, 0.f), scp[0]);
                hh = fmaf(w6v[u], dv[1], av[u] + Bv.y); scp[1] = fmaf(w2v[u], fmaxf(hh, 0.f), scp[1]);
            }
        }
    }
    if constexpr (R == 4) {
        *(float4*)&sm->scp[r][sp][lane*4] = make_float4(sc[0][0]+sc[1][0], sc[0][1]+sc[1][1],
                                                        sc[0][2]+sc[1][2], sc[0][3]+sc[1][3]);
    } else {
        *(float2*)&sm->scp[r][sp][lane*2] = make_float2(sc[0][0]+sc[1][0], sc[0][1]+sc[1][1]);
    }
    __syncthreads();

    if (sp == 0) {
        float s[R];
        #pragma unroll
        for (int k = 0; k < R; k++) {
            float acc = 0.f;
            #pragma unroll
            for (int q = 0; q < SPLIT; q++) acc += sm->scp[r][q][lane*R + k];
            s[k] = acc;
        }
        float mx = s[0];
        #pragma unroll
        for (int k = 1; k < R; k++) mx = fmaxf(mx, s[k]);
        #pragma unroll
        for (int o = 16; o; o >>= 1) mx = fmaxf(mx, __shfl_xor_sync(0xffffffffu, mx, o));
        float sum = 0.f;
        #pragma unroll
        for (int k = 0; k < R; k++) { s[k] = __expf(s[k] - mx); sum += s[k]; }
        #pragma unroll
        for (int o = 16; o; o >>= 1) sum += __shfl_xor_sync(0xffffffffu, sum, o);
        float inv = 1.f / sum;
        if constexpr (R == 4) {
            float4 p = make_float4(s[0]*inv, s[1]*inv, s[2]*inv, s[3]*inv);
            *(float4*)&sm->es[r][lane*4] = p;
            if (MODE == 2) *(float4*)&eout[(b*Nx + i)*Ny + lane*4] = p;
        } else {
            *(float2*)&sm->es[r][lane*2] = make_float2(s[0]*inv, s[1]*inv);
        }
    }
    __syncthreads();

    {
        const float* yvb = yv + (b*Ny + sp*SEG)*32;
        const float* esr = sm->es[r] + sp*SEG;
        float a0 = 0.f, a1 = 0.f, a2 = 0.f, a3 = 0.f;
        #pragma unroll 4
        for (int m = 0; m < SEG; m += 4) {
            a0 = fmaf(esr[m],   yvb[(m)*32 + lane],   a0);
            a1 = fmaf(esr[m+1], yvb[(m+1)*32 + lane], a1);
            a2 = fmaf(esr[m+2], yvb[(m+2)*32 + lane], a2);
            a3 = fmaf(esr[m+3], yvb[(m+3)*32 + lane], a3);
        }
        sm->aggp[r][sp][lane] = (a0 + a1) + (a2 + a3);
    }
    __syncthreads();
    if (w < ROWS) {
        int rr = w, ii = i0 + rr;
        float xv = x[(b*Nx + ii)*32 + lane];
        float acc = 0.f;
        #pragma unroll
        for (int q = 0; q < SPLIT; q++) acc += sm->aggp[rr][q][lane];
        sm->csT[lane][rr] = xv;
        sm->csT[32 + lane][rr] = acc;
    }
    __syncthreads();

    // node-MLP hidden: i-split across all threads
    float h[ROWS];
    if (tid < 256) {
        float bb = bn1[tid];
        #pragma unroll
        for (int rr = 0; rr < ROWS; rr++) h[rr] = bb;
        #pragma unroll 8
        for (int ii2 = 0; ii2 < 32; ii2++) {
            float wv = g_Wn1T[ii2*256 + tid];
            #pragma unroll
            for (int rr = 0; rr < ROWS; rr++) h[rr] = fmaf(wv, sm->csT[ii2][rr], h[rr]);
        }
    } else {
        int t2 = tid - 256;
        #pragma unroll
        for (int rr = 0; rr < ROWS; rr++) h[rr] = 0.f;
        #pragma unroll 8
        for (int ii2 = 32; ii2 < 64; ii2++) {
            float wv = g_Wn1T[ii2*256 + t2];
            #pragma unroll
            for (int rr = 0; rr < ROWS; rr++) h[rr] = fmaf(wv, sm->csT[ii2][rr], h[rr]);
        }
        #pragma unroll
        for (int rr = 0; rr < ROWS; rr++) sm->hp2[rr][t2] = h[rr];
    }
    __syncthreads();
    if (tid < 256) {
        #pragma unroll
        for (int rr = 0; rr < ROWS; rr++)
            sm->hs[rr][tid] = fmaxf(h[rr] + sm->hp2[rr][tid], 0.f);
    }
    __syncthreads();

    if (w < ROWS) {
        int ii = i0 + w;
        float res = sm->csT[lane][w] + mlp_out_row(sm->hs[w], lane, bn2);
        if (MODE == 0 || MODE == 2) xout[(b*Nx + ii)*32 + lane] = res;
        sm->rs[w][lane] = res;
    }
    __syncwarp();
    if constexpr (MODE == 0) {
        if (w < ROWS) {
            int ii = i0 + w;
            float r8[8];
            proj8(sm->rs[w], lane, g_CA, g_cbA, r8);
            float* dst = Atail + (b*Nx + ii)*256 + lane*8;
            *(float4*)dst       = make_float4(r8[0], r8[1], r8[2], r8[3]);
            *(float4*)(dst + 4) = make_float4(r8[4], r8[5], r8[6], r8[7]);
        }
    } else if constexpr (MODE == 1) {
        if (w < ROWS) {
            int ii = i0 + w;
            float r8[8];
            proj8(sm->rs[w], lane, g_CB, g_cbB, r8);
            *(float4*)&sm->hs[w][lane*8]     = make_float4(r8[0], r8[1], r8[2], r8[3]);
            *(float4*)&sm->hs[w][lane*8 + 4] = make_float4(r8[4], r8[5], r8[6], r8[7]);
            float v0 = bv[lane], v1 = 0.f;
            #pragma unroll 8
            for (int d = 0; d < 32; d += 2) {
                v0 = fmaf(sm->rs[w][d],   g_WvT[d*32 + lane],     v0);
                v1 = fmaf(sm->rs[w][d+1], g_WvT[(d+1)*32 + lane], v1);
            }
            yvtail[(b*Nx + ii)*32 + lane] = v0 + v1;
        }
        __syncthreads();
        if (tid < 256) {
            int t = tid;
            float* dst = Btail + b*256*128 + t*128 + i0;
            static_assert(ROWS == 4, "MODE 1 expects ROWS==4");
            *(float4*)dst = make_float4(sm->hs[0][t], sm->hs[1][t], sm->hs[2][t], sm->hs[3][t]);
        }
    }
}

// inter1 (256 blocks) + inter2 (1024 blocks). grid 1280, block 512.
__global__ void __launch_bounds__(512, 3) edge12_kernel(
        const float* __restrict__ f_in, const float* __restrict__ rp,
        const float* __restrict__ fpd,
        const float* __restrict__ bn1, const float* __restrict__ bn2,
        const float* __restrict__ We2, const float* __restrict__ bv) {
    __shared__ __align__(16) ESmem<2,4,4> sm;
    int blk = blockIdx.x;
    if (blk < 256) {
        int b = blk >> 3, i0 = (blk & 7)*4;
        edge_run<2,4,4,0>(&sm, g_R1, rp, g_A1, g_B1t, g_yv1, bn1, bn2, bv, We2,
                          g_R2, nullptr, 32, b, i0, g_A3, nullptr, nullptr);
    } else {
        blk -= 256;
        int b = blk >> 5, i0 = (blk & 31)*4;
        edge_run<2,4,4,1>(&sm, f_in, fpd, g_A2, g_B2t, g_yv2, bn1, bn2, bv, We2,
                          nullptr, nullptr, 128, b, i0, nullptr, g_B3t, g_yv3);
    }
}

// inter3: robot <- new_frontier. grid 512, block 512 (2 rows x 8 t-eighths).
__global__ void __launch_bounds__(512, 3) edge3_kernel(
        const float* __restrict__ rf,
        const float* __restrict__ bn1, const float* __restrict__ bn2,
        const float* __restrict__ We2, const float* __restrict__ bv,
        float* __restrict__ r_out, float* __restrict__ e_out) {
    __shared__ __align__(16) ESmem<4,8,2> sm;
    int b = blockIdx.x >> 4, i0 = (blockIdx.x & 15)*2;
    edge_run<4,8,2,2>(&sm, g_R2, rf, g_A3, g_B3t, g_yv3, bn1, bn2, bv, We2,
                      r_out, e_out, 32, b, i0, nullptr, nullptr, nullptr);
}

// ============================================================================
extern "C" void kernel_launch(void* const* d_in, const int* in_sizes, int n_in,
                              void* d_out, int out_size) {
    const float* robot    = (const float*)d_in[0];
    const float* frontier = (const float*)d_in[1];
    const float* rh       = (const float*)d_in[2];
    const float* fh       = (const float*)d_in[3];
    const float* rf       = (const float*)d_in[4];
    const float* rp       = (const float*)d_in[5];
    const float* fpd      = (const float*)d_in[6];
    const float* Wq  = (const float*)d_in[7];  const float* bq  = (const float*)d_in[8];
    const float* Wk  = (const float*)d_in[9];  const float* bk  = (const float*)d_in[10];
    const float* Wv  = (const float*)d_in[11]; const float* bv  = (const float*)d_in[12];
    const float* Wn1 = (const float*)d_in[13]; const float* bn1 = (const float*)d_in[14];
    const float* Wn2 = (const float*)d_in[15]; const float* bn2 = (const float*)d_in[16];
    const float* We1 = (const float*)d_in[17]; const float* be1 = (const float*)d_in[18];
    const float* We2 = (const float*)d_in[19];
    // d_in[20] = be2: softmax-invariant, unused.

    float* out    = (float*)d_out;
    float* r_out  = out;
    float* f_out  = r_out  + 32*32*32;
    float* rh_out = f_out  + 32*128*32;
    float* fh_out = rh_out + 32*64*32;
    float* e_out  = fh_out + 32*64*32;

    prep_kernel<<<57, 256>>>(Wq, bq, Wk, bk, Wv, Wn1, Wn2, We1, be1);
    qkv_kernel<<<32*36, 256>>>(robot, frontier, rh, fh, bq, bk, bv);
    intra_kernel<<<32*36, 256>>>(robot, frontier, rh, fh, bn1, bn2, bv,
                                 f_out, rh_out, fh_out);
    edge12_kernel<<<1280, 512>>>(f_out, rp, fpd, bn1, bn2, We2, bv);
    edge3_kernel<<<512, 512>>>(rf, bn1, bn2, We2, bv, r_out, e_out);
}

// round 8
// speedup vs baseline: 4.4533x; 1.1400x over previous
#include <cuda_runtime.h>
#include <math.h>

#define BV 32

// ---------------- weight scratch ----------------
__device__ __align__(16) float g_WqT[1024];
__device__ __align__(16) float g_WkT[1024];
__device__ __align__(16) float g_WvT[1024];
__device__ __align__(16) float g_Wn1T[64*256];    // [i][j]
__device__ __align__(16) float g_Wn2q[64*32*4];   // [jg][d][4] quad-packed Wn2
__device__ __align__(16) float g_CA[32*256];      // [d][j]
__device__ __align__(16) float g_CB[32*256];
__device__ __align__(16) float g_cbA[256];
__device__ __align__(16) float g_cbB[256];        // includes be1
__device__ __align__(16) float g_w65[256];

// ---------------- activation scratch ----------------
__device__ __align__(16) float g_q [9216*32];
__device__ __align__(16) float g_v [9216*32];
__device__ __align__(16) float g_kT[9216*32];     // per seg: [b][d][node]

__device__ __align__(16) float g_R1 [BV*32*32];
__device__ __align__(16) float g_R2 [BV*32*32];
__device__ __align__(16) float g_A1 [BV*32*256];
__device__ __align__(16) float g_A2 [BV*128*256];
__device__ __align__(16) float g_A3 [BV*32*256];
__device__ __align__(16) float g_B1t[BV*256*64];  // [b][t][node]
__device__ __align__(16) float g_B2t[BV*256*64];
__device__ __align__(16) float g_B3t[BV*256*128];
__device__ __align__(16) float g_yv1[BV*64*32];
__device__ __align__(16) float g_yv2[BV*64*32];
__device__ __align__(16) float g_yv3[BV*128*32];

// ============================================================================
// prep: weight transposes + edge-MLP folding + Wn2 quad-pack. grid 57.
// ============================================================================
__global__ void prep_kernel(const float* __restrict__ Wq, const float* __restrict__ bq,
                            const float* __restrict__ Wk, const float* __restrict__ bk,
                            const float* __restrict__ Wv, const float* __restrict__ Wn1,
                            const float* __restrict__ Wn2,
                            const float* __restrict__ We1, const float* __restrict__ be1) {
    int blk = blockIdx.x, t = threadIdx.x;
    if (blk < 32) {
        int d = blk, j = t;
        float a = 0.f, b2 = 0.f;
        #pragma unroll 8
        for (int i = 0; i < 32; i++) {
            a  += Wq[i*32 + d] * We1[j*65 + i];
            b2 += Wk[i*32 + d] * We1[j*65 + 32 + i];
        }
        g_CA[d*256 + j] = a;
        g_CB[d*256 + j] = b2;
    } else if (blk == 32) {
        for (int idx = t; idx < 1024; idx += 256) {
            int d = idx >> 5, dd = idx & 31;
            g_WqT[dd*32 + d] = Wq[idx];
            g_WkT[dd*32 + d] = Wk[idx];
            g_WvT[dd*32 + d] = Wv[idx];
        }
        float ca = 0.f, cb2 = 0.f;
        #pragma unroll 8
        for (int i = 0; i < 32; i++) {
            ca  += We1[t*65 + i]      * bq[i];
            cb2 += We1[t*65 + 32 + i] * bk[i];
        }
        g_cbA[t] = ca;
        g_cbB[t] = cb2 + be1[t];
        g_w65[t] = We1[t*65 + 64];
    } else if (blk < 49) {
        int base = (blk - 33) * 1024;
        for (int k = t; k < 1024; k += 256) {
            int idx = base + k;
            int j = idx >> 6, i = idx & 63;
            g_Wn1T[i*256 + j] = Wn1[idx];
        }
    } else {
        int base = (blk - 49) * 1024;
        for (int k = t; k < 1024; k += 256) {
            int f = base + k;
            int jg = f >> 7, rem = f & 127;
            int d = rem >> 2, u = rem & 3;
            g_Wn2q[f] = Wn2[d*256 + jg*4 + u];
        }
    }
}

// ============================================================================
// qkv: warp per node, lane = d. grid 32*36, block 256 (8 nodes).
// ============================================================================
__global__ void __launch_bounds__(256) qkv_kernel(
        const float* __restrict__ robot, const float* __restrict__ frontier,
        const float* __restrict__ rh, const float* __restrict__ fh,
        const float* __restrict__ bq, const float* __restrict__ bk,
        const float* __restrict__ bv) {
    __shared__ float ks[32][9];
    int tid = threadIdx.x, w = tid >> 5, lane = tid & 31;
    int b = blockIdx.x / 36, c = blockIdx.x % 36;
    const float* x; int n, chunk, rowbase;
    if (c < 4)       { x = robot;    n = 32;  chunk = c;      rowbase = 0; }
    else if (c < 20) { x = frontier; n = 128; chunk = c - 4;  rowbase = 1024; }
    else if (c < 28) { x = rh;       n = 64;  chunk = c - 20; rowbase = 5120; }
    else             { x = fh;       n = 64;  chunk = c - 28; rowbase = 7168; }
    int node = chunk*8 + w;
    float xval = x[(b*n + node)*32 + lane];
    float q = bq[lane], k = bk[lane], v = bv[lane];
    #pragma unroll 8
    for (int dd = 0; dd < 32; dd++) {
        float xv = __shfl_sync(0xffffffffu, xval, dd);
        q = fmaf(xv, g_WqT[dd*32 + lane], q);
        k = fmaf(xv, g_WkT[dd*32 + lane], k);
        v = fmaf(xv, g_WvT[dd*32 + lane], v);
    }
    int grow = rowbase + b*n + node;
    g_q[grow*32 + lane] = q;
    g_v[grow*32 + lane] = v;
    ks[lane][w] = k;
    __syncthreads();
    int d = tid >> 3, nd = tid & 7;
    g_kT[rowbase*32 + b*32*n + d*n + chunk*8 + nd] = ks[d][nd];
}

// ============================================================================
// node MLP helpers
// ============================================================================
__device__ __forceinline__ void mlp8_hidden(const float (*csT)[8], float (*hs)[256],
        const float* __restrict__ bn1, int tid) {
    float h[8];
    float b = bn1[tid];
    #pragma unroll
    for (int r = 0; r < 8; r++) h[r] = b;
    #pragma unroll 8
    for (int i = 0; i < 64; i++) {
        float wv = g_Wn1T[i*256 + tid];
        float4 c0 = *(const float4*)&csT[i][0];
        float4 c1 = *(const float4*)&csT[i][4];
        h[0] = fmaf(wv, c0.x, h[0]); h[1] = fmaf(wv, c0.y, h[1]);
        h[2] = fmaf(wv, c0.z, h[2]); h[3] = fmaf(wv, c0.w, h[3]);
        h[4] = fmaf(wv, c1.x, h[4]); h[5] = fmaf(wv, c1.y, h[5]);
        h[6] = fmaf(wv, c1.z, h[6]); h[7] = fmaf(wv, c1.w, h[7]);
    }
    #pragma unroll
    for (int r = 0; r < 8; r++) hs[r][tid] = fmaxf(h[r], 0.f);
}

__device__ __forceinline__ float mlp_out_row(const float* __restrict__ hsr, int lane,
        const float* __restrict__ bn2) {
    float o0 = bn2[lane], o1 = 0.f, o2 = 0.f, o3 = 0.f;
    #pragma unroll 4
    for (int jg = 0; jg < 64; jg++) {
        float4 hv = *(const float4*)&hsr[jg*4];
        float4 wv = *(const float4*)&g_Wn2q[(jg*32 + lane)*4];
        o0 = fmaf(hv.x, wv.x, o0); o1 = fmaf(hv.y, wv.y, o1);
        o2 = fmaf(hv.z, wv.z, o2); o3 = fmaf(hv.w, wv.w, o3);
    }
    return (o0 + o1) + (o2 + o3);
}

__device__ __forceinline__ void proj8(const float* __restrict__ csw, int lane,
        const float* __restrict__ C, const float* __restrict__ cb, float* r) {
    int j0 = lane*8;
    float4 a0 = *(const float4*)&cb[j0];
    float4 a1 = *(const float4*)&cb[j0 + 4];
    #pragma unroll 4
    for (int d = 0; d < 32; d++) {
        float c = csw[d];
        float4 w0 = *(const float4*)&C[d*256 + j0];
        float4 w1 = *(const float4*)&C[d*256 + j0 + 4];
        a0.x = fmaf(c, w0.x, a0.x); a0.y = fmaf(c, w0.y, a0.y);
        a0.z = fmaf(c, w0.z, a0.z); a0.w = fmaf(c, w0.w, a0.w);
        a1.x = fmaf(c, w1.x, a1.x); a1.y = fmaf(c, w1.y, a1.y);
        a1.z = fmaf(c, w1.z, a1.z); a1.w = fmaf(c, w1.w, a1.w);
    }
    r[0]=a0.x; r[1]=a0.y; r[2]=a0.z; r[3]=a0.w;
    r[4]=a1.x; r[5]=a1.y; r[6]=a1.z; r[7]=a1.w;
}

// ============================================================================
// Intra: attention + coop MLP + projection tail. Warp per row, 8 rows/block.
// ============================================================================
template<int NMI, int MODE>
__device__ __forceinline__ void intra_body(
        const float* __restrict__ x, float* __restrict__ out,
        const float* __restrict__ bn1, const float* __restrict__ bn2,
        const float* __restrict__ bv,
        int b, int chunk, int rowbase,
        float (*qs)[32], float (*es)[128], float (*csT)[8], float (*hs)[256],
        float* __restrict__ Aout, float* __restrict__ Bout, float* __restrict__ yvout) {
    constexpr int n = NMI*32;
    int tid = threadIdx.x, w = tid >> 5, lane = tid & 31;
    int row = chunk*8 + w;
    int grow = rowbase + b*n + row;
    qs[w][lane] = g_q[grow*32 + lane];
    __syncwarp();

    const float* kTg = g_kT + rowbase*32 + b*32*n;
    float s[NMI];
    #pragma unroll
    for (int k = 0; k < NMI; k++) s[k] = 0.f;
    #pragma unroll 8
    for (int d = 0; d < 32; d++) {
        float qd = qs[w][d];
        if constexpr (NMI == 4) {
            float4 kv = *(const float4*)&kTg[d*n + lane*4];
            s[0] = fmaf(qd, kv.x, s[0]); s[1] = fmaf(qd, kv.y, s[1]);
            s[2] = fmaf(qd, kv.z, s[2]); s[3] = fmaf(qd, kv.w, s[3]);
        } else if constexpr (NMI == 2) {
            float2 kv = *(const float2*)&kTg[d*n + lane*2];
            s[0] = fmaf(qd, kv.x, s[0]); s[1] = fmaf(qd, kv.y, s[1]);
        } else {
            s[0] = fmaf(qd, kTg[d*n + lane], s[0]);
        }
    }
    float mx = s[0];
    #pragma unroll
    for (int k = 1; k < NMI; k++) mx = fmaxf(mx, s[k]);
    #pragma unroll
    for (int o = 16; o; o >>= 1) mx = fmaxf(mx, __shfl_xor_sync(0xffffffffu, mx, o));
    float sum = 0.f;
    #pragma unroll
    for (int k = 0; k < NMI; k++) { s[k] = __expf(s[k] - mx); sum += s[k]; }
    #pragma unroll
    for (int o = 16; o; o >>= 1) sum += __shfl_xor_sync(0xffffffffu, sum, o);
    float inv = 1.f / sum;
    if constexpr (NMI == 4) {
        *(float4*)&es[w][lane*4] = make_float4(s[0]*inv, s[1]*inv, s[2]*inv, s[3]*inv);
    } else if constexpr (NMI == 2) {
        *(float2*)&es[w][lane*2] = make_float2(s[0]*inv, s[1]*inv);
    } else {
        es[w][lane] = s[0]*inv;
    }
    __syncwarp();
    const float* vg = g_v + (rowbase + b*n)*32;
    float a0 = 0.f, a1 = 0.f, a2 = 0.f, a3 = 0.f;
    #pragma unroll 4
    for (int m = 0; m < n; m += 4) {
        a0 = fmaf(es[w][m],   vg[(m)*32 + lane],   a0);
        a1 = fmaf(es[w][m+1], vg[(m+1)*32 + lane], a1);
        a2 = fmaf(es[w][m+2], vg[(m+2)*32 + lane], a2);
        a3 = fmaf(es[w][m+3], vg[(m+3)*32 + lane], a3);
    }
    float agg = (a0 + a1) + (a2 + a3);
    float xv = x[(b*n + row)*32 + lane];
    csT[lane][w] = xv;
    csT[32 + lane][w] = agg;
    __syncthreads();
    mlp8_hidden(csT, hs, bn1, tid);
    __syncthreads();
    float res = csT[lane][w] + mlp_out_row(hs[w], lane, bn2);
    out[(b*n + row)*32 + lane] = res;
    es[w][lane] = res;
    __syncwarp();

    float r8[8];
    if constexpr (MODE <= 1) {
        proj8(es[w], lane, g_CA, g_cbA, r8);
        float* dst = Aout + (b*n + row)*256 + lane*8;
        *(float4*)dst       = make_float4(r8[0], r8[1], r8[2], r8[3]);
        *(float4*)(dst + 4) = make_float4(r8[4], r8[5], r8[6], r8[7]);
    } else {
        proj8(es[w], lane, g_CB, g_cbB, r8);
        float v0 = bv[lane], v1 = 0.f;
        #pragma unroll 8
        for (int d = 0; d < 32; d += 2) {
            v0 = fmaf(es[w][d],   g_WvT[d*32 + lane],     v0);
            v1 = fmaf(es[w][d+1], g_WvT[(d+1)*32 + lane], v1);
        }
        yvout[(b*n + row)*32 + lane] = v0 + v1;
        __syncthreads();
        *(float4*)&hs[w][lane*8]     = make_float4(r8[0], r8[1], r8[2], r8[3]);
        *(float4*)&hs[w][lane*8 + 4] = make_float4(r8[4], r8[5], r8[6], r8[7]);
        __syncthreads();
        int t = tid;
        float* dst = Bout + b*256*n + t*n + chunk*8;
        *(float4*)dst       = make_float4(hs[0][t], hs[1][t], hs[2][t], hs[3][t]);
        *(float4*)(dst + 4) = make_float4(hs[4][t], hs[5][t], hs[6][t], hs[7][t]);
    }
}

__global__ void __launch_bounds__(256) intra_kernel(
        const float* __restrict__ robot, const float* __restrict__ frontier,
        const float* __restrict__ rh, const float* __restrict__ fh,
        const float* __restrict__ bn1, const float* __restrict__ bn2,
        const float* __restrict__ bv,
        float* __restrict__ f_out, float* __restrict__ rh_out, float* __restrict__ fh_out) {
    __shared__ __align__(16) float qs[8][32];
    __shared__ __align__(16) float es[8][128];
    __shared__ __align__(16) float csT[64][8];
    __shared__ __align__(16) float hs[8][256];
    int b = blockIdx.x / 36, c = blockIdx.x % 36;
    if (c < 4)
        intra_body<1,0>(robot, g_R1, bn1, bn2, bv, b, c, 0,
                        qs, es, csT, hs, g_A1, nullptr, nullptr);
    else if (c < 20)
        intra_body<4,1>(frontier, f_out, bn1, bn2, bv, b, c-4, 1024,
                        qs, es, csT, hs, g_A2, nullptr, nullptr);
    else if (c < 28)
        intra_body<2,2>(rh, rh_out, bn1, bn2, bv, b, c-20, 5120,
                        qs, es, csT, hs, nullptr, g_B1t, g_yv1);
    else
        intra_body<2,3>(fh, fh_out, bn1, bn2, bv, b, c-28, 7168,
                        qs, es, csT, hs, nullptr, g_B2t, g_yv2);
}

// ============================================================================
// Edge kernel: warp = t-chunk; each warp processes ALL ROWS rows so every
// B / yv load is reused ROWS x in registers. 256 threads = 8 t-chunks.
// MODE: 0=inter1(xout, Atail) 1=inter2(Btail/yvtail) 2=inter3(xout + eout)
// ============================================================================
template<int R, int ROWS>
struct __align__(16) ESmem {
    float As[ROWS][256];
    float scp[ROWS][8][32*R];
    float es[ROWS][32*R];
    float aggp[ROWS][8][32];
    float csT[64][ROWS];
    float hs[ROWS][256];
    float rs[ROWS][32];
    float w65s[256];
    float we2s[256];
};

template<int R, int ROWS, int MODE>
__device__ __forceinline__ void edge_run(
        ESmem<R,ROWS>* sm,
        const float* __restrict__ x, const float* __restrict__ dis,
        const float* __restrict__ A, const float* __restrict__ Bt,
        const float* __restrict__ yv,
        const float* __restrict__ bn1, const float* __restrict__ bn2,
        const float* __restrict__ bv, const float* __restrict__ We2,
        float* __restrict__ xout, float* __restrict__ eout,
        int Nx, int b, int i0,
        float* __restrict__ Atail, float* __restrict__ Btail,
        float* __restrict__ yvtail) {
    constexpr int Ny  = 32*R;
    constexpr int TCH = 32;            // t per warp (256/8)
    constexpr int SEG = Ny/8;          // aggregate span per warp
    int tid = threadIdx.x, w = tid >> 5, lane = tid & 31;
    int sp = w;                        // t-chunk id

    sm->w65s[tid] = g_w65[tid];
    sm->we2s[tid] = We2[tid];
    // A rows into smem: warp w loads its 32-col slice for each row
    #pragma unroll
    for (int r = 0; r < ROWS; r++) {
        const float* Ar = A + (b*Nx + i0 + r)*256;
        sm->As[r][w*32 + lane] = Ar[w*32 + lane];
    }
    __syncthreads();

    // dis for all rows
    float dv[ROWS][R];
    #pragma unroll
    for (int r = 0; r < ROWS; r++) {
        const float* dr = dis + (b*Nx + i0 + r)*Ny;
        if constexpr (R == 4) {
            float4 t4 = *(const float4*)&dr[lane*4];
            dv[r][0]=t4.x; dv[r][1]=t4.y; dv[r][2]=t4.z; dv[r][3]=t4.w;
        } else {
            float2 t2 = *(const float2*)&dr[lane*2];
            dv[r][0]=t2.x; dv[r][1]=t2.y;
        }
    }
    float sc[ROWS][R];
    #pragma unroll
    for (int r = 0; r < ROWS; r++)
        #pragma unroll
        for (int k = 0; k < R; k++) sc[r][k] = 0.f;

    const float* Bb = Bt + (b*256 + sp*TCH)*Ny;
    #pragma unroll 2
    for (int tt = 0; tt < TCH; tt += 4) {
        int t = sp*TCH + tt;
        float4 w6 = *(const float4*)&sm->w65s[t];
        float4 w2 = *(const float4*)&sm->we2s[t];
        float w6v[4] = {w6.x, w6.y, w6.z, w6.w};
        float w2v[4] = {w2.x, w2.y, w2.z, w2.w};
        float av[ROWS][4];
        #pragma unroll
        for (int r = 0; r < ROWS; r++) {
            float4 a4 = *(const float4*)&sm->As[r][t];
            av[r][0]=a4.x; av[r][1]=a4.y; av[r][2]=a4.z; av[r][3]=a4.w;
        }
        #pragma unroll
        for (int u = 0; u < 4; u++) {
            if constexpr (R == 4) {
                float4 Bv = *(const float4*)&Bb[(tt+u)*Ny + lane*4];
                #pragma unroll
                for (int r = 0; r < ROWS; r++) {
                    float base = av[r][u];
                    float hh;
                    hh = fmaf(w6v[u], dv[r][0], base + Bv.x); sc[r][0] = fmaf(w2v[u], fmaxf(hh, 0.f), sc[r][0]);
                    hh = fmaf(w6v[u], dv[r][1], base + Bv.y); sc[r][1] = fmaf(w2v[u], fmaxf(hh, 0.f), sc[r][1]);
                    hh = fmaf(w6v[u], dv[r][2], base + Bv.z); sc[r][2] = fmaf(w2v[u], fmaxf(hh, 0.f), sc[r][2]);
                    hh = fmaf(w6v[u], dv[r][3], base + Bv.w); sc[r][3] = fmaf(w2v[u], fmaxf(hh, 0.f), sc[r][3]);
                }
            } else {
                float2 Bv = *(const float2*)&Bb[(tt+u)*Ny + lane*2];
                #pragma unroll
                for (int r = 0; r < ROWS; r++) {
                    float base = av[r][u];
                    float hh;
                    hh = fmaf(w6v[u], dv[r][0], base + Bv.x); sc[r][0] = fmaf(w2v[u], fmaxf(hh, 0.f), sc[r][0]);
                    hh = fmaf(w6v[u], dv[r][1], base + Bv.y); sc[r][1] = fmaf(w2v[u], fmaxf(hh, 0.f), sc[r][1]);
                }
            }
        }
    }
    #pragma unroll
    for (int r = 0; r < ROWS; r++) {
        if constexpr (R == 4) {
            *(float4*)&sm->scp[r][sp][lane*4] = make_float4(sc[r][0], sc[r][1], sc[r][2], sc[r][3]);
        } else {
            *(float2*)&sm->scp[r][sp][lane*2] = make_float2(sc[r][0], sc[r][1]);
        }
    }
    __syncthreads();

    // combine partials + softmax: warp w < ROWS owns row w
    if (w < ROWS) {
        int i = i0 + w;
        float s[R];
        #pragma unroll
        for (int k = 0; k < R; k++) {
            float acc = 0.f;
            #pragma unroll
            for (int q = 0; q < 8; q++) acc += sm->scp[w][q][lane*R + k];
            s[k] = acc;
        }
        float mx = s[0];
        #pragma unroll
        for (int k = 1; k < R; k++) mx = fmaxf(mx, s[k]);
        #pragma unroll
        for (int o = 16; o; o >>= 1) mx = fmaxf(mx, __shfl_xor_sync(0xffffffffu, mx, o));
        float sum = 0.f;
        #pragma unroll
        for (int k = 0; k < R; k++) { s[k] = __expf(s[k] - mx); sum += s[k]; }
        #pragma unroll
        for (int o = 16; o; o >>= 1) sum += __shfl_xor_sync(0xffffffffu, sum, o);
        float inv = 1.f / sum;
        if constexpr (R == 4) {
            float4 p = make_float4(s[0]*inv, s[1]*inv, s[2]*inv, s[3]*inv);
            *(float4*)&sm->es[w][lane*4] = p;
            if (MODE == 2) *(float4*)&eout[(b*Nx + i)*Ny + lane*4] = p;
        } else {
            *(float2*)&sm->es[w][lane*2] = make_float2(s[0]*inv, s[1]*inv);
        }
    }
    __syncthreads();

    // aggregate: warp sp covers its yv segment for ALL rows (yv load reused)
    {
        const float* yvb = yv + (b*Ny + sp*SEG)*32;
        float agg[ROWS];
        #pragma unroll
        for (int r = 0; r < ROWS; r++) agg[r] = 0.f;
        #pragma unroll 4
        for (int m = 0; m < SEG; m++) {
            float vv = yvb[m*32 + lane];
            #pragma unroll
            for (int r = 0; r < ROWS; r++)
                agg[r] = fmaf(sm->es[r][sp*SEG + m], vv, agg[r]);
        }
        #pragma unroll
        for (int r = 0; r < ROWS; r++) sm->aggp[r][sp][lane] = agg[r];
    }
    __syncthreads();
    if (w < ROWS) {
        float xv = x[(b*Nx + i0 + w)*32 + lane];
        float acc = 0.f;
        #pragma unroll
        for (int q = 0; q < 8; q++) acc += sm->aggp[w][q][lane];
        sm->csT[lane][w] = xv;
        sm->csT[32 + lane][w] = acc;
    }
    __syncthreads();

    // node-MLP hidden: thread j covers all rows
    {
        float h[ROWS];
        float bb = bn1[tid];
        #pragma unroll
        for (int r = 0; r < ROWS; r++) h[r] = bb;
        #pragma unroll 8
        for (int i2 = 0; i2 < 64; i2++) {
            float wv = g_Wn1T[i2*256 + tid];
            #pragma unroll
            for (int r = 0; r < ROWS; r++) h[r] = fmaf(wv, sm->csT[i2][r], h[r]);
        }
        #pragma unroll
        for (int r = 0; r < ROWS; r++) sm->hs[r][tid] = fmaxf(h[r], 0.f);
    }
    __syncthreads();

    if (w < ROWS) {
        int ii = i0 + w;
        float res = sm->csT[lane][w] + mlp_out_row(sm->hs[w], lane, bn2);
        if (MODE == 0 || MODE == 2) xout[(b*Nx + ii)*32 + lane] = res;
        sm->rs[w][lane] = res;
    }
    __syncwarp();
    if constexpr (MODE == 0) {
        if (w < ROWS) {
            int ii = i0 + w;
            float r8[8];
            proj8(sm->rs[w], lane, g_CA, g_cbA, r8);
            float* dst = Atail + (b*Nx + ii)*256 + lane*8;
            *(float4*)dst       = make_float4(r8[0], r8[1], r8[2], r8[3]);
            *(float4*)(dst + 4) = make_float4(r8[4], r8[5], r8[6], r8[7]);
        }
    } else if constexpr (MODE == 1) {
        if (w < ROWS) {
            int ii = i0 + w;
            float r8[8];
            proj8(sm->rs[w], lane, g_CB, g_cbB, r8);
            *(float4*)&sm->hs[w][lane*8]     = make_float4(r8[0], r8[1], r8[2], r8[3]);
            *(float4*)&sm->hs[w][lane*8 + 4] = make_float4(r8[4], r8[5], r8[6], r8[7]);
            float v0 = bv[lane], v1 = 0.f;
            #pragma unroll 8
            for (int d = 0; d < 32; d += 2) {
                v0 = fmaf(sm->rs[w][d],   g_WvT[d*32 + lane],     v0);
                v1 = fmaf(sm->rs[w][d+1], g_WvT[(d+1)*32 + lane], v1);
            }
            yvtail[(b*Nx + ii)*32 + lane] = v0 + v1;
        }
        __syncthreads();
        static_assert(MODE != 1 || ROWS == 4, "MODE 1 expects ROWS==4");
        int t = tid;
        float* dst = Btail + b*256*128 + t*128 + i0;
        *(float4*)dst = make_float4(sm->hs[0][t], sm->hs[1][t], sm->hs[2][t], sm->hs[3][t]);
    }
}

// inter1 (256 blocks) + inter2 (1024 blocks). grid 1280, block 256.
__global__ void __launch_bounds__(256, 4) edge12_kernel(
        const float* __restrict__ f_in, const float* __restrict__ rp,
        const float* __restrict__ fpd,
        const float* __restrict__ bn1, const float* __restrict__ bn2,
        const float* __restrict__ We2, const float* __restrict__ bv) {
    __shared__ __align__(16) ESmem<2,4> sm;
    int blk = blockIdx.x;
    if (blk < 256) {
        int b = blk >> 3, i0 = (blk & 7)*4;
        edge_run<2,4,0>(&sm, g_R1, rp, g_A1, g_B1t, g_yv1, bn1, bn2, bv, We2,
                        g_R2, nullptr, 32, b, i0, g_A3, nullptr, nullptr);
    } else {
        blk -= 256;
        int b = blk >> 5, i0 = (blk & 31)*4;
        edge_run<2,4,1>(&sm, f_in, fpd, g_A2, g_B2t, g_yv2, bn1, bn2, bv, We2,
                        nullptr, nullptr, 128, b, i0, nullptr, g_B3t, g_yv3);
    }
}

// inter3: robot <- new_frontier. grid 512, block 256 (2 rows x 8 t-chunks).
__global__ void __launch_bounds__(256, 4) edge3_kernel(
        const float* __restrict__ rf,
        const float* __restrict__ bn1, const float* __restrict__ bn2,
        const float* __restrict__ We2, const float* __restrict__ bv,
        float* __restrict__ r_out, float* __restrict__ e_out) {
    __shared__ __align__(16) ESmem<4,2> sm;
    int b = blockIdx.x >> 4, i0 = (blockIdx.x & 15)*2;
    edge_run<4,2,2>(&sm, g_R2, rf, g_A3, g_B3t, g_yv3, bn1, bn2, bv, We2,
                    r_out, e_out, 32, b, i0, nullptr, nullptr, nullptr);
}

// ============================================================================
extern "C" void kernel_launch(void* const* d_in, const int* in_sizes, int n_in,
                              void* d_out, int out_size) {
    const float* robot    = (const float*)d_in[0];
    const float* frontier = (const float*)d_in[1];
    const float* rh       = (const float*)d_in[2];
    const float* fh       = (const float*)d_in[3];
    const float* rf       = (const float*)d_in[4];
    const float* rp       = (const float*)d_in[5];
    const float* fpd      = (const float*)d_in[6];
    const float* Wq  = (const float*)d_in[7];  const float* bq  = (const float*)d_in[8];
    const float* Wk  = (const float*)d_in[9];  const float* bk  = (const float*)d_in[10];
    const float* Wv  = (const float*)d_in[11]; const float* bv  = (const float*)d_in[12];
    const float* Wn1 = (const float*)d_in[13]; const float* bn1 = (const float*)d_in[14];
    const float* Wn2 = (const float*)d_in[15]; const float* bn2 = (const float*)d_in[16];
    const float* We1 = (const float*)d_in[17]; const float* be1 = (const float*)d_in[18];
    const float* We2 = (const float*)d_in[19];
    // d_in[20] = be2: softmax-invariant, unused.

    float* out    = (float*)d_out;
    float* r_out  = out;
    float* f_out  = r_out  + 32*32*32;
    float* rh_out = f_out  + 32*128*32;
    float* fh_out = rh_out + 32*64*32;
    float* e_out  = fh_out + 32*64*32;

    prep_kernel<<<57, 256>>>(Wq, bq, Wk, bk, Wv, Wn1, Wn2, We1, be1);
    qkv_kernel<<<32*36, 256>>>(robot, frontier, rh, fh, bq, bk, bv);
    intra_kernel<<<32*36, 256>>>(robot, frontier, rh, fh, bn1, bn2, bv,
                                 f_out, rh_out, fh_out);
    edge12_kernel<<<1280, 256>>>(f_out, rp, fpd, bn1, bn2, We2, bv);
    edge3_kernel<<<512, 256>>>(rf, bn1, bn2, We2, bv, r_out, e_out);
}

// round 10
// speedup vs baseline: 6.0418x; 1.3567x over previous
#include <cuda_runtime.h>
#include <math.h>

#define BV 32

// ---------------- weight scratch ----------------
__device__ __align__(16) float g_WqT[1024];
__device__ __align__(16) float g_WkT[1024];
__device__ __align__(16) float g_WvT[1024];
__device__ __align__(16) float g_Wn1T[64*256];    // [i][j]
__device__ __align__(16) float g_Wn2T[256*32];    // [j][d]
__device__ __align__(16) float g_CA[32*256];      // [d][j]
__device__ __align__(16) float g_CB[32*256];
__device__ __align__(16) float g_cbA[256];
__device__ __align__(16) float g_cbB[256];        // includes be1
__device__ __align__(16) float g_w65[256];

// ---------------- activation scratch ----------------
__device__ __align__(16) float g_q [9216*32];
__device__ __align__(16) float g_v [9216*32];
__device__ __align__(16) float g_kT[9216*32];     // per seg: [b][d][node]

__device__ __align__(16) float g_R1 [BV*32*32];
__device__ __align__(16) float g_R2 [BV*32*32];
__device__ __align__(16) float g_A1 [BV*32*256];
__device__ __align__(16) float g_A2 [BV*128*256];
__device__ __align__(16) float g_A3 [BV*32*256];
__device__ __align__(16) float g_B1t[BV*256*64];  // [b][t][node]
__device__ __align__(16) float g_B2t[BV*256*64];
__device__ __align__(16) float g_B3t[BV*256*128];
__device__ __align__(16) float g_yv1[BV*64*32];
__device__ __align__(16) float g_yv2[BV*64*32];
__device__ __align__(16) float g_yv3[BV*128*32];

// ============================================================================
// prep: weight transposes + edge-MLP folding + Wn2 transpose. grid 57.
// ============================================================================
__global__ void prep_kernel(const float* __restrict__ Wq, const float* __restrict__ bq,
                            const float* __restrict__ Wk, const float* __restrict__ bk,
                            const float* __restrict__ Wv, const float* __restrict__ Wn1,
                            const float* __restrict__ Wn2,
                            const float* __restrict__ We1, const float* __restrict__ be1) {
    int blk = blockIdx.x, t = threadIdx.x;
    if (blk < 32) {
        int d = blk, j = t;
        float a = 0.f, b2 = 0.f;
        #pragma unroll 8
        for (int i = 0; i < 32; i++) {
            a  += Wq[i*32 + d] * We1[j*65 + i];
            b2 += Wk[i*32 + d] * We1[j*65 + 32 + i];
        }
        g_CA[d*256 + j] = a;
        g_CB[d*256 + j] = b2;
    } else if (blk == 32) {
        for (int idx = t; idx < 1024; idx += 256) {
            int d = idx >> 5, dd = idx & 31;
            g_WqT[dd*32 + d] = Wq[idx];
            g_WkT[dd*32 + d] = Wk[idx];
            g_WvT[dd*32 + d] = Wv[idx];
        }
        float ca = 0.f, cb2 = 0.f;
        #pragma unroll 8
        for (int i = 0; i < 32; i++) {
            ca  += We1[t*65 + i]      * bq[i];
            cb2 += We1[t*65 + 32 + i] * bk[i];
        }
        g_cbA[t] = ca;
        g_cbB[t] = cb2 + be1[t];
        g_w65[t] = We1[t*65 + 64];
    } else if (blk < 49) {
        int base = (blk - 33) * 1024;
        for (int k = t; k < 1024; k += 256) {
            int idx = base + k;
            int j = idx >> 6, i = idx & 63;
            g_Wn1T[i*256 + j] = Wn1[idx];
        }
    } else {                              // Wn2T: 8 blocks x 1024
        int base = (blk - 49) * 1024;
        for (int k = t; k < 1024; k += 256) {
            int f = base + k;
            int j = f >> 5, d = f & 31;
            g_Wn2T[f] = Wn2[d*256 + j];
        }
    }
}

// ============================================================================
// qkv: warp per node, lane = d. grid 32*36, block 256 (8 nodes).
// ============================================================================
__global__ void __launch_bounds__(256) qkv_kernel(
        const float* __restrict__ robot, const float* __restrict__ frontier,
        const float* __restrict__ rh, const float* __restrict__ fh,
        const float* __restrict__ bq, const float* __restrict__ bk,
        const float* __restrict__ bv) {
    __shared__ float ks[32][9];
    int tid = threadIdx.x, w = tid >> 5, lane = tid & 31;
    int b = blockIdx.x / 36, c = blockIdx.x % 36;
    const float* x; int n, chunk, rowbase;
    if (c < 4)       { x = robot;    n = 32;  chunk = c;      rowbase = 0; }
    else if (c < 20) { x = frontier; n = 128; chunk = c - 4;  rowbase = 1024; }
    else if (c < 28) { x = rh;       n = 64;  chunk = c - 20; rowbase = 5120; }
    else             { x = fh;       n = 64;  chunk = c - 28; rowbase = 7168; }
    int node = chunk*8 + w;
    float xval = x[(b*n + node)*32 + lane];
    float q = bq[lane], k = bk[lane], v = bv[lane];
    #pragma unroll 8
    for (int dd = 0; dd < 32; dd++) {
        float xv = __shfl_sync(0xffffffffu, xval, dd);
        q = fmaf(xv, g_WqT[dd*32 + lane], q);
        k = fmaf(xv, g_WkT[dd*32 + lane], k);
        v = fmaf(xv, g_WvT[dd*32 + lane], v);
    }
    int grow = rowbase + b*n + node;
    g_q[grow*32 + lane] = q;
    g_v[grow*32 + lane] = v;
    ks[lane][w] = k;
    __syncthreads();
    int d = tid >> 3, nd = tid & 7;
    g_kT[rowbase*32 + b*32*n + d*n + chunk*8 + nd] = ks[d][nd];
}

// ============================================================================
// node MLP hidden (intra, 8 rows)
// ============================================================================
__device__ __forceinline__ void mlp8_hidden(const float (*csT)[8], float (*hs)[256],
        const float* __restrict__ bn1, int tid) {
    float h[8];
    float b = bn1[tid];
    #pragma unroll
    for (int r = 0; r < 8; r++) h[r] = b;
    #pragma unroll 8
    for (int i = 0; i < 64; i++) {
        float wv = g_Wn1T[i*256 + tid];
        float4 c0 = *(const float4*)&csT[i][0];
        float4 c1 = *(const float4*)&csT[i][4];
        h[0] = fmaf(wv, c0.x, h[0]); h[1] = fmaf(wv, c0.y, h[1]);
        h[2] = fmaf(wv, c0.z, h[2]); h[3] = fmaf(wv, c0.w, h[3]);
        h[4] = fmaf(wv, c1.x, h[4]); h[5] = fmaf(wv, c1.y, h[5]);
        h[6] = fmaf(wv, c1.z, h[6]); h[7] = fmaf(wv, c1.w, h[7]);
    }
    #pragma unroll
    for (int r = 0; r < 8; r++) hs[r][tid] = fmaxf(h[r], 0.f);
}

// ============================================================================
// Intra: attention + coop MLP (j-split out layer) + j-parallel proj tails.
// Warp per row, 8 rows/block. MODE: 0=robot(A1) 1=frontier(A2) 2=rh(B1t,yv1) 3=fh(B2t,yv2)
// ============================================================================
template<int NMI, int MODE>
__device__ __forceinline__ void intra_body(
        const float* __restrict__ x, float* __restrict__ out,
        const float* __restrict__ bn1, const float* __restrict__ bn2,
        const float* __restrict__ bv,
        int b, int chunk, int rowbase,
        float (*qs)[32], float (*es)[128], float (*csT)[8], float (*hs)[256],
        float (*psum)[8][32],
        float* __restrict__ Aout, float* __restrict__ Bout, float* __restrict__ yvout) {
    constexpr int n = NMI*32;
    int tid = threadIdx.x, w = tid >> 5, lane = tid & 31;
    int row = chunk*8 + w;
    int grow = rowbase + b*n + row;
    qs[w][lane] = g_q[grow*32 + lane];
    __syncwarp();

    const float* kTg = g_kT + rowbase*32 + b*32*n;
    float s[NMI];
    #pragma unroll
    for (int k = 0; k < NMI; k++) s[k] = 0.f;
    #pragma unroll 8
    for (int d = 0; d < 32; d++) {
        float qd = qs[w][d];
        if constexpr (NMI == 4) {
            float4 kv = *(const float4*)&kTg[d*n + lane*4];
            s[0] = fmaf(qd, kv.x, s[0]); s[1] = fmaf(qd, kv.y, s[1]);
            s[2] = fmaf(qd, kv.z, s[2]); s[3] = fmaf(qd, kv.w, s[3]);
        } else if constexpr (NMI == 2) {
            float2 kv = *(const float2*)&kTg[d*n + lane*2];
            s[0] = fmaf(qd, kv.x, s[0]); s[1] = fmaf(qd, kv.y, s[1]);
        } else {
            s[0] = fmaf(qd, kTg[d*n + lane], s[0]);
        }
    }
    float mx = s[0];
    #pragma unroll
    for (int k = 1; k < NMI; k++) mx = fmaxf(mx, s[k]);
    #pragma unroll
    for (int o = 16; o; o >>= 1) mx = fmaxf(mx, __shfl_xor_sync(0xffffffffu, mx, o));
    float sum = 0.f;
    #pragma unroll
    for (int k = 0; k < NMI; k++) { s[k] = __expf(s[k] - mx); sum += s[k]; }
    #pragma unroll
    for (int o = 16; o; o >>= 1) sum += __shfl_xor_sync(0xffffffffu, sum, o);
    float inv = 1.f / sum;
    if constexpr (NMI == 4) {
        *(float4*)&es[w][lane*4] = make_float4(s[0]*inv, s[1]*inv, s[2]*inv, s[3]*inv);
    } else if constexpr (NMI == 2) {
        *(float2*)&es[w][lane*2] = make_float2(s[0]*inv, s[1]*inv);
    } else {
        es[w][lane] = s[0]*inv;
    }
    __syncwarp();
    const float* vg = g_v + (rowbase + b*n)*32;
    float a0 = 0.f, a1 = 0.f, a2 = 0.f, a3 = 0.f;
    #pragma unroll 4
    for (int m = 0; m < n; m += 4) {
        a0 = fmaf(es[w][m],   vg[(m)*32 + lane],   a0);
        a1 = fmaf(es[w][m+1], vg[(m+1)*32 + lane], a1);
        a2 = fmaf(es[w][m+2], vg[(m+2)*32 + lane], a2);
        a3 = fmaf(es[w][m+3], vg[(m+3)*32 + lane], a3);
    }
    float agg = (a0 + a1) + (a2 + a3);
    float xv = x[(b*n + row)*32 + lane];
    csT[lane][w] = xv;
    csT[32 + lane][w] = agg;
    __syncthreads();
    mlp8_hidden(csT, hs, bn1, tid);
    __syncthreads();

    // ---- out layer, j-split: warp w covers j in [32w, 32w+32) for ALL rows ----
    {
        float po[8];
        #pragma unroll
        for (int r = 0; r < 8; r++) po[r] = 0.f;
        #pragma unroll 2
        for (int jj = 0; jj < 32; jj += 4) {
            int j = w*32 + jj;
            float wv0 = g_Wn2T[(j+0)*32 + lane];
            float wv1 = g_Wn2T[(j+1)*32 + lane];
            float wv2 = g_Wn2T[(j+2)*32 + lane];
            float wv3 = g_Wn2T[(j+3)*32 + lane];
            #pragma unroll
            for (int r = 0; r < 8; r++) {
                float4 hv = *(const float4*)&hs[r][j];
                po[r] = fmaf(hv.x, wv0, fmaf(hv.y, wv1, fmaf(hv.z, wv2, fmaf(hv.w, wv3, po[r]))));
            }
        }
        #pragma unroll
        for (int r = 0; r < 8; r++) psum[r][w][lane] = po[r];
    }
    __syncthreads();
    {
        float acc = bn2[lane];
        #pragma unroll
        for (int q = 0; q < 8; q++) acc += psum[w][q][lane];
        float res = csT[lane][w] + acc;
        out[(b*n + row)*32 + lane] = res;
        qs[w][lane] = res;              // rs buffer for projection
    }
    __syncthreads();

    // ---- projection, j-parallel: thread tid = j for ALL 8 rows ----
    {
        const float* C  = (MODE <= 1) ? g_CA  : g_CB;
        const float* cb = (MODE <= 1) ? g_cbA : g_cbB;
        float pa[8];
        float c0 = cb[tid];
        #pragma unroll
        for (int r = 0; r < 8; r++) pa[r] = c0;
        #pragma unroll 2
        for (int dd = 0; dd < 32; dd += 4) {
            float wv0 = C[(dd+0)*256 + tid];
            float wv1 = C[(dd+1)*256 + tid];
            float wv2 = C[(dd+2)*256 + tid];
            float wv3 = C[(dd+3)*256 + tid];
            #pragma unroll
            for (int r = 0; r < 8; r++) {
                float4 rv = *(const float4*)&qs[r][dd];
                pa[r] = fmaf(rv.x, wv0, fmaf(rv.y, wv1, fmaf(rv.z, wv2, fmaf(rv.w, wv3, pa[r]))));
            }
        }
        if constexpr (MODE <= 1) {
            #pragma unroll
            for (int r = 0; r < 8; r++)
                Aout[(b*n + chunk*8 + r)*256 + tid] = pa[r];
        } else {
            float* dst = Bout + b*256*n + tid*n + chunk*8;
            *(float4*)dst       = make_float4(pa[0], pa[1], pa[2], pa[3]);
            *(float4*)(dst + 4) = make_float4(pa[4], pa[5], pa[6], pa[7]);
            // yv tail: warp per row
            float v0 = bv[lane], v1 = 0.f;
            #pragma unroll 8
            for (int d = 0; d < 32; d += 2) {
                v0 = fmaf(qs[w][d],   g_WvT[d*32 + lane],     v0);
                v1 = fmaf(qs[w][d+1], g_WvT[(d+1)*32 + lane], v1);
            }
            yvout[(b*n + row)*32 + lane] = v0 + v1;
        }
    }
}

__global__ void __launch_bounds__(256) intra_kernel(
        const float* __restrict__ robot, const float* __restrict__ frontier,
        const float* __restrict__ rh, const float* __restrict__ fh,
        const float* __restrict__ bn1, const float* __restrict__ bn2,
        const float* __restrict__ bv,
        float* __restrict__ f_out, float* __restrict__ rh_out, float* __restrict__ fh_out) {
    __shared__ __align__(16) float qs[8][32];
    __shared__ __align__(16) float es[8][128];
    __shared__ __align__(16) float csT[64][8];
    __shared__ __align__(16) float hs[8][256];
    __shared__ __align__(16) float psum[8][8][32];
    int b = blockIdx.x / 36, c = blockIdx.x % 36;
    if (c < 4)
        intra_body<1,0>(robot, g_R1, bn1, bn2, bv, b, c, 0,
                        qs, es, csT, hs, psum, g_A1, nullptr, nullptr);
    else if (c < 20)
        intra_body<4,1>(frontier, f_out, bn1, bn2, bv, b, c-4, 1024,
                        qs, es, csT, hs, psum, g_A2, nullptr, nullptr);
    else if (c < 28)
        intra_body<2,2>(rh, rh_out, bn1, bn2, bv, b, c-20, 5120,
                        qs, es, csT, hs, psum, nullptr, g_B1t, g_yv1);
    else
        intra_body<2,3>(fh, fh_out, bn1, bn2, bv, b, c-28, 7168,
                        qs, es, csT, hs, psum, nullptr, g_B2t, g_yv2);
}

// ============================================================================
// Edge kernel: warp = t-chunk, each warp processes ALL ROWS rows (B/yv loads
// amortized in registers); j-split out layer; j-parallel projections.
// MODE: 0=inter1(xout, Atail) 1=inter2(Btail/yvtail) 2=inter3(xout + eout)
// ============================================================================
template<int R, int ROWS>
struct __align__(16) ESmem {
    float As[ROWS][256];
    float scp[ROWS][8][32*R];   // reused as psum[ROWS][8][32] after softmax
    float es[ROWS][32*R];
    float aggp[ROWS][8][32];
    float csT[64][ROWS];
    float hs[ROWS][256];
    float rs[ROWS][32];
    float w65s[256];
    float we2s[256];
};

template<int R, int ROWS, int MODE>
__device__ __forceinline__ void edge_run(
        ESmem<R,ROWS>* sm,
        const float* __restrict__ x, const float* __restrict__ dis,
        const float* __restrict__ A, const float* __restrict__ Bt,
        const float* __restrict__ yv,
        const float* __restrict__ bn1, const float* __restrict__ bn2,
        const float* __restrict__ bv, const float* __restrict__ We2,
        float* __restrict__ xout, float* __restrict__ eout,
        int Nx, int b, int i0,
        float* __restrict__ Atail, float* __restrict__ Btail,
        float* __restrict__ yvtail) {
    constexpr int Ny  = 32*R;
    constexpr int TCH = 32;
    constexpr int SEG = Ny/8;
    int tid = threadIdx.x, w = tid >> 5, lane = tid & 31;
    int sp = w;

    sm->w65s[tid] = g_w65[tid];
    sm->we2s[tid] = We2[tid];
    #pragma unroll
    for (int r = 0; r < ROWS; r++) {
        const float* Ar = A + (b*Nx + i0 + r)*256;
        sm->As[r][w*32 + lane] = Ar[w*32 + lane];
    }
    __syncthreads();

    float dv[ROWS][R];
    #pragma unroll
    for (int r = 0; r < ROWS; r++) {
        const float* dr = dis + (b*Nx + i0 + r)*Ny;
        if constexpr (R == 4) {
            float4 t4 = *(const float4*)&dr[lane*4];
            dv[r][0]=t4.x; dv[r][1]=t4.y; dv[r][2]=t4.z; dv[r][3]=t4.w;
        } else {
            float2 t2 = *(const float2*)&dr[lane*2];
            dv[r][0]=t2.x; dv[r][1]=t2.y;
        }
    }
    float sc[ROWS][R];
    #pragma unroll
    for (int r = 0; r < ROWS; r++)
        #pragma unroll
        for (int k = 0; k < R; k++) sc[r][k] = 0.f;

    const float* Bb = Bt + (b*256 + sp*TCH)*Ny;
    #pragma unroll 2
    for (int tt = 0; tt < TCH; tt += 4) {
        int t = sp*TCH + tt;
        float4 w6 = *(const float4*)&sm->w65s[t];
        float4 w2 = *(const float4*)&sm->we2s[t];
        float w6v[4] = {w6.x, w6.y, w6.z, w6.w};
        float w2v[4] = {w2.x, w2.y, w2.z, w2.w};
        float av[ROWS][4];
        #pragma unroll
        for (int r = 0; r < ROWS; r++) {
            float4 a4 = *(const float4*)&sm->As[r][t];
            av[r][0]=a4.x; av[r][1]=a4.y; av[r][2]=a4.z; av[r][3]=a4.w;
        }
        #pragma unroll
        for (int u = 0; u < 4; u++) {
            if constexpr (R == 4) {
                float4 Bv = *(const float4*)&Bb[(tt+u)*Ny + lane*4];
                #pragma unroll
                for (int r = 0; r < ROWS; r++) {
                    float base = av[r][u];
                    float hh;
                    hh = fmaf(w6v[u], dv[r][0], base + Bv.x); sc[r][0] = fmaf(w2v[u], fmaxf(hh, 0.f), sc[r][0]);
                    hh = fmaf(w6v[u], dv[r][1], base + Bv.y); sc[r][1] = fmaf(w2v[u], fmaxf(hh, 0.f), sc[r][1]);
                    hh = fmaf(w6v[u], dv[r][2], base + Bv.z); sc[r][2] = fmaf(w2v[u], fmaxf(hh, 0.f), sc[r][2]);
                    hh = fmaf(w6v[u], dv[r][3], base + Bv.w); sc[r][3] = fmaf(w2v[u], fmaxf(hh, 0.f), sc[r][3]);
                }
            } else {
                float2 Bv = *(const float2*)&Bb[(tt+u)*Ny + lane*2];
                #pragma unroll
                for (int r = 0; r < ROWS; r++) {
                    float base = av[r][u];
                    float hh;
                    hh = fmaf(w6v[u], dv[r][0], base + Bv.x); sc[r][0] = fmaf(w2v[u], fmaxf(hh, 0.f), sc[r][0]);
                    hh = fmaf(w6v[u], dv[r][1], base + Bv.y); sc[r][1] = fmaf(w2v[u], fmaxf(hh, 0.f), sc[r][1]);
                }
            }
        }
    }
    #pragma unroll
    for (int r = 0; r < ROWS; r++) {
        if constexpr (R == 4) {
            *(float4*)&sm->scp[r][sp][lane*4] = make_float4(sc[r][0], sc[r][1], sc[r][2], sc[r][3]);
        } else {
            *(float2*)&sm->scp[r][sp][lane*2] = make_float2(sc[r][0], sc[r][1]);
        }
    }
    __syncthreads();

    if (w < ROWS) {
        int i = i0 + w;
        float s[R];
        #pragma unroll
        for (int k = 0; k < R; k++) {
            float acc = 0.f;
            #pragma unroll
            for (int q = 0; q < 8; q++) acc += sm->scp[w][q][lane*R + k];
            s[k] = acc;
        }
        float mx = s[0];
        #pragma unroll
        for (int k = 1; k < R; k++) mx = fmaxf(mx, s[k]);
        #pragma unroll
        for (int o = 16; o; o >>= 1) mx = fmaxf(mx, __shfl_xor_sync(0xffffffffu, mx, o));
        float sum = 0.f;
        #pragma unroll
        for (int k = 0; k < R; k++) { s[k] = __expf(s[k] - mx); sum += s[k]; }
        #pragma unroll
        for (int o = 16; o; o >>= 1) sum += __shfl_xor_sync(0xffffffffu, sum, o);
        float inv = 1.f / sum;
        if constexpr (R == 4) {
            float4 p = make_float4(s[0]*inv, s[1]*inv, s[2]*inv, s[3]*inv);
            *(float4*)&sm->es[w][lane*4] = p;
            if (MODE == 2) *(float4*)&eout[(b*Nx + i)*Ny + lane*4] = p;
        } else {
            *(float2*)&sm->es[w][lane*2] = make_float2(s[0]*inv, s[1]*inv);
        }
    }
    __syncthreads();

    {
        const float* yvb = yv + (b*Ny + sp*SEG)*32;
        float agg[ROWS];
        #pragma unroll
        for (int r = 0; r < ROWS; r++) agg[r] = 0.f;
        #pragma unroll 4
        for (int m = 0; m < SEG; m++) {
            float vv = yvb[m*32 + lane];
            #pragma unroll
            for (int r = 0; r < ROWS; r++)
                agg[r] = fmaf(sm->es[r][sp*SEG + m], vv, agg[r]);
        }
        #pragma unroll
        for (int r = 0; r < ROWS; r++) sm->aggp[r][sp][lane] = agg[r];
    }
    __syncthreads();
    if (w < ROWS) {
        float xv = x[(b*Nx + i0 + w)*32 + lane];
        float acc = 0.f;
        #pragma unroll
        for (int q = 0; q < 8; q++) acc += sm->aggp[w][q][lane];
        sm->csT[lane][w] = xv;
        sm->csT[32 + lane][w] = acc;
    }
    __syncthreads();

    // hidden layer: thread j covers all rows
    {
        float h[ROWS];
        float bb = bn1[tid];
        #pragma unroll
        for (int r = 0; r < ROWS; r++) h[r] = bb;
        #pragma unroll 8
        for (int i2 = 0; i2 < 64; i2++) {
            float wv = g_Wn1T[i2*256 + tid];
            #pragma unroll
            for (int r = 0; r < ROWS; r++) h[r] = fmaf(wv, sm->csT[i2][r], h[r]);
        }
        #pragma unroll
        for (int r = 0; r < ROWS; r++) sm->hs[r][tid] = fmaxf(h[r], 0.f);
    }
    __syncthreads();

    // out layer, j-split (psum overlays scp)
    float* psum = &sm->scp[0][0][0];     // [ROWS][8][32] indexing below
    {
        float po[ROWS];
        #pragma unroll
        for (int r = 0; r < ROWS; r++) po[r] = 0.f;
        #pragma unroll 2
        for (int jj = 0; jj < 32; jj += 4) {
            int j = w*32 + jj;
            float wv0 = g_Wn2T[(j+0)*32 + lane];
            float wv1 = g_Wn2T[(j+1)*32 + lane];
            float wv2 = g_Wn2T[(j+2)*32 + lane];
            float wv3 = g_Wn2T[(j+3)*32 + lane];
            #pragma unroll
            for (int r = 0; r < ROWS; r++) {
                float4 hv = *(const float4*)&sm->hs[r][j];
                po[r] = fmaf(hv.x, wv0, fmaf(hv.y, wv1, fmaf(hv.z, wv2, fmaf(hv.w, wv3, po[r]))));
            }
        }
        #pragma unroll
        for (int r = 0; r < ROWS; r++) psum[(r*8 + w)*32 + lane] = po[r];
    }
    __syncthreads();
    if (w < ROWS) {
        int ii = i0 + w;
        float acc = bn2[lane];
        #pragma unroll
        for (int q = 0; q < 8; q++) acc += psum[(w*8 + q)*32 + lane];
        float res = sm->csT[lane][w] + acc;
        if (MODE == 0 || MODE == 2) xout[(b*Nx + ii)*32 + lane] = res;
        sm->rs[w][lane] = res;
    }
    __syncthreads();

    // projection tails, j-parallel
    if constexpr (MODE == 0 || MODE == 1) {
        const float* C  = (MODE == 0) ? g_CA  : g_CB;
        const float* cb = (MODE == 0) ? g_cbA : g_cbB;
        float pa[ROWS];
        float c0 = cb[tid];
        #pragma unroll
        for (int r = 0; r < ROWS; r++) pa[r] = c0;
        #pragma unroll 2
        for (int dd = 0; dd < 32; dd += 4) {
            float wv0 = C[(dd+0)*256 + tid];
            float wv1 = C[(dd+1)*256 + tid];
            float wv2 = C[(dd+2)*256 + tid];
            float wv3 = C[(dd+3)*256 + tid];
            #pragma unroll
            for (int r = 0; r < ROWS; r++) {
                float4 rv = *(const float4*)&sm->rs[r][dd];
                pa[r] = fmaf(rv.x, wv0, fmaf(rv.y, wv1, fmaf(rv.z, wv2, fmaf(rv.w, wv3, pa[r]))));
            }
        }
        if constexpr (MODE == 0) {
            #pragma unroll
            for (int r = 0; r < ROWS; r++)
                Atail[(b*Nx + i0 + r)*256 + tid] = pa[r];
        } else {
            static_assert(ROWS == 4, "MODE 1 expects ROWS==4");
            float* dst = Btail + b*256*128 + tid*128 + i0;
            *(float4*)dst = make_float4(pa[0], pa[1], pa[2], pa[3]);
            if (w < ROWS) {
                int ii = i0 + w;
                float v0 = bv[lane], v1 = 0.f;
                #pragma unroll 8
                for (int d = 0; d < 32; d += 2) {
                    v0 = fmaf(sm->rs[w][d],   g_WvT[d*32 + lane],     v0);
                    v1 = fmaf(sm->rs[w][d+1], g_WvT[(d+1)*32 + lane], v1);
                }
                yvtail[(b*Nx + ii)*32 + lane] = v0 + v1;
            }
        }
    }
}

// inter1 (256 blocks) + inter2 (1024 blocks). grid 1280, block 256.
__global__ void __launch_bounds__(256, 4) edge12_kernel(
        const float* __restrict__ f_in, const float* __restrict__ rp,
        const float* __restrict__ fpd,
        const float* __restrict__ bn1, const float* __restrict__ bn2,
        const float* __restrict__ We2, const float* __restrict__ bv) {
    __shared__ __align__(16) ESmem<2,4> sm;
    int blk = blockIdx.x;
    if (blk < 256) {
        int b = blk >> 3, i0 = (blk & 7)*4;
        edge_run<2,4,0>(&sm, g_R1, rp, g_A1, g_B1t, g_yv1, bn1, bn2, bv, We2,
                        g_R2, nullptr, 32, b, i0, g_A3, nullptr, nullptr);
    } else {
        blk -= 256;
        int b = blk >> 5, i0 = (blk & 31)*4;
        edge_run<2,4,1>(&sm, f_in, fpd, g_A2, g_B2t, g_yv2, bn1, bn2, bv, We2,
                        nullptr, nullptr, 128, b, i0, nullptr, g_B3t, g_yv3);
    }
}

// inter3: robot <- new_frontier. grid 512, block 256 (2 rows x 8 t-chunks).
__global__ void __launch_bounds__(256, 4) edge3_kernel(
        const float* __restrict__ rf,
        const float* __restrict__ bn1, const float* __restrict__ bn2,
        const float* __restrict__ We2, const float* __restrict__ bv,
        float* __restrict__ r_out, float* __restrict__ e_out) {
    __shared__ __align__(16) ESmem<4,2> sm;
    int b = blockIdx.x >> 4, i0 = (blockIdx.x & 15)*2;
    edge_run<4,2,2>(&sm, g_R2, rf, g_A3, g_B3t, g_yv3, bn1, bn2, bv, We2,
                    r_out, e_out, 32, b, i0, nullptr, nullptr, nullptr);
}

// ============================================================================
extern "C" void kernel_launch(void* const* d_in, const int* in_sizes, int n_in,
                              void* d_out, int out_size) {
    const float* robot    = (const float*)d_in[0];
    const float* frontier = (const float*)d_in[1];
    const float* rh       = (const float*)d_in[2];
    const float* fh       = (const float*)d_in[3];
    const float* rf       = (const float*)d_in[4];
    const float* rp       = (const float*)d_in[5];
    const float* fpd      = (const float*)d_in[6];
    const float* Wq  = (const float*)d_in[7];  const float* bq  = (const float*)d_in[8];
    const float* Wk  = (const float*)d_in[9];  const float* bk  = (const float*)d_in[10];
    const float* Wv  = (const float*)d_in[11]; const float* bv  = (const float*)d_in[12];
    const float* Wn1 = (const float*)d_in[13]; const float* bn1 = (const float*)d_in[14];
    const float* Wn2 = (const float*)d_in[15]; const float* bn2 = (const float*)d_in[16];
    const float* We1 = (const float*)d_in[17]; const float* be1 = (const float*)d_in[18];
    const float* We2 = (const float*)d_in[19];
    // d_in[20] = be2: softmax-invariant, unused.

    float* out    = (float*)d_out;
    float* r_out  = out;
    float* f_out  = r_out  + 32*32*32;
    float* rh_out = f_out  + 32*128*32;
    float* fh_out = rh_out + 32*64*32;
    float* e_out  = fh_out + 32*64*32;

    prep_kernel<<<57, 256>>>(Wq, bq, Wk, bk, Wv, Wn1, Wn2, We1, be1);
    qkv_kernel<<<32*36, 256>>>(robot, frontier, rh, fh, bq, bk, bv);
    intra_kernel<<<32*36, 256>>>(robot, frontier, rh, fh, bn1, bn2, bv,
                                 f_out, rh_out, fh_out);
    edge12_kernel<<<1280, 256>>>(f_out, rp, fpd, bn1, bn2, We2, bv);
    edge3_kernel<<<512, 256>>>(rf, bn1, bn2, We2, bv, r_out, e_out);
}

// round 11
// speedup vs baseline: 6.2068x; 1.0273x over previous
#include <cuda_runtime.h>
#include <math.h>

#define BV 32

// ---------------- weight scratch ----------------
__device__ __align__(16) float g_WqT[1024];
__device__ __align__(16) float g_WkT[1024];
__device__ __align__(16) float g_WvT[1024];
__device__ __align__(16) float g_Wn1T[64*256];    // [i][j]
__device__ __align__(16) float g_Wn2T[256*32];    // [j][d]
__device__ __align__(16) float g_CA[32*256];      // [d][j]
__device__ __align__(16) float g_CB[32*256];
__device__ __align__(16) float g_cbA[256];
__device__ __align__(16) float g_cbB[256];        // includes be1
__device__ __align__(16) float g_w65[256];

// ---------------- activation scratch ----------------
__device__ __align__(16) float g_q [9216*32];
__device__ __align__(16) float g_v [9216*32];
__device__ __align__(16) float g_kT[9216*32];     // per seg: [b][d][node]

__device__ __align__(16) float g_R1 [BV*32*32];
__device__ __align__(16) float g_R2 [BV*32*32];
__device__ __align__(16) float g_A1 [BV*32*256];
__device__ __align__(16) float g_A2 [BV*128*256];
__device__ __align__(16) float g_A3 [BV*32*256];
__device__ __align__(16) float g_B1t[BV*256*64];  // [b][t][node]
__device__ __align__(16) float g_B2t[BV*256*64];
__device__ __align__(16) float g_B3t[BV*256*128];
__device__ __align__(16) float g_yv1[BV*64*32];
__device__ __align__(16) float g_yv2[BV*64*32];
__device__ __align__(16) float g_yv3[BV*128*32];

// ============================================================================
// prep: weight transposes + edge-MLP folding + Wn2 transpose. grid 57.
// ============================================================================
__global__ void prep_kernel(const float* __restrict__ Wq, const float* __restrict__ bq,
                            const float* __restrict__ Wk, const float* __restrict__ bk,
                            const float* __restrict__ Wv, const float* __restrict__ Wn1,
                            const float* __restrict__ Wn2,
                            const float* __restrict__ We1, const float* __restrict__ be1) {
    int blk = blockIdx.x, t = threadIdx.x;
    if (blk < 32) {
        int d = blk, j = t;
        float a = 0.f, b2 = 0.f;
        #pragma unroll 8
        for (int i = 0; i < 32; i++) {
            a  += Wq[i*32 + d] * We1[j*65 + i];
            b2 += Wk[i*32 + d] * We1[j*65 + 32 + i];
        }
        g_CA[d*256 + j] = a;
        g_CB[d*256 + j] = b2;
    } else if (blk == 32) {
        for (int idx = t; idx < 1024; idx += 256) {
            int d = idx >> 5, dd = idx & 31;
            g_WqT[dd*32 + d] = Wq[idx];
            g_WkT[dd*32 + d] = Wk[idx];
            g_WvT[dd*32 + d] = Wv[idx];
        }
        float ca = 0.f, cb2 = 0.f;
        #pragma unroll 8
        for (int i = 0; i < 32; i++) {
            ca  += We1[t*65 + i]      * bq[i];
            cb2 += We1[t*65 + 32 + i] * bk[i];
        }
        g_cbA[t] = ca;
        g_cbB[t] = cb2 + be1[t];
        g_w65[t] = We1[t*65 + 64];
    } else if (blk < 49) {
        int base = (blk - 33) * 1024;
        for (int k = t; k < 1024; k += 256) {
            int idx = base + k;
            int j = idx >> 6, i = idx & 63;
            g_Wn1T[i*256 + j] = Wn1[idx];
        }
    } else {                              // Wn2T: 8 blocks x 1024
        int base = (blk - 49) * 1024;
        for (int k = t; k < 1024; k += 256) {
            int f = base + k;
            int j = f >> 5, d = f & 31;
            g_Wn2T[f] = Wn2[d*256 + j];
        }
    }
}

// ============================================================================
// qkv: warp per node, lane = d. grid 32*36, block 256 (8 nodes).
// ============================================================================
__global__ void __launch_bounds__(256) qkv_kernel(
        const float* __restrict__ robot, const float* __restrict__ frontier,
        const float* __restrict__ rh, const float* __restrict__ fh,
        const float* __restrict__ bq, const float* __restrict__ bk,
        const float* __restrict__ bv) {
    __shared__ float ks[32][9];
    int tid = threadIdx.x, w = tid >> 5, lane = tid & 31;
    int b = blockIdx.x / 36, c = blockIdx.x % 36;
    const float* x; int n, chunk, rowbase;
    if (c < 4)       { x = robot;    n = 32;  chunk = c;      rowbase = 0; }
    else if (c < 20) { x = frontier; n = 128; chunk = c - 4;  rowbase = 1024; }
    else if (c < 28) { x = rh;       n = 64;  chunk = c - 20; rowbase = 5120; }
    else             { x = fh;       n = 64;  chunk = c - 28; rowbase = 7168; }
    int node = chunk*8 + w;
    float xval = x[(b*n + node)*32 + lane];
    float q = bq[lane], k = bk[lane], v = bv[lane];
    #pragma unroll 8
    for (int dd = 0; dd < 32; dd++) {
        float xv = __shfl_sync(0xffffffffu, xval, dd);
        q = fmaf(xv, g_WqT[dd*32 + lane], q);
        k = fmaf(xv, g_WkT[dd*32 + lane], k);
        v = fmaf(xv, g_WvT[dd*32 + lane], v);
    }
    int grow = rowbase + b*n + node;
    g_q[grow*32 + lane] = q;
    g_v[grow*32 + lane] = v;
    ks[lane][w] = k;
    __syncthreads();
    int d = tid >> 3, nd = tid & 7;
    g_kT[rowbase*32 + b*32*n + d*n + chunk*8 + nd] = ks[d][nd];
}

// ============================================================================
// node MLP hidden (intra, 8 rows)
// ============================================================================
__device__ __forceinline__ void mlp8_hidden(const float (*csT)[8], float (*hs)[256],
        const float* __restrict__ bn1, int tid) {
    float h[8];
    float b = bn1[tid];
    #pragma unroll
    for (int r = 0; r < 8; r++) h[r] = b;
    #pragma unroll 8
    for (int i = 0; i < 64; i++) {
        float wv = g_Wn1T[i*256 + tid];
        float4 c0 = *(const float4*)&csT[i][0];
        float4 c1 = *(const float4*)&csT[i][4];
        h[0] = fmaf(wv, c0.x, h[0]); h[1] = fmaf(wv, c0.y, h[1]);
        h[2] = fmaf(wv, c0.z, h[2]); h[3] = fmaf(wv, c0.w, h[3]);
        h[4] = fmaf(wv, c1.x, h[4]); h[5] = fmaf(wv, c1.y, h[5]);
        h[6] = fmaf(wv, c1.z, h[6]); h[7] = fmaf(wv, c1.w, h[7]);
    }
    #pragma unroll
    for (int r = 0; r < 8; r++) hs[r][tid] = fmaxf(h[r], 0.f);
}

// ============================================================================
// Intra: attention + coop MLP (j-split out layer) + j-parallel proj tails.
// Warp per row, 8 rows/block. Aggregate phase: warp = m-chunk covering ALL
// 8 rows (v loads amortized 8x). MODE: 0=robot(A1) 1=frontier(A2)
// 2=rh(B1t,yv1) 3=fh(B2t,yv2)
// ============================================================================
template<int NMI, int MODE>
__device__ __forceinline__ void intra_body(
        const float* __restrict__ x, float* __restrict__ out,
        const float* __restrict__ bn1, const float* __restrict__ bn2,
        const float* __restrict__ bv,
        int b, int chunk, int rowbase,
        float (*qs)[32], float (*es)[128], float (*csT)[8], float (*hs)[256],
        float (*psum)[8][32],
        float* __restrict__ Aout, float* __restrict__ Bout, float* __restrict__ yvout) {
    constexpr int n = NMI*32;
    int tid = threadIdx.x, w = tid >> 5, lane = tid & 31;
    int row = chunk*8 + w;
    int grow = rowbase + b*n + row;
    qs[w][lane] = g_q[grow*32 + lane];
    __syncwarp();

    const float* kTg = g_kT + rowbase*32 + b*32*n;
    float s[NMI];
    #pragma unroll
    for (int k = 0; k < NMI; k++) s[k] = 0.f;
    #pragma unroll 8
    for (int d = 0; d < 32; d++) {
        float qd = qs[w][d];
        if constexpr (NMI == 4) {
            float4 kv = *(const float4*)&kTg[d*n + lane*4];
            s[0] = fmaf(qd, kv.x, s[0]); s[1] = fmaf(qd, kv.y, s[1]);
            s[2] = fmaf(qd, kv.z, s[2]); s[3] = fmaf(qd, kv.w, s[3]);
        } else if constexpr (NMI == 2) {
            float2 kv = *(const float2*)&kTg[d*n + lane*2];
            s[0] = fmaf(qd, kv.x, s[0]); s[1] = fmaf(qd, kv.y, s[1]);
        } else {
            s[0] = fmaf(qd, kTg[d*n + lane], s[0]);
        }
    }
    float mx = s[0];
    #pragma unroll
    for (int k = 1; k < NMI; k++) mx = fmaxf(mx, s[k]);
    #pragma unroll
    for (int o = 16; o; o >>= 1) mx = fmaxf(mx, __shfl_xor_sync(0xffffffffu, mx, o));
    float sum = 0.f;
    #pragma unroll
    for (int k = 0; k < NMI; k++) { s[k] = __expf(s[k] - mx); sum += s[k]; }
    #pragma unroll
    for (int o = 16; o; o >>= 1) sum += __shfl_xor_sync(0xffffffffu, sum, o);
    float inv = 1.f / sum;
    if constexpr (NMI == 4) {
        *(float4*)&es[w][lane*4] = make_float4(s[0]*inv, s[1]*inv, s[2]*inv, s[3]*inv);
    } else if constexpr (NMI == 2) {
        *(float2*)&es[w][lane*2] = make_float2(s[0]*inv, s[1]*inv);
    } else {
        es[w][lane] = s[0]*inv;
    }
    __syncthreads();   // cross-warp es reads below

    // ---- aggregate, m-chunk split: warp sp covers m in [sp*NM8, ...) for ALL rows ----
    {
        constexpr int NM8 = n/8;          // 4, 8 or 16
        int sp = w;
        const float* vg = g_v + (rowbase + b*n)*32;
        float agg[8];
        #pragma unroll
        for (int r = 0; r < 8; r++) agg[r] = 0.f;
        #pragma unroll
        for (int m4 = 0; m4 < NM8/4; m4++) {
            int m = sp*NM8 + m4*4;
            float vv0 = vg[(m+0)*32 + lane];
            float vv1 = vg[(m+1)*32 + lane];
            float vv2 = vg[(m+2)*32 + lane];
            float vv3 = vg[(m+3)*32 + lane];
            #pragma unroll
            for (int r = 0; r < 8; r++) {
                float4 e4 = *(const float4*)&es[r][m];
                agg[r] = fmaf(e4.x, vv0, fmaf(e4.y, vv1, fmaf(e4.z, vv2, fmaf(e4.w, vv3, agg[r]))));
            }
        }
        #pragma unroll
        for (int r = 0; r < 8; r++) psum[r][sp][lane] = agg[r];   // psum as agg scratch
    }
    __syncthreads();
    {
        float xv = x[(b*n + row)*32 + lane];
        float acc = 0.f;
        #pragma unroll
        for (int q = 0; q < 8; q++) acc += psum[w][q][lane];
        csT[lane][w] = xv;
        csT[32 + lane][w] = acc;
    }
    __syncthreads();
    mlp8_hidden(csT, hs, bn1, tid);
    __syncthreads();

    // ---- out layer, j-split: warp w covers j in [32w, 32w+32) for ALL rows ----
    {
        float po[8];
        #pragma unroll
        for (int r = 0; r < 8; r++) po[r] = 0.f;
        #pragma unroll 2
        for (int jj = 0; jj < 32; jj += 4) {
            int j = w*32 + jj;
            float wv0 = g_Wn2T[(j+0)*32 + lane];
            float wv1 = g_Wn2T[(j+1)*32 + lane];
            float wv2 = g_Wn2T[(j+2)*32 + lane];
            float wv3 = g_Wn2T[(j+3)*32 + lane];
            #pragma unroll
            for (int r = 0; r < 8; r++) {
                float4 hv = *(const float4*)&hs[r][j];
                po[r] = fmaf(hv.x, wv0, fmaf(hv.y, wv1, fmaf(hv.z, wv2, fmaf(hv.w, wv3, po[r]))));
            }
        }
        #pragma unroll
        for (int r = 0; r < 8; r++) psum[r][w][lane] = po[r];
    }
    __syncthreads();
    {
        float acc = bn2[lane];
        #pragma unroll
        for (int q = 0; q < 8; q++) acc += psum[w][q][lane];
        float res = csT[lane][w] + acc;
        out[(b*n + row)*32 + lane] = res;
        qs[w][lane] = res;              // rs buffer for projection
    }
    __syncthreads();

    // ---- projection, j-parallel: thread tid = j for ALL 8 rows ----
    {
        const float* C  = (MODE <= 1) ? g_CA  : g_CB;
        const float* cb = (MODE <= 1) ? g_cbA : g_cbB;
        float pa[8];
        float c0 = cb[tid];
        #pragma unroll
        for (int r = 0; r < 8; r++) pa[r] = c0;
        #pragma unroll 2
        for (int dd = 0; dd < 32; dd += 4) {
            float wv0 = C[(dd+0)*256 + tid];
            float wv1 = C[(dd+1)*256 + tid];
            float wv2 = C[(dd+2)*256 + tid];
            float wv3 = C[(dd+3)*256 + tid];
            #pragma unroll
            for (int r = 0; r < 8; r++) {
                float4 rv = *(const float4*)&qs[r][dd];
                pa[r] = fmaf(rv.x, wv0, fmaf(rv.y, wv1, fmaf(rv.z, wv2, fmaf(rv.w, wv3, pa[r]))));
            }
        }
        if constexpr (MODE <= 1) {
            #pragma unroll
            for (int r = 0; r < 8; r++)
                Aout[(b*n + chunk*8 + r)*256 + tid] = pa[r];
        } else {
            float* dst = Bout + b*256*n + tid*n + chunk*8;
            *(float4*)dst       = make_float4(pa[0], pa[1], pa[2], pa[3]);
            *(float4*)(dst + 4) = make_float4(pa[4], pa[5], pa[6], pa[7]);
            // yv tail: warp per row
            float v0 = bv[lane], v1 = 0.f;
            #pragma unroll 8
            for (int d = 0; d < 32; d += 2) {
                v0 = fmaf(qs[w][d],   g_WvT[d*32 + lane],     v0);
                v1 = fmaf(qs[w][d+1], g_WvT[(d+1)*32 + lane], v1);
            }
            yvout[(b*n + row)*32 + lane] = v0 + v1;
        }
    }
}

__global__ void __launch_bounds__(256) intra_kernel(
        const float* __restrict__ robot, const float* __restrict__ frontier,
        const float* __restrict__ rh, const float* __restrict__ fh,
        const float* __restrict__ bn1, const float* __restrict__ bn2,
        const float* __restrict__ bv,
        float* __restrict__ f_out, float* __restrict__ rh_out, float* __restrict__ fh_out) {
    __shared__ __align__(16) float qs[8][32];
    __shared__ __align__(16) float es[8][128];
    __shared__ __align__(16) float csT[64][8];
    __shared__ __align__(16) float hs[8][256];
    __shared__ __align__(16) float psum[8][8][32];
    int b = blockIdx.x / 36, c = blockIdx.x % 36;
    if (c < 4)
        intra_body<1,0>(robot, g_R1, bn1, bn2, bv, b, c, 0,
                        qs, es, csT, hs, psum, g_A1, nullptr, nullptr);
    else if (c < 20)
        intra_body<4,1>(frontier, f_out, bn1, bn2, bv, b, c-4, 1024,
                        qs, es, csT, hs, psum, g_A2, nullptr, nullptr);
    else if (c < 28)
        intra_body<2,2>(rh, rh_out, bn1, bn2, bv, b, c-20, 5120,
                        qs, es, csT, hs, psum, nullptr, g_B1t, g_yv1);
    else
        intra_body<2,3>(fh, fh_out, bn1, bn2, bv, b, c-28, 7168,
                        qs, es, csT, hs, psum, nullptr, g_B2t, g_yv2);
}

// ============================================================================
// Edge kernel: warp = t-chunk, each warp processes ALL ROWS rows (B/yv loads
// amortized in registers); j-split out layer; j-parallel projections.
// MODE: 0=inter1(xout, Atail) 1=inter2(Btail/yvtail) 2=inter3(xout + eout)
// ============================================================================
template<int R, int ROWS>
struct __align__(16) ESmem {
    float As[ROWS][256];
    float scp[ROWS][8][32*R];   // reused as psum[ROWS][8][32] after softmax
    float es[ROWS][32*R];
    float aggp[ROWS][8][32];
    float csT[64][ROWS];
    float hs[ROWS][256];
    float rs[ROWS][32];
    float w65s[256];
    float we2s[256];
};

template<int R, int ROWS, int MODE>
__device__ __forceinline__ void edge_run(
        ESmem<R,ROWS>* sm,
        const float* __restrict__ x, const float* __restrict__ dis,
        const float* __restrict__ A, const float* __restrict__ Bt,
        const float* __restrict__ yv,
        const float* __restrict__ bn1, const float* __restrict__ bn2,
        const float* __restrict__ bv, const float* __restrict__ We2,
        float* __restrict__ xout, float* __restrict__ eout,
        int Nx, int b, int i0,
        float* __restrict__ Atail, float* __restrict__ Btail,
        float* __restrict__ yvtail) {
    constexpr int Ny  = 32*R;
    constexpr int TCH = 32;
    constexpr int SEG = Ny/8;
    int tid = threadIdx.x, w = tid >> 5, lane = tid & 31;
    int sp = w;

    sm->w65s[tid] = g_w65[tid];
    sm->we2s[tid] = We2[tid];
    #pragma unroll
    for (int r = 0; r < ROWS; r++) {
        const float* Ar = A + (b*Nx + i0 + r)*256;
        sm->As[r][w*32 + lane] = Ar[w*32 + lane];
    }
    __syncthreads();

    float dv[ROWS][R];
    #pragma unroll
    for (int r = 0; r < ROWS; r++) {
        const float* dr = dis + (b*Nx + i0 + r)*Ny;
        if constexpr (R == 4) {
            float4 t4 = *(const float4*)&dr[lane*4];
            dv[r][0]=t4.x; dv[r][1]=t4.y; dv[r][2]=t4.z; dv[r][3]=t4.w;
        } else {
            float2 t2 = *(const float2*)&dr[lane*2];
            dv[r][0]=t2.x; dv[r][1]=t2.y;
        }
    }
    float sc[ROWS][R];
    #pragma unroll
    for (int r = 0; r < ROWS; r++)
        #pragma unroll
        for (int k = 0; k < R; k++) sc[r][k] = 0.f;

    const float* Bb = Bt + (b*256 + sp*TCH)*Ny;
    #pragma unroll 2
    for (int tt = 0; tt < TCH; tt += 4) {
        int t = sp*TCH + tt;
        float4 w6 = *(const float4*)&sm->w65s[t];
        float4 w2 = *(const float4*)&sm->we2s[t];
        float w6v[4] = {w6.x, w6.y, w6.z, w6.w};
        float w2v[4] = {w2.x, w2.y, w2.z, w2.w};
        float av[ROWS][4];
        #pragma unroll
        for (int r = 0; r < ROWS; r++) {
            float4 a4 = *(const float4*)&sm->As[r][t];
            av[r][0]=a4.x; av[r][1]=a4.y; av[r][2]=a4.z; av[r][3]=a4.w;
        }
        #pragma unroll
        for (int u = 0; u < 4; u++) {
            if constexpr (R == 4) {
                float4 Bv = *(const float4*)&Bb[(tt+u)*Ny + lane*4];
                #pragma unroll
                for (int r = 0; r < ROWS; r++) {
                    float base = av[r][u];
                    float hh;
                    hh = fmaf(w6v[u], dv[r][0], base + Bv.x); sc[r][0] = fmaf(w2v[u], fmaxf(hh, 0.f), sc[r][0]);
                    hh = fmaf(w6v[u], dv[r][1], base + Bv.y); sc[r][1] = fmaf(w2v[u], fmaxf(hh, 0.f), sc[r][1]);
                    hh = fmaf(w6v[u], dv[r][2], base + Bv.z); sc[r][2] = fmaf(w2v[u], fmaxf(hh, 0.f), sc[r][2]);
                    hh = fmaf(w6v[u], dv[r][3], base + Bv.w); sc[r][3] = fmaf(w2v[u], fmaxf(hh, 0.f), sc[r][3]);
                }
            } else {
                float2 Bv = *(const float2*)&Bb[(tt+u)*Ny + lane*2];
                #pragma unroll
                for (int r = 0; r < ROWS; r++) {
                    float base = av[r][u];
                    float hh;
                    hh = fmaf(w6v[u], dv[r][0], base + Bv.x); sc[r][0] = fmaf(w2v[u], fmaxf(hh, 0.f), sc[r][0]);
                    hh = fmaf(w6v[u], dv[r][1], base + Bv.y); sc[r][1] = fmaf(w2v[u], fmaxf(hh, 0.f), sc[r][1]);
                }
            }
        }
    }
    #pragma unroll
    for (int r = 0; r < ROWS; r++) {
        if constexpr (R == 4) {
            *(float4*)&sm->scp[r][sp][lane*4] = make_float4(sc[r][0], sc[r][1], sc[r][2], sc[r][3]);
        } else {
            *(float2*)&sm->scp[r][sp][lane*2] = make_float2(sc[r][0], sc[r][1]);
        }
    }
    __syncthreads();

    if (w < ROWS) {
        int i = i0 + w;
        float s[R];
        #pragma unroll
        for (int k = 0; k < R; k++) {
            float acc = 0.f;
            #pragma unroll
            for (int q = 0; q < 8; q++) acc += sm->scp[w][q][lane*R + k];
            s[k] = acc;
        }
        float mx = s[0];
        #pragma unroll
        for (int k = 1; k < R; k++) mx = fmaxf(mx, s[k]);
        #pragma unroll
        for (int o = 16; o; o >>= 1) mx = fmaxf(mx, __shfl_xor_sync(0xffffffffu, mx, o));
        float sum = 0.f;
        #pragma unroll
        for (int k = 0; k < R; k++) { s[k] = __expf(s[k] - mx); sum += s[k]; }
        #pragma unroll
        for (int o = 16; o; o >>= 1) sum += __shfl_xor_sync(0xffffffffu, sum, o);
        float inv = 1.f / sum;
        if constexpr (R == 4) {
            float4 p = make_float4(s[0]*inv, s[1]*inv, s[2]*inv, s[3]*inv);
            *(float4*)&sm->es[w][lane*4] = p;
            if (MODE == 2) *(float4*)&eout[(b*Nx + i)*Ny + lane*4] = p;
        } else {
            *(float2*)&sm->es[w][lane*2] = make_float2(s[0]*inv, s[1]*inv);
        }
    }
    __syncthreads();

    {
        const float* yvb = yv + (b*Ny + sp*SEG)*32;
        float agg[ROWS];
        #pragma unroll
        for (int r = 0; r < ROWS; r++) agg[r] = 0.f;
        #pragma unroll 4
        for (int m = 0; m < SEG; m++) {
            float vv = yvb[m*32 + lane];
            #pragma unroll
            for (int r = 0; r < ROWS; r++)
                agg[r] = fmaf(sm->es[r][sp*SEG + m], vv, agg[r]);
        }
        #pragma unroll
        for (int r = 0; r < ROWS; r++) sm->aggp[r][sp][lane] = agg[r];
    }
    __syncthreads();
    if (w < ROWS) {
        float xv = x[(b*Nx + i0 + w)*32 + lane];
        float acc = 0.f;
        #pragma unroll
        for (int q = 0; q < 8; q++) acc += sm->aggp[w][q][lane];
        sm->csT[lane][w] = xv;
        sm->csT[32 + lane][w] = acc;
    }
    __syncthreads();

    // hidden layer: thread j covers all rows
    {
        float h[ROWS];
        float bb = bn1[tid];
        #pragma unroll
        for (int r = 0; r < ROWS; r++) h[r] = bb;
        #pragma unroll 8
        for (int i2 = 0; i2 < 64; i2++) {
            float wv = g_Wn1T[i2*256 + tid];
            #pragma unroll
            for (int r = 0; r < ROWS; r++) h[r] = fmaf(wv, sm->csT[i2][r], h[r]);
        }
        #pragma unroll
        for (int r = 0; r < ROWS; r++) sm->hs[r][tid] = fmaxf(h[r], 0.f);
    }
    __syncthreads();

    // out layer, j-split (psum overlays scp)
    float* psum = &sm->scp[0][0][0];     // [ROWS][8][32] indexing below
    {
        float po[ROWS];
        #pragma unroll
        for (int r = 0; r < ROWS; r++) po[r] = 0.f;
        #pragma unroll 2
        for (int jj = 0; jj < 32; jj += 4) {
            int j = w*32 + jj;
            float wv0 = g_Wn2T[(j+0)*32 + lane];
            float wv1 = g_Wn2T[(j+1)*32 + lane];
            float wv2 = g_Wn2T[(j+2)*32 + lane];
            float wv3 = g_Wn2T[(j+3)*32 + lane];
            #pragma unroll
            for (int r = 0; r < ROWS; r++) {
                float4 hv = *(const float4*)&sm->hs[r][j];
                po[r] = fmaf(hv.x, wv0, fmaf(hv.y, wv1, fmaf(hv.z, wv2, fmaf(hv.w, wv3, po[r]))));
            }
        }
        #pragma unroll
        for (int r = 0; r < ROWS; r++) psum[(r*8 + w)*32 + lane] = po[r];
    }
    __syncthreads();
    if (w < ROWS) {
        int ii = i0 + w;
        float acc = bn2[lane];
        #pragma unroll
        for (int q = 0; q < 8; q++) acc += psum[(w*8 + q)*32 + lane];
        float res = sm->csT[lane][w] + acc;
        if (MODE == 0 || MODE == 2) xout[(b*Nx + ii)*32 + lane] = res;
        sm->rs[w][lane] = res;
    }
    __syncthreads();

    // projection tails, j-parallel
    if constexpr (MODE == 0 || MODE == 1) {
        const float* C  = (MODE == 0) ? g_CA  : g_CB;
        const float* cb = (MODE == 0) ? g_cbA : g_cbB;
        float pa[ROWS];
        float c0 = cb[tid];
        #pragma unroll
        for (int r = 0; r < ROWS; r++) pa[r] = c0;
        #pragma unroll 2
        for (int dd = 0; dd < 32; dd += 4) {
            float wv0 = C[(dd+0)*256 + tid];
            float wv1 = C[(dd+1)*256 + tid];
            float wv2 = C[(dd+2)*256 + tid];
            float wv3 = C[(dd+3)*256 + tid];
            #pragma unroll
            for (int r = 0; r < ROWS; r++) {
                float4 rv = *(const float4*)&sm->rs[r][dd];
                pa[r] = fmaf(rv.x, wv0, fmaf(rv.y, wv1, fmaf(rv.z, wv2, fmaf(rv.w, wv3, pa[r]))));
            }
        }
        if constexpr (MODE == 0) {
            #pragma unroll
            for (int r = 0; r < ROWS; r++)
                Atail[(b*Nx + i0 + r)*256 + tid] = pa[r];
        } else {
            static_assert(ROWS == 4, "MODE 1 expects ROWS==4");
            float* dst = Btail + b*256*128 + tid*128 + i0;
            *(float4*)dst = make_float4(pa[0], pa[1], pa[2], pa[3]);
            if (w < ROWS) {
                int ii = i0 + w;
                float v0 = bv[lane], v1 = 0.f;
                #pragma unroll 8
                for (int d = 0; d < 32; d += 2) {
                    v0 = fmaf(sm->rs[w][d],   g_WvT[d*32 + lane],     v0);
                    v1 = fmaf(sm->rs[w][d+1], g_WvT[(d+1)*32 + lane], v1);
                }
                yvtail[(b*Nx + ii)*32 + lane] = v0 + v1;
            }
        }
    }
}

// inter1 (256 blocks) + inter2 (1024 blocks). grid 1280, block 256.
__global__ void __launch_bounds__(256, 5) edge12_kernel(
        const float* __restrict__ f_in, const float* __restrict__ rp,
        const float* __restrict__ fpd,
        const float* __restrict__ bn1, const float* __restrict__ bn2,
        const float* __restrict__ We2, const float* __restrict__ bv) {
    __shared__ __align__(16) ESmem<2,4> sm;
    int blk = blockIdx.x;
    if (blk < 256) {
        int b = blk >> 3, i0 = (blk & 7)*4;
        edge_run<2,4,0>(&sm, g_R1, rp, g_A1, g_B1t, g_yv1, bn1, bn2, bv, We2,
                        g_R2, nullptr, 32, b, i0, g_A3, nullptr, nullptr);
    } else {
        blk -= 256;
        int b = blk >> 5, i0 = (blk & 31)*4;
        edge_run<2,4,1>(&sm, f_in, fpd, g_A2, g_B2t, g_yv2, bn1, bn2, bv, We2,
                        nullptr, nullptr, 128, b, i0, nullptr, g_B3t, g_yv3);
    }
}

// inter3: robot <- new_frontier. grid 512, block 256 (2 rows x 8 t-chunks).
__global__ void __launch_bounds__(256, 5) edge3_kernel(
        const float* __restrict__ rf,
        const float* __restrict__ bn1, const float* __restrict__ bn2,
        const float* __restrict__ We2, const float* __restrict__ bv,
        float* __restrict__ r_out, float* __restrict__ e_out) {
    __shared__ __align__(16) ESmem<4,2> sm;
    int b = blockIdx.x >> 4, i0 = (blockIdx.x & 15)*2;
    edge_run<4,2,2>(&sm, g_R2, rf, g_A3, g_B3t, g_yv3, bn1, bn2, bv, We2,
                    r_out, e_out, 32, b, i0, nullptr, nullptr, nullptr);
}

// ============================================================================
extern "C" void kernel_launch(void* const* d_in, const int* in_sizes, int n_in,
                              void* d_out, int out_size) {
    const float* robot    = (const float*)d_in[0];
    const float* frontier = (const float*)d_in[1];
    const float* rh       = (const float*)d_in[2];
    const float* fh       = (const float*)d_in[3];
    const float* rf       = (const float*)d_in[4];
    const float* rp       = (const float*)d_in[5];
    const float* fpd      = (const float*)d_in[6];
    const float* Wq  = (const float*)d_in[7];  const float* bq  = (const float*)d_in[8];
    const float* Wk  = (const float*)d_in[9];  const float* bk  = (const float*)d_in[10];
    const float* Wv  = (const float*)d_in[11]; const float* bv  = (const float*)d_in[12];
    const float* Wn1 = (const float*)d_in[13]; const float* bn1 = (const float*)d_in[14];
    const float* Wn2 = (const float*)d_in[15]; const float* bn2 = (const float*)d_in[16];
    const float* We1 = (const float*)d_in[17]; const float* be1 = (const float*)d_in[18];
    const float* We2 = (const float*)d_in[19];
    // d_in[20] = be2: softmax-invariant, unused.

    float* out    = (float*)d_out;
    float* r_out  = out;
    float* f_out  = r_out  + 32*32*32;
    float* rh_out = f_out  + 32*128*32;
    float* fh_out = rh_out + 32*64*32;
    float* e_out  = fh_out + 32*64*32;

    prep_kernel<<<57, 256>>>(Wq, bq, Wk, bk, Wv, Wn1, Wn2, We1, be1);
    qkv_kernel<<<32*36, 256>>>(robot, frontier, rh, fh, bq, bk, bv);
    intra_kernel<<<32*36, 256>>>(robot, frontier, rh, fh, bn1, bn2, bv,
                                 f_out, rh_out, fh_out);
    edge12_kernel<<<1280, 256>>>(f_out, rp, fpd, bn1, bn2, We2, bv);
    edge3_kernel<<<512, 256>>>(rf, bn1, bn2, We2, bv, r_out, e_out);
}